// round 1
// baseline (speedup 1.0000x reference)
#include <cuda_runtime.h>
#include <math.h>
#include <stdint.h>

// Problem constants
constexpr int Bc  = 4;
constexpr int Lc  = 1024;
constexpr int Dc  = 1024;
constexpr int Fc  = 4096;
constexpr int Hc  = 16;
constexpr int HDc = 64;
constexpr int BLc = Bc * Lc;          // 4096 rows

// ---------------------------------------------------------------------------
// Scratch (static __device__ arrays — allocation-free per harness rules)
// ---------------------------------------------------------------------------
__device__ float g_Q [BLc * Dc];
__device__ float g_K [BLc * Dc];
__device__ float g_V [BLc * Dc];
__device__ float g_S [(size_t)Bc * Hc * Lc * Lc];   // 256 MB scores
__device__ float g_O [BLc * Dc];                    // attention output (pre-Wo)
__device__ float g_M [BLc * Dc];                    // MHA output (post-Wo)
__device__ float g_T1[BLc * Dc];
__device__ float g_A1[BLc * Dc];
__device__ float g_T2[BLc * Dc];
__device__ float g_A2[BLc * Dc];
__device__ float g_FH[BLc * Fc];                    // FFN hidden, 64 MB

// ---------------------------------------------------------------------------
// SGEMM: C[M,N] = A[M,K] @ B[K,N] (+bias) (+relu). All dims multiples of 128
// (K multiple of 8). 128x128 tile, 8x8 per thread, 256 threads.
// ---------------------------------------------------------------------------
__global__ __launch_bounds__(256) void sgemm128(
    const float* __restrict__ A, const float* __restrict__ Bm,
    const float* __restrict__ bias, float* __restrict__ C,
    int M, int N, int K, int relu)
{
    constexpr int BK = 8;
    __shared__ float As[BK][128];
    __shared__ float Bs[BK][128];

    const int tid  = threadIdx.x;
    const int brow = blockIdx.y * 128;
    const int bcol = blockIdx.x * 128;

    const int aRow = tid >> 1;          // 0..127
    const int aCol = (tid & 1) << 2;    // 0 or 4
    const int bRow = tid >> 5;          // 0..7
    const int bCol = (tid & 31) << 2;   // 0..124
    const int tRow = (tid >> 4) << 3;
    const int tCol = (tid & 15) << 3;

    float acc[8][8];
    #pragma unroll
    for (int i = 0; i < 8; i++)
        #pragma unroll
        for (int j = 0; j < 8; j++) acc[i][j] = 0.f;

    const float* Aptr = A  + (size_t)(brow + aRow) * K + aCol;
    const float* Bptr = Bm + (size_t)bRow * N + bcol + bCol;

    for (int kk = 0; kk < K; kk += BK) {
        float4 a4 = *(const float4*)(Aptr + kk);
        float4 b4 = *(const float4*)(Bptr + (size_t)kk * N);
        As[aCol + 0][aRow] = a4.x;
        As[aCol + 1][aRow] = a4.y;
        As[aCol + 2][aRow] = a4.z;
        As[aCol + 3][aRow] = a4.w;
        *(float4*)&Bs[bRow][bCol] = b4;
        __syncthreads();

        #pragma unroll
        for (int k = 0; k < BK; k++) {
            float ra[8], rb[8];
            #pragma unroll
            for (int i = 0; i < 8; i++) ra[i] = As[k][tRow + i];
            #pragma unroll
            for (int j = 0; j < 8; j++) rb[j] = Bs[k][tCol + j];
            #pragma unroll
            for (int i = 0; i < 8; i++)
                #pragma unroll
                for (int j = 0; j < 8; j++)
                    acc[i][j] += ra[i] * rb[j];
        }
        __syncthreads();
    }

    #pragma unroll
    for (int i = 0; i < 8; i++) {
        const int r = brow + tRow + i;
        #pragma unroll
        for (int j = 0; j < 8; j += 4) {
            float4 v;
            v.x = acc[i][j + 0]; v.y = acc[i][j + 1];
            v.z = acc[i][j + 2]; v.w = acc[i][j + 3];
            if (bias) {
                float4 bb = *(const float4*)&bias[bcol + tCol + j];
                v.x += bb.x; v.y += bb.y; v.z += bb.z; v.w += bb.w;
            }
            if (relu) {
                v.x = fmaxf(v.x, 0.f); v.y = fmaxf(v.y, 0.f);
                v.z = fmaxf(v.z, 0.f); v.w = fmaxf(v.w, 0.f);
            }
            *(float4*)&C[(size_t)r * N + bcol + tCol + j] = v;
        }
    }
}

// ---------------------------------------------------------------------------
// Attention scores: S[bh,q,k] = (Q_h[q,:] . K_h[k,:]) / 8 + mask[q,k] + pad[b,k]
// Q/K are [B*L, D] with head h in columns [h*64, h*64+64).
// Block computes a 64x64 (q,k) tile for one (b,h).
// ---------------------------------------------------------------------------
__global__ __launch_bounds__(256) void attn_scores(
    const float* __restrict__ Q, const float* __restrict__ Km,
    const float* __restrict__ mask, const int* __restrict__ pad,
    float* __restrict__ S)
{
    __shared__ float Qs[64][65];
    __shared__ float Ks[64][65];
    const int tid = threadIdx.x;
    const int kx  = blockIdx.x * 64;
    const int qy  = blockIdx.y * 64;
    const int bh  = blockIdx.z;
    const int b   = bh >> 4;
    const int h   = bh & 15;
    const int hcol = h * HDc;

    for (int i = tid; i < 64 * 16; i += 256) {
        int r = i >> 4;
        int c = (i & 15) << 2;
        float4 q4 = *(const float4*)&Q [(size_t)(b * Lc + qy + r) * Dc + hcol + c];
        Qs[r][c] = q4.x; Qs[r][c+1] = q4.y; Qs[r][c+2] = q4.z; Qs[r][c+3] = q4.w;
        float4 k4 = *(const float4*)&Km[(size_t)(b * Lc + kx + r) * Dc + hcol + c];
        Ks[r][c] = k4.x; Ks[r][c+1] = k4.y; Ks[r][c+2] = k4.z; Ks[r][c+3] = k4.w;
    }
    __syncthreads();

    const int tr = (tid >> 4) << 2;
    const int tc = (tid & 15) << 2;
    float acc[4][4];
    #pragma unroll
    for (int i = 0; i < 4; i++)
        #pragma unroll
        for (int j = 0; j < 4; j++) acc[i][j] = 0.f;

    #pragma unroll 8
    for (int k = 0; k < 64; k++) {
        float ra[4], rb[4];
        #pragma unroll
        for (int i = 0; i < 4; i++) ra[i] = Qs[tr + i][k];
        #pragma unroll
        for (int j = 0; j < 4; j++) rb[j] = Ks[tc + j][k];
        #pragma unroll
        for (int i = 0; i < 4; i++)
            #pragma unroll
            for (int j = 0; j < 4; j++)
                acc[i][j] += ra[i] * rb[j];
    }

    #pragma unroll
    for (int i = 0; i < 4; i++) {
        const int q = qy + tr + i;
        #pragma unroll
        for (int j = 0; j < 4; j++) {
            const int kc = kx + tc + j;
            float v = acc[i][j] * 0.125f
                    + mask[(size_t)q * Lc + kc]
                    + (float)pad[b * Lc + kc];
            S[((size_t)bh * Lc + q) * Lc + kc] = v;
        }
    }
}

// ---------------------------------------------------------------------------
// In-place softmax over rows of length 1024. One block (256 thr) per row.
// ---------------------------------------------------------------------------
__global__ __launch_bounds__(256) void softmax_rows(float* __restrict__ S)
{
    __shared__ float red[8];
    const int tid = threadIdx.x;
    float* row = S + (size_t)blockIdx.x * 1024;
    float4 v = *(float4*)&row[tid * 4];

    float m = fmaxf(fmaxf(v.x, v.y), fmaxf(v.z, v.w));
    #pragma unroll
    for (int o = 16; o > 0; o >>= 1) m = fmaxf(m, __shfl_xor_sync(0xffffffffu, m, o));
    if ((tid & 31) == 0) red[tid >> 5] = m;
    __syncthreads();
    m = red[0];
    #pragma unroll
    for (int i = 1; i < 8; i++) m = fmaxf(m, red[i]);
    __syncthreads();  // before red[] reuse

    v.x = __expf(v.x - m); v.y = __expf(v.y - m);
    v.z = __expf(v.z - m); v.w = __expf(v.w - m);
    float s = v.x + v.y + v.z + v.w;
    #pragma unroll
    for (int o = 16; o > 0; o >>= 1) s += __shfl_xor_sync(0xffffffffu, s, o);
    if ((tid & 31) == 0) red[tid >> 5] = s;
    __syncthreads();
    s = red[0];
    #pragma unroll
    for (int i = 1; i < 8; i++) s += red[i];

    const float inv = 1.f / s;
    v.x *= inv; v.y *= inv; v.z *= inv; v.w *= inv;
    *(float4*)&row[tid * 4] = v;
}

// ---------------------------------------------------------------------------
// PV: O[b, q, h*64+d] = sum_k P[bh,q,k] * V[b,k,h*64+d].
// Block: 64 q-rows x 64 d-cols (full head) for one (b,h); K-loop over L.
// ---------------------------------------------------------------------------
__global__ __launch_bounds__(256) void attn_pv(
    const float* __restrict__ P, const float* __restrict__ V,
    float* __restrict__ O)
{
    __shared__ float Ps[64][65];
    __shared__ float Vs[64][65];
    const int tid = threadIdx.x;
    const int qy  = blockIdx.x * 64;
    const int bh  = blockIdx.y;
    const int b   = bh >> 4;
    const int h   = bh & 15;
    const int hcol = h * HDc;
    const int tr = (tid >> 4) << 2;
    const int tc = (tid & 15) << 2;

    float acc[4][4];
    #pragma unroll
    for (int i = 0; i < 4; i++)
        #pragma unroll
        for (int j = 0; j < 4; j++) acc[i][j] = 0.f;

    for (int kt = 0; kt < Lc; kt += 64) {
        for (int i = tid; i < 64 * 16; i += 256) {
            int r = i >> 4;
            int c = (i & 15) << 2;
            float4 p4 = *(const float4*)&P[((size_t)bh * Lc + qy + r) * Lc + kt + c];
            Ps[r][c] = p4.x; Ps[r][c+1] = p4.y; Ps[r][c+2] = p4.z; Ps[r][c+3] = p4.w;
            float4 v4 = *(const float4*)&V[(size_t)(b * Lc + kt + r) * Dc + hcol + c];
            Vs[r][c] = v4.x; Vs[r][c+1] = v4.y; Vs[r][c+2] = v4.z; Vs[r][c+3] = v4.w;
        }
        __syncthreads();

        #pragma unroll 8
        for (int k = 0; k < 64; k++) {
            float ra[4], rb[4];
            #pragma unroll
            for (int i = 0; i < 4; i++) ra[i] = Ps[tr + i][k];
            #pragma unroll
            for (int j = 0; j < 4; j++) rb[j] = Vs[k][tc + j];
            #pragma unroll
            for (int i = 0; i < 4; i++)
                #pragma unroll
                for (int j = 0; j < 4; j++)
                    acc[i][j] += ra[i] * rb[j];
        }
        __syncthreads();
    }

    #pragma unroll
    for (int i = 0; i < 4; i++)
        #pragma unroll
        for (int j = 0; j < 4; j++)
            O[(size_t)(b * Lc + qy + tr + i) * Dc + hcol + tc + j] = acc[i][j];
}

// ---------------------------------------------------------------------------
// y = LayerNorm(x + res) * g + b  over rows of length 1024
// ---------------------------------------------------------------------------
__global__ __launch_bounds__(256) void add_ln(
    const float* __restrict__ x, const float* __restrict__ res,
    const float* __restrict__ g, const float* __restrict__ bta,
    float* __restrict__ y)
{
    __shared__ float rs[8], rq[8];
    const int tid = threadIdx.x;
    const size_t base = (size_t)blockIdx.x * 1024 + tid * 4;

    float4 a = *(const float4*)&x[base];
    float4 r = *(const float4*)&res[base];
    a.x += r.x; a.y += r.y; a.z += r.z; a.w += r.w;

    float s = a.x + a.y + a.z + a.w;
    float q = a.x*a.x + a.y*a.y + a.z*a.z + a.w*a.w;
    #pragma unroll
    for (int o = 16; o > 0; o >>= 1) {
        s += __shfl_xor_sync(0xffffffffu, s, o);
        q += __shfl_xor_sync(0xffffffffu, q, o);
    }
    if ((tid & 31) == 0) { rs[tid >> 5] = s; rq[tid >> 5] = q; }
    __syncthreads();
    s = 0.f; q = 0.f;
    #pragma unroll
    for (int i = 0; i < 8; i++) { s += rs[i]; q += rq[i]; }

    const float mean = s * (1.f / 1024.f);
    const float var  = q * (1.f / 1024.f) - mean * mean;
    const float rstd = rsqrtf(var + 1e-5f);

    const int c = tid * 4;
    float4 gv = *(const float4*)&g[c];
    float4 bv = *(const float4*)&bta[c];
    float4 o;
    o.x = (a.x - mean) * rstd * gv.x + bv.x;
    o.y = (a.y - mean) * rstd * gv.y + bv.y;
    o.z = (a.z - mean) * rstd * gv.z + bv.z;
    o.w = (a.w - mean) * rstd * gv.w + bv.w;
    *(float4*)&y[base] = o;
}

// ---------------------------------------------------------------------------
// Launch orchestration
// ---------------------------------------------------------------------------
extern "C" void kernel_launch(void* const* d_in, const int* in_sizes, int n_in,
                              void* d_out, int out_size)
{
    const float* T    = (const float*)d_in[0];
    const float* A    = (const float*)d_in[1];
    const float* mask = (const float*)d_in[2];
    const int*   pad  = (const int*)  d_in[3];
    const float* Wq   = (const float*)d_in[4];
    const float* bq   = (const float*)d_in[5];
    const float* Wk   = (const float*)d_in[6];
    const float* bk   = (const float*)d_in[7];
    const float* Wv   = (const float*)d_in[8];
    const float* bv   = (const float*)d_in[9];
    const float* Wo   = (const float*)d_in[10];
    const float* ffW1 = (const float*)d_in[11];
    const float* ffb1 = (const float*)d_in[12];
    const float* ffW2 = (const float*)d_in[13];
    const float* ffb2 = (const float*)d_in[14];
    const float* lng  = (const float*)d_in[15];
    const float* lnb  = (const float*)d_in[16];
    float* out = (float*)d_out;

    float *Qb, *Kb, *Vb, *Sb, *Ob, *Mo, *T1, *A1, *T2, *A2, *Hb;
    cudaGetSymbolAddress((void**)&Qb, g_Q);
    cudaGetSymbolAddress((void**)&Kb, g_K);
    cudaGetSymbolAddress((void**)&Vb, g_V);
    cudaGetSymbolAddress((void**)&Sb, g_S);
    cudaGetSymbolAddress((void**)&Ob, g_O);
    cudaGetSymbolAddress((void**)&Mo, g_M);
    cudaGetSymbolAddress((void**)&T1, g_T1);
    cudaGetSymbolAddress((void**)&A1, g_A1);
    cudaGetSymbolAddress((void**)&T2, g_T2);
    cudaGetSymbolAddress((void**)&A2, g_A2);
    cudaGetSymbolAddress((void**)&Hb, g_FH);

    auto gemm = [&](const float* a, const float* w, const float* bias, float* c,
                    int M, int N, int K, int relu) {
        dim3 grid(N / 128, M / 128);
        sgemm128<<<grid, 256>>>(a, w, bias, c, M, N, K, relu);
    };

    auto mha = [&](int i, const float* xq, const float* xk, const float* xv, float* ob) {
        const size_t wo = (size_t)i * Dc * Dc;
        gemm(xq, Wq + wo, bq + i * Dc, Qb, BLc, Dc, Dc, 0);
        gemm(xk, Wk + wo, bk + i * Dc, Kb, BLc, Dc, Dc, 0);
        gemm(xv, Wv + wo, bv + i * Dc, Vb, BLc, Dc, Dc, 0);
        attn_scores<<<dim3(Lc / 64, Lc / 64, Bc * Hc), 256>>>(Qb, Kb, mask, pad, Sb);
        softmax_rows<<<Bc * Hc * Lc, 256>>>(Sb);
        attn_pv<<<dim3(Lc / 64, Bc * Hc), 256>>>(Sb, Vb, Ob);
        gemm(Ob, Wo + wo, nullptr, ob, BLc, Dc, Dc, 0);
    };

    // Self-attention per modality
    mha(0, T, T, T, Mo);
    add_ln<<<BLc, 256>>>(T, Mo, lng + 0 * Dc, lnb + 0 * Dc, T1);
    mha(1, A, A, A, Mo);
    add_ln<<<BLc, 256>>>(A, Mo, lng + 1 * Dc, lnb + 1 * Dc, A1);
    // Cross-attention
    mha(2, T1, A1, A1, Mo);
    add_ln<<<BLc, 256>>>(T1, Mo, lng + 2 * Dc, lnb + 2 * Dc, T2);
    mha(3, A1, T2, T2, Mo);
    add_ln<<<BLc, 256>>>(A1, Mo, lng + 3 * Dc, lnb + 3 * Dc, A2);
    // FFNs (written straight into d_out: T_out then A_out)
    gemm(T2, ffW1,                    ffb1,      Hb,  BLc, Fc, Dc, 1);
    gemm(Hb, ffW2,                    ffb2,      out, BLc, Dc, Fc, 0);
    gemm(A2, ffW1 + (size_t)Dc * Fc,  ffb1 + Fc, Hb,  BLc, Fc, Dc, 1);
    gemm(Hb, ffW2 + (size_t)Fc * Dc,  ffb2 + Dc, out + (size_t)BLc * Dc, BLc, Dc, Fc, 0);
}

// round 3
// speedup vs baseline: 1.7641x; 1.7641x over previous
#include <cuda_runtime.h>
#include <cuda_bf16.h>
#include <math.h>
#include <stdint.h>

// Problem constants
constexpr int Bc  = 4;
constexpr int Lc  = 1024;
constexpr int Dc  = 1024;
constexpr int Fc  = 4096;
constexpr int Hc  = 16;
constexpr int HDc = 64;
constexpr int BLc = Bc * Lc;          // 4096 rows

// ---------------------------------------------------------------------------
// Scratch (static __device__ arrays — allocation-free per harness rules)
// ---------------------------------------------------------------------------
__device__ float g_Q [BLc * Dc];
__device__ float g_K [BLc * Dc];
__device__ float g_V [BLc * Dc];
__device__ float g_S [(size_t)Bc * Hc * Lc * Lc];   // 256 MB scores
__device__ float g_O [BLc * Dc];
__device__ float g_M [BLc * Dc];
__device__ float g_T1[BLc * Dc];
__device__ float g_A1[BLc * Dc];
__device__ float g_T2[BLc * Dc];
__device__ float g_A2[BLc * Dc];
__device__ float g_FH[BLc * Fc];                    // FFN hidden (fp32)

// bf16 split weights (transposed to [N,K]) and activations
__device__ __nv_bfloat16 g_wqh[4*Dc*Dc], g_wql[4*Dc*Dc];
__device__ __nv_bfloat16 g_wkh[4*Dc*Dc], g_wkl[4*Dc*Dc];
__device__ __nv_bfloat16 g_wvh[4*Dc*Dc], g_wvl[4*Dc*Dc];
__device__ __nv_bfloat16 g_woh[4*Dc*Dc], g_wol[4*Dc*Dc];
__device__ __nv_bfloat16 g_w1h[2*Dc*Fc], g_w1l[2*Dc*Fc];   // ff1^T : [F, D]
__device__ __nv_bfloat16 g_w2h[2*Fc*Dc], g_w2l[2*Fc*Dc];   // ff2^T : [D, F]
__device__ __nv_bfloat16 g_xh1[(size_t)BLc*Fc], g_xl1[(size_t)BLc*Fc];
__device__ __nv_bfloat16 g_xh2[(size_t)BLc*Dc], g_xl2[(size_t)BLc*Dc];

// ---------------------------------------------------------------------------
// PTX helpers (sm_103 baseline-safe: mma.sync + ldmatrix + cp.async only)
// ---------------------------------------------------------------------------
__device__ __forceinline__ uint32_t smem_u32(const void* p) {
    uint32_t a;
    asm("{ .reg .u64 t; cvta.to.shared.u64 t, %1; cvt.u32.u64 %0, t; }" : "=r"(a) : "l"(p));
    return a;
}
__device__ __forceinline__ void cpasync16(uint32_t dst, const void* src) {
    asm volatile("cp.async.cg.shared.global [%0], [%1], 16;" :: "r"(dst), "l"(src));
}
#define CP_COMMIT()  asm volatile("cp.async.commit_group;" ::: "memory")
#define CP_WAIT(n)   asm volatile("cp.async.wait_group %0;" :: "n"(n) : "memory")

#define LDSM4(r, a) \
    asm volatile("ldmatrix.sync.aligned.m8n8.x4.shared.b16 {%0,%1,%2,%3}, [%4];" \
        : "=r"((r)[0]), "=r"((r)[1]), "=r"((r)[2]), "=r"((r)[3]) : "r"(a))

__device__ __forceinline__ void mma16816(float* c, const uint32_t* a, const uint32_t* b) {
    asm volatile(
        "mma.sync.aligned.m16n8k16.row.col.f32.bf16.bf16.f32 "
        "{%0,%1,%2,%3}, {%4,%5,%6,%7}, {%8,%9}, {%0,%1,%2,%3};"
        : "+f"(c[0]), "+f"(c[1]), "+f"(c[2]), "+f"(c[3])
        : "r"(a[0]), "r"(a[1]), "r"(a[2]), "r"(a[3]), "r"(b[0]), "r"(b[1]));
}

__device__ __forceinline__ void split1(float v, __nv_bfloat16& h, __nv_bfloat16& l) {
    h = __float2bfloat16(v);
    l = __float2bfloat16(v - __bfloat162float(h));
}

// ---------------------------------------------------------------------------
// Tensor-core GEMM: C[M,N] = (Ah+Al)[M,K] @ (Bh+Bl)[N,K]^T (+bias)(+relu).
// 128x128 CTA tile, BK=32, 8 warps (2m x 4n), warp tile 64x32.
// cp.async double-buffered smem; ldmatrix operand loads; split-bf16 (3 MMAs).
// M,N multiples of 128; K multiple of 32.
// ---------------------------------------------------------------------------
constexpr int GSTR    = 40;                       // smem row stride (bf16)
constexpr int TILE_B  = 128 * GSTR * 2;           // 10240 B per tile
constexpr int STAGE_B = 4 * TILE_B;               // Ah,Al,Bh,Bl = 40960 B
constexpr int GEMM_SMEM = 2 * STAGE_B;            // 81920 B

__global__ __launch_bounds__(256, 2) void gemm_mma(
    const __nv_bfloat16* __restrict__ Ah, const __nv_bfloat16* __restrict__ Al,
    const __nv_bfloat16* __restrict__ Bh, const __nv_bfloat16* __restrict__ Bl,
    const float* __restrict__ bias, float* __restrict__ C,
    int M, int N, int K, int relu)
{
    extern __shared__ char sm[];
    const uint32_t sb = smem_u32(sm);
    const int tid  = threadIdx.x;
    const int wid  = tid >> 5;
    const int lane = tid & 31;
    const int brow = blockIdx.y * 128;
    const int bcol = blockIdx.x * 128;
    const int wm   = (wid & 1) * 64;     // warp row offset in tile
    const int wn   = (wid >> 1) * 32;    // warp col offset in tile

    float acc[4][4][4];
    #pragma unroll
    for (int i = 0; i < 4; i++)
        #pragma unroll
        for (int j = 0; j < 4; j++)
            #pragma unroll
            for (int k = 0; k < 4; k++) acc[i][j][k] = 0.f;

    // per-thread load coords: 2 x (row, 16B-unit) per tile
    const int r0 = tid >> 2,            q0 = tid & 3;
    const int r1 = (tid + 256) >> 2,    q1 = (tid + 256) & 3;

    const int nch = K >> 5;

    // --- issue chunk c into stage s ---
    auto issue = [&](int c, int s) {
        const int kc = c << 5;
        const uint32_t st = sb + s * STAGE_B;
        {
            const uint32_t so = (uint32_t)(r0 * 80 + q0 * 16);
            const size_t ga = (size_t)(brow + r0) * K + kc + q0 * 8;
            const size_t gb = (size_t)(bcol + r0) * K + kc + q0 * 8;
            cpasync16(st + so,              Ah + ga);
            cpasync16(st + TILE_B + so,     Al + ga);
            cpasync16(st + 2*TILE_B + so,   Bh + gb);
            cpasync16(st + 3*TILE_B + so,   Bl + gb);
        }
        {
            const uint32_t so = (uint32_t)(r1 * 80 + q1 * 16);
            const size_t ga = (size_t)(brow + r1) * K + kc + q1 * 8;
            const size_t gb = (size_t)(bcol + r1) * K + kc + q1 * 8;
            cpasync16(st + so,              Ah + ga);
            cpasync16(st + TILE_B + so,     Al + ga);
            cpasync16(st + 2*TILE_B + so,   Bh + gb);
            cpasync16(st + 3*TILE_B + so,   Bl + gb);
        }
        CP_COMMIT();
    };

    issue(0, 0);

    // ldmatrix address components (bytes)
    const int a_row = (lane & 15);             // row within 16-row tile
    const int a_kof = ((lane >> 4) << 3);      // 0 or 8 (k half)
    const int g8    = lane >> 3;               // 0..3
    const int b_nt  = (g8 >> 1) << 3;          // 0 or 8 (n-tile within pair)
    const int b_kof = (g8 & 1) << 3;           // 0 or 8
    const int b_row = (lane & 7);

    for (int c = 0; c < nch; c++) {
        if (c + 1 < nch) { issue(c + 1, (c + 1) & 1); CP_WAIT(1); }
        else             { CP_WAIT(0); }
        __syncthreads();

        const uint32_t st = sb + (c & 1) * STAGE_B;
        #pragma unroll
        for (int k16 = 0; k16 < 32; k16 += 16) {
            uint32_t aH[4][4], bH[4][2], t[4];
            // A hi fragments: 4 m-tiles
            #pragma unroll
            for (int mt = 0; mt < 4; mt++) {
                uint32_t ad = st + (uint32_t)((wm + mt*16 + a_row) * 80
                                              + (k16 + a_kof) * 2);
                LDSM4(aH[mt], ad);
            }
            // B hi fragments: 2 x ldmatrix.x4, each covers 2 n-tiles
            #pragma unroll
            for (int p = 0; p < 2; p++) {
                uint32_t ad = st + 2*TILE_B
                    + (uint32_t)((wn + p*16 + b_nt + b_row) * 80
                                 + (k16 + b_kof) * 2);
                LDSM4(t, ad);
                bH[2*p    ][0] = t[0]; bH[2*p    ][1] = t[1];
                bH[2*p + 1][0] = t[2]; bH[2*p + 1][1] = t[3];
            }
            // hi x hi
            #pragma unroll
            for (int mt = 0; mt < 4; mt++)
                #pragma unroll
                for (int nt = 0; nt < 4; nt++)
                    mma16816(acc[mt][nt], aH[mt], bH[nt]);
            // hi x lo
            #pragma unroll
            for (int p = 0; p < 2; p++) {
                uint32_t ad = st + 3*TILE_B
                    + (uint32_t)((wn + p*16 + b_nt + b_row) * 80
                                 + (k16 + b_kof) * 2);
                LDSM4(t, ad);
                uint32_t bl0[2] = { t[0], t[1] }, bl1[2] = { t[2], t[3] };
                #pragma unroll
                for (int mt = 0; mt < 4; mt++) {
                    mma16816(acc[mt][2*p    ], aH[mt], bl0);
                    mma16816(acc[mt][2*p + 1], aH[mt], bl1);
                }
            }
            // lo x hi
            #pragma unroll
            for (int mt = 0; mt < 4; mt++) {
                uint32_t ad = st + TILE_B
                    + (uint32_t)((wm + mt*16 + a_row) * 80
                                 + (k16 + a_kof) * 2);
                LDSM4(t, ad);
                #pragma unroll
                for (int nt = 0; nt < 4; nt++)
                    mma16816(acc[mt][nt], t, bH[nt]);
            }
        }
        __syncthreads();
    }

    // Epilogue: frag (mt,nt): c0,c1 -> row g, cols 2tg,2tg+1; c2,c3 -> row g+8
    const int g  = lane >> 2;
    const int tg = lane & 3;
    #pragma unroll
    for (int mt = 0; mt < 4; mt++) {
        #pragma unroll
        for (int nt = 0; nt < 4; nt++) {
            const int row = brow + wm + mt*16 + g;
            const int col = bcol + wn + nt*8 + tg*2;
            float2 v0, v1;
            v0.x = acc[mt][nt][0]; v0.y = acc[mt][nt][1];
            v1.x = acc[mt][nt][2]; v1.y = acc[mt][nt][3];
            if (bias) {
                float2 bb = *(const float2*)&bias[col];
                v0.x += bb.x; v0.y += bb.y; v1.x += bb.x; v1.y += bb.y;
            }
            if (relu) {
                v0.x = fmaxf(v0.x, 0.f); v0.y = fmaxf(v0.y, 0.f);
                v1.x = fmaxf(v1.x, 0.f); v1.y = fmaxf(v1.y, 0.f);
            }
            *(float2*)&C[(size_t)row * N + col]       = v0;
            *(float2*)&C[(size_t)(row + 8) * N + col] = v1;
        }
    }
}

// ---------------------------------------------------------------------------
// fp32 -> bf16 hi/lo split
// ---------------------------------------------------------------------------
__global__ __launch_bounds__(256) void split_f32(
    const float* __restrict__ x, __nv_bfloat16* __restrict__ h,
    __nv_bfloat16* __restrict__ l)
{
    const size_t i = ((size_t)blockIdx.x * 256 + threadIdx.x) * 4;
    float4 v = *(const float4*)(x + i);
    __nv_bfloat16 h0, h1, h2, h3, l0, l1, l2, l3;
    split1(v.x, h0, l0); split1(v.y, h1, l1);
    split1(v.z, h2, l2); split1(v.w, h3, l3);
    __nv_bfloat162 hh0; hh0.x = h0; hh0.y = h1;
    __nv_bfloat162 hh1; hh1.x = h2; hh1.y = h3;
    __nv_bfloat162 ll0; ll0.x = l0; ll0.y = l1;
    __nv_bfloat162 ll1; ll1.x = l2; ll1.y = l3;
    *(__nv_bfloat162*)(h + i)     = hh0;
    *(__nv_bfloat162*)(h + i + 2) = hh1;
    *(__nv_bfloat162*)(l + i)     = ll0;
    *(__nv_bfloat162*)(l + i + 2) = ll1;
}

// ---------------------------------------------------------------------------
// W[K,N] fp32 -> Wt[N,K] bf16 hi/lo, batched over blockIdx.z
// ---------------------------------------------------------------------------
__global__ __launch_bounds__(256) void transpose_split(
    const float* __restrict__ W, __nv_bfloat16* __restrict__ h,
    __nv_bfloat16* __restrict__ l, int K, int N)
{
    __shared__ float t[32][33];
    const size_t base = (size_t)blockIdx.z * K * N;
    const int k0 = blockIdx.y * 32, n0 = blockIdx.x * 32;
    const int tx = threadIdx.x & 31, ty = threadIdx.x >> 5;
    #pragma unroll
    for (int r = 0; r < 32; r += 8)
        t[ty + r][tx] = W[base + (size_t)(k0 + ty + r) * N + n0 + tx];
    __syncthreads();
    #pragma unroll
    for (int r = 0; r < 32; r += 8) {
        const float v = t[tx][ty + r];
        const size_t o = base + (size_t)(n0 + ty + r) * K + k0 + tx;
        __nv_bfloat16 hh, ll;
        split1(v, hh, ll);
        h[o] = hh; l[o] = ll;
    }
}

// ---------------------------------------------------------------------------
// Attention kernels (fp32, unchanged)
// ---------------------------------------------------------------------------
__global__ __launch_bounds__(256) void attn_scores(
    const float* __restrict__ Q, const float* __restrict__ Km,
    const float* __restrict__ mask, const int* __restrict__ pad,
    float* __restrict__ S)
{
    __shared__ float Qs[64][65];
    __shared__ float Ks[64][65];
    const int tid = threadIdx.x;
    const int kx  = blockIdx.x * 64;
    const int qy  = blockIdx.y * 64;
    const int bh  = blockIdx.z;
    const int b   = bh >> 4;
    const int h   = bh & 15;
    const int hcol = h * HDc;

    for (int i = tid; i < 64 * 16; i += 256) {
        int r = i >> 4;
        int c = (i & 15) << 2;
        float4 q4 = *(const float4*)&Q [(size_t)(b * Lc + qy + r) * Dc + hcol + c];
        Qs[r][c] = q4.x; Qs[r][c+1] = q4.y; Qs[r][c+2] = q4.z; Qs[r][c+3] = q4.w;
        float4 k4 = *(const float4*)&Km[(size_t)(b * Lc + kx + r) * Dc + hcol + c];
        Ks[r][c] = k4.x; Ks[r][c+1] = k4.y; Ks[r][c+2] = k4.z; Ks[r][c+3] = k4.w;
    }
    __syncthreads();

    const int tr = (tid >> 4) << 2;
    const int tc = (tid & 15) << 2;
    float acc[4][4];
    #pragma unroll
    for (int i = 0; i < 4; i++)
        #pragma unroll
        for (int j = 0; j < 4; j++) acc[i][j] = 0.f;

    #pragma unroll 8
    for (int k = 0; k < 64; k++) {
        float ra[4], rb[4];
        #pragma unroll
        for (int i = 0; i < 4; i++) ra[i] = Qs[tr + i][k];
        #pragma unroll
        for (int j = 0; j < 4; j++) rb[j] = Ks[tc + j][k];
        #pragma unroll
        for (int i = 0; i < 4; i++)
            #pragma unroll
            for (int j = 0; j < 4; j++)
                acc[i][j] += ra[i] * rb[j];
    }

    #pragma unroll
    for (int i = 0; i < 4; i++) {
        const int q = qy + tr + i;
        #pragma unroll
        for (int j = 0; j < 4; j++) {
            const int kc = kx + tc + j;
            float v = acc[i][j] * 0.125f
                    + mask[(size_t)q * Lc + kc]
                    + (float)pad[b * Lc + kc];
            S[((size_t)bh * Lc + q) * Lc + kc] = v;
        }
    }
}

__global__ __launch_bounds__(256) void softmax_rows(float* __restrict__ S)
{
    __shared__ float red[8];
    const int tid = threadIdx.x;
    float* row = S + (size_t)blockIdx.x * 1024;
    float4 v = *(float4*)&row[tid * 4];

    float m = fmaxf(fmaxf(v.x, v.y), fmaxf(v.z, v.w));
    #pragma unroll
    for (int o = 16; o > 0; o >>= 1) m = fmaxf(m, __shfl_xor_sync(0xffffffffu, m, o));
    if ((tid & 31) == 0) red[tid >> 5] = m;
    __syncthreads();
    m = red[0];
    #pragma unroll
    for (int i = 1; i < 8; i++) m = fmaxf(m, red[i]);
    __syncthreads();

    v.x = __expf(v.x - m); v.y = __expf(v.y - m);
    v.z = __expf(v.z - m); v.w = __expf(v.w - m);
    float s = v.x + v.y + v.z + v.w;
    #pragma unroll
    for (int o = 16; o > 0; o >>= 1) s += __shfl_xor_sync(0xffffffffu, s, o);
    if ((tid & 31) == 0) red[tid >> 5] = s;
    __syncthreads();
    s = red[0];
    #pragma unroll
    for (int i = 1; i < 8; i++) s += red[i];

    const float inv = 1.f / s;
    v.x *= inv; v.y *= inv; v.z *= inv; v.w *= inv;
    *(float4*)&row[tid * 4] = v;
}

__global__ __launch_bounds__(256) void attn_pv(
    const float* __restrict__ P, const float* __restrict__ V,
    float* __restrict__ O)
{
    __shared__ float Ps[64][65];
    __shared__ float Vs[64][65];
    const int tid = threadIdx.x;
    const int qy  = blockIdx.x * 64;
    const int bh  = blockIdx.y;
    const int b   = bh >> 4;
    const int h   = bh & 15;
    const int hcol = h * HDc;
    const int tr = (tid >> 4) << 2;
    const int tc = (tid & 15) << 2;

    float acc[4][4];
    #pragma unroll
    for (int i = 0; i < 4; i++)
        #pragma unroll
        for (int j = 0; j < 4; j++) acc[i][j] = 0.f;

    for (int kt = 0; kt < Lc; kt += 64) {
        for (int i = tid; i < 64 * 16; i += 256) {
            int r = i >> 4;
            int c = (i & 15) << 2;
            float4 p4 = *(const float4*)&P[((size_t)bh * Lc + qy + r) * Lc + kt + c];
            Ps[r][c] = p4.x; Ps[r][c+1] = p4.y; Ps[r][c+2] = p4.z; Ps[r][c+3] = p4.w;
            float4 v4 = *(const float4*)&V[(size_t)(b * Lc + kt + r) * Dc + hcol + c];
            Vs[r][c] = v4.x; Vs[r][c+1] = v4.y; Vs[r][c+2] = v4.z; Vs[r][c+3] = v4.w;
        }
        __syncthreads();

        #pragma unroll 8
        for (int k = 0; k < 64; k++) {
            float ra[4], rb[4];
            #pragma unroll
            for (int i = 0; i < 4; i++) ra[i] = Ps[tr + i][k];
            #pragma unroll
            for (int j = 0; j < 4; j++) rb[j] = Vs[k][tc + j];
            #pragma unroll
            for (int i = 0; i < 4; i++)
                #pragma unroll
                for (int j = 0; j < 4; j++)
                    acc[i][j] += ra[i] * rb[j];
        }
        __syncthreads();
    }

    #pragma unroll
    for (int i = 0; i < 4; i++)
        #pragma unroll
        for (int j = 0; j < 4; j++)
            O[(size_t)(b * Lc + qy + tr + i) * Dc + hcol + tc + j] = acc[i][j];
}

__global__ __launch_bounds__(256) void add_ln(
    const float* __restrict__ x, const float* __restrict__ res,
    const float* __restrict__ g, const float* __restrict__ bta,
    float* __restrict__ y)
{
    __shared__ float rs[8], rq[8];
    const int tid = threadIdx.x;
    const size_t base = (size_t)blockIdx.x * 1024 + tid * 4;

    float4 a = *(const float4*)&x[base];
    float4 r = *(const float4*)&res[base];
    a.x += r.x; a.y += r.y; a.z += r.z; a.w += r.w;

    float s = a.x + a.y + a.z + a.w;
    float q = a.x*a.x + a.y*a.y + a.z*a.z + a.w*a.w;
    #pragma unroll
    for (int o = 16; o > 0; o >>= 1) {
        s += __shfl_xor_sync(0xffffffffu, s, o);
        q += __shfl_xor_sync(0xffffffffu, q, o);
    }
    if ((tid & 31) == 0) { rs[tid >> 5] = s; rq[tid >> 5] = q; }
    __syncthreads();
    s = 0.f; q = 0.f;
    #pragma unroll
    for (int i = 0; i < 8; i++) { s += rs[i]; q += rq[i]; }

    const float mean = s * (1.f / 1024.f);
    const float var  = q * (1.f / 1024.f) - mean * mean;
    const float rstd = rsqrtf(var + 1e-5f);

    const int c = tid * 4;
    float4 gv = *(const float4*)&g[c];
    float4 bv = *(const float4*)&bta[c];
    float4 o;
    o.x = (a.x - mean) * rstd * gv.x + bv.x;
    o.y = (a.y - mean) * rstd * gv.y + bv.y;
    o.z = (a.z - mean) * rstd * gv.z + bv.z;
    o.w = (a.w - mean) * rstd * gv.w + bv.w;
    *(float4*)&y[base] = o;
}

// ---------------------------------------------------------------------------
// Launch orchestration
// ---------------------------------------------------------------------------
extern "C" void kernel_launch(void* const* d_in, const int* in_sizes, int n_in,
                              void* d_out, int out_size)
{
    const float* T    = (const float*)d_in[0];
    const float* A    = (const float*)d_in[1];
    const float* mask = (const float*)d_in[2];
    const int*   pad  = (const int*)  d_in[3];
    const float* Wq   = (const float*)d_in[4];
    const float* bq   = (const float*)d_in[5];
    const float* Wk   = (const float*)d_in[6];
    const float* bk   = (const float*)d_in[7];
    const float* Wv   = (const float*)d_in[8];
    const float* bv   = (const float*)d_in[9];
    const float* Wo   = (const float*)d_in[10];
    const float* ffW1 = (const float*)d_in[11];
    const float* ffb1 = (const float*)d_in[12];
    const float* ffW2 = (const float*)d_in[13];
    const float* ffb2 = (const float*)d_in[14];
    const float* lng  = (const float*)d_in[15];
    const float* lnb  = (const float*)d_in[16];
    float* out = (float*)d_out;

    float *Qb, *Kb, *Vb, *Sb, *Ob, *Mo, *T1, *A1, *T2, *A2, *Hb;
    cudaGetSymbolAddress((void**)&Qb, g_Q);
    cudaGetSymbolAddress((void**)&Kb, g_K);
    cudaGetSymbolAddress((void**)&Vb, g_V);
    cudaGetSymbolAddress((void**)&Sb, g_S);
    cudaGetSymbolAddress((void**)&Ob, g_O);
    cudaGetSymbolAddress((void**)&Mo, g_M);
    cudaGetSymbolAddress((void**)&T1, g_T1);
    cudaGetSymbolAddress((void**)&A1, g_A1);
    cudaGetSymbolAddress((void**)&T2, g_T2);
    cudaGetSymbolAddress((void**)&A2, g_A2);
    cudaGetSymbolAddress((void**)&Hb, g_FH);

    __nv_bfloat16 *wqh,*wql,*wkh,*wkl,*wvh,*wvl,*woh,*wol;
    __nv_bfloat16 *w1h,*w1l,*w2h,*w2l,*xh1,*xl1,*xh2,*xl2;
    cudaGetSymbolAddress((void**)&wqh, g_wqh);
    cudaGetSymbolAddress((void**)&wql, g_wql);
    cudaGetSymbolAddress((void**)&wkh, g_wkh);
    cudaGetSymbolAddress((void**)&wkl, g_wkl);
    cudaGetSymbolAddress((void**)&wvh, g_wvh);
    cudaGetSymbolAddress((void**)&wvl, g_wvl);
    cudaGetSymbolAddress((void**)&woh, g_woh);
    cudaGetSymbolAddress((void**)&wol, g_wol);
    cudaGetSymbolAddress((void**)&w1h, g_w1h);
    cudaGetSymbolAddress((void**)&w1l, g_w1l);
    cudaGetSymbolAddress((void**)&w2h, g_w2h);
    cudaGetSymbolAddress((void**)&w2l, g_w2l);
    cudaGetSymbolAddress((void**)&xh1, g_xh1);
    cudaGetSymbolAddress((void**)&xl1, g_xl1);
    cudaGetSymbolAddress((void**)&xh2, g_xh2);
    cudaGetSymbolAddress((void**)&xl2, g_xl2);

    cudaFuncSetAttribute(gemm_mma, cudaFuncAttributeMaxDynamicSharedMemorySize, GEMM_SMEM);

    // weight transpose + bf16 split
    transpose_split<<<dim3(Dc/32, Dc/32, 4), 256>>>(Wq,   wqh, wql, Dc, Dc);
    transpose_split<<<dim3(Dc/32, Dc/32, 4), 256>>>(Wk,   wkh, wkl, Dc, Dc);
    transpose_split<<<dim3(Dc/32, Dc/32, 4), 256>>>(Wv,   wvh, wvl, Dc, Dc);
    transpose_split<<<dim3(Dc/32, Dc/32, 4), 256>>>(Wo,   woh, wol, Dc, Dc);
    transpose_split<<<dim3(Fc/32, Dc/32, 2), 256>>>(ffW1, w1h, w1l, Dc, Fc);
    transpose_split<<<dim3(Dc/32, Fc/32, 2), 256>>>(ffW2, w2h, w2l, Fc, Dc);

    auto gemm = [&](const __nv_bfloat16* ah, const __nv_bfloat16* al,
                    const __nv_bfloat16* bh, const __nv_bfloat16* bl,
                    const float* bias, float* c, int M, int N, int K, int relu) {
        gemm_mma<<<dim3(N/128, M/128), 256, GEMM_SMEM>>>(ah, al, bh, bl, bias, c, M, N, K, relu);
    };
    auto split = [&](const float* x, __nv_bfloat16* h, __nv_bfloat16* l, size_t n) {
        split_f32<<<(int)(n / 1024), 256>>>(x, h, l);
    };

    auto mha = [&](int i, const float* xq, const float* xk, float* ob) {
        const size_t wo = (size_t)i * Dc * Dc;
        split(xq, xh1, xl1, (size_t)BLc * Dc);
        gemm(xh1, xl1, wqh + wo, wql + wo, bq + i * Dc, Qb, BLc, Dc, Dc, 0);
        split(xk, xh2, xl2, (size_t)BLc * Dc);
        gemm(xh2, xl2, wkh + wo, wkl + wo, bk + i * Dc, Kb, BLc, Dc, Dc, 0);
        gemm(xh2, xl2, wvh + wo, wvl + wo, bv + i * Dc, Vb, BLc, Dc, Dc, 0);
        attn_scores<<<dim3(Lc/64, Lc/64, Bc*Hc), 256>>>(Qb, Kb, mask, pad, Sb);
        softmax_rows<<<Bc * Hc * Lc, 256>>>(Sb);
        attn_pv<<<dim3(Lc/64, Bc*Hc), 256>>>(Sb, Vb, Ob);
        split(Ob, xh1, xl1, (size_t)BLc * Dc);
        gemm(xh1, xl1, woh + wo, wol + wo, nullptr, ob, BLc, Dc, Dc, 0);
    };

    // Self-attention per modality
    mha(0, T, T, Mo);
    add_ln<<<BLc, 256>>>(T, Mo, lng + 0 * Dc, lnb + 0 * Dc, T1);
    mha(1, A, A, Mo);
    add_ln<<<BLc, 256>>>(A, Mo, lng + 1 * Dc, lnb + 1 * Dc, A1);
    // Cross-attention
    mha(2, T1, A1, Mo);
    add_ln<<<BLc, 256>>>(T1, Mo, lng + 2 * Dc, lnb + 2 * Dc, T2);
    mha(3, A1, T2, Mo);
    add_ln<<<BLc, 256>>>(A1, Mo, lng + 3 * Dc, lnb + 3 * Dc, A2);

    // FFNs -> d_out (T_out then A_out)
    split(T2, xh1, xl1, (size_t)BLc * Dc);
    gemm(xh1, xl1, w1h, w1l, ffb1, Hb, BLc, Fc, Dc, 1);
    split(Hb, xh1, xl1, (size_t)BLc * Fc);
    gemm(xh1, xl1, w2h, w2l, ffb2, out, BLc, Dc, Fc, 0);

    split(A2, xh1, xl1, (size_t)BLc * Dc);
    gemm(xh1, xl1, w1h + (size_t)Dc * Fc, w1l + (size_t)Dc * Fc, ffb1 + Fc, Hb, BLc, Fc, Dc, 1);
    split(Hb, xh1, xl1, (size_t)BLc * Fc);
    gemm(xh1, xl1, w2h + (size_t)Fc * Dc, w2l + (size_t)Fc * Dc, ffb2 + Dc,
         out + (size_t)BLc * Dc, BLc, Dc, Fc, 0);
}

// round 4
// speedup vs baseline: 2.7546x; 1.5615x over previous
#include <cuda_runtime.h>
#include <cuda_bf16.h>
#include <math.h>
#include <stdint.h>

// Problem constants
constexpr int Bc  = 4;
constexpr int Lc  = 1024;
constexpr int Dc  = 1024;
constexpr int Fc  = 4096;
constexpr int Hc  = 16;
constexpr int HDc = 64;
constexpr int BLc = Bc * Lc;          // 4096 rows

// ---------------------------------------------------------------------------
// Scratch (static __device__ arrays — allocation-free per harness rules)
// ---------------------------------------------------------------------------
__device__ float g_Q [BLc * Dc];
__device__ float g_K [BLc * Dc];
__device__ float g_V [BLc * Dc];
__device__ float g_O [BLc * Dc];
__device__ float g_M [BLc * Dc];
__device__ float g_T1[BLc * Dc];
__device__ float g_A1[BLc * Dc];
__device__ float g_T2[BLc * Dc];
__device__ float g_A2[BLc * Dc];
__device__ float g_FH[BLc * Fc];                    // FFN hidden (fp32)

// bf16 split weights (transposed to [N,K]) and activations
__device__ __nv_bfloat16 g_wqh[4*Dc*Dc], g_wql[4*Dc*Dc];
__device__ __nv_bfloat16 g_wkh[4*Dc*Dc], g_wkl[4*Dc*Dc];
__device__ __nv_bfloat16 g_wvh[4*Dc*Dc], g_wvl[4*Dc*Dc];
__device__ __nv_bfloat16 g_woh[4*Dc*Dc], g_wol[4*Dc*Dc];
__device__ __nv_bfloat16 g_w1h[2*Dc*Fc], g_w1l[2*Dc*Fc];   // ff1^T : [F, D]
__device__ __nv_bfloat16 g_w2h[2*Fc*Dc], g_w2l[2*Fc*Dc];   // ff2^T : [D, F]
__device__ __nv_bfloat16 g_xh1[(size_t)BLc*Fc], g_xl1[(size_t)BLc*Fc];
__device__ __nv_bfloat16 g_xh2[(size_t)BLc*Dc], g_xl2[(size_t)BLc*Dc];

// ---------------------------------------------------------------------------
// PTX helpers (sm_103 baseline-safe: mma.sync + ldmatrix + cp.async only)
// ---------------------------------------------------------------------------
__device__ __forceinline__ uint32_t smem_u32(const void* p) {
    uint32_t a;
    asm("{ .reg .u64 t; cvta.to.shared.u64 t, %1; cvt.u32.u64 %0, t; }" : "=r"(a) : "l"(p));
    return a;
}
__device__ __forceinline__ void cpasync16(uint32_t dst, const void* src) {
    asm volatile("cp.async.cg.shared.global [%0], [%1], 16;" :: "r"(dst), "l"(src));
}
#define CP_COMMIT()  asm volatile("cp.async.commit_group;" ::: "memory")
#define CP_WAIT(n)   asm volatile("cp.async.wait_group %0;" :: "n"(n) : "memory")

#define LDSM4(r, a) \
    asm volatile("ldmatrix.sync.aligned.m8n8.x4.shared.b16 {%0,%1,%2,%3}, [%4];" \
        : "=r"((r)[0]), "=r"((r)[1]), "=r"((r)[2]), "=r"((r)[3]) : "r"(a))
#define LDSM4T(r, a) \
    asm volatile("ldmatrix.sync.aligned.m8n8.x4.trans.shared.b16 {%0,%1,%2,%3}, [%4];" \
        : "=r"((r)[0]), "=r"((r)[1]), "=r"((r)[2]), "=r"((r)[3]) : "r"(a))

__device__ __forceinline__ void mma16816(float* c, const uint32_t* a, const uint32_t* b) {
    asm volatile(
        "mma.sync.aligned.m16n8k16.row.col.f32.bf16.bf16.f32 "
        "{%0,%1,%2,%3}, {%4,%5,%6,%7}, {%8,%9}, {%0,%1,%2,%3};"
        : "+f"(c[0]), "+f"(c[1]), "+f"(c[2]), "+f"(c[3])
        : "r"(a[0]), "r"(a[1]), "r"(a[2]), "r"(a[3]), "r"(b[0]), "r"(b[1]));
}

__device__ __forceinline__ void split1(float v, __nv_bfloat16& h, __nv_bfloat16& l) {
    h = __float2bfloat16(v);
    l = __float2bfloat16(v - __bfloat162float(h));
}
__device__ __forceinline__ uint32_t packbf(float a, float b) {
    __nv_bfloat162 t; t.x = __float2bfloat16(a); t.y = __float2bfloat16(b);
    return *(uint32_t*)&t;
}

// ---------------------------------------------------------------------------
// Tensor-core GEMM (unchanged from round 3 — passing)
// ---------------------------------------------------------------------------
constexpr int GSTR    = 40;
constexpr int TILE_B  = 128 * GSTR * 2;
constexpr int STAGE_B = 4 * TILE_B;
constexpr int GEMM_SMEM = 2 * STAGE_B;

__global__ __launch_bounds__(256, 2) void gemm_mma(
    const __nv_bfloat16* __restrict__ Ah, const __nv_bfloat16* __restrict__ Al,
    const __nv_bfloat16* __restrict__ Bh, const __nv_bfloat16* __restrict__ Bl,
    const float* __restrict__ bias, float* __restrict__ C,
    int M, int N, int K, int relu)
{
    extern __shared__ char sm[];
    const uint32_t sb = smem_u32(sm);
    const int tid  = threadIdx.x;
    const int wid  = tid >> 5;
    const int lane = tid & 31;
    const int brow = blockIdx.y * 128;
    const int bcol = blockIdx.x * 128;
    const int wm   = (wid & 1) * 64;
    const int wn   = (wid >> 1) * 32;

    float acc[4][4][4];
    #pragma unroll
    for (int i = 0; i < 4; i++)
        #pragma unroll
        for (int j = 0; j < 4; j++)
            #pragma unroll
            for (int k = 0; k < 4; k++) acc[i][j][k] = 0.f;

    const int r0 = tid >> 2,            q0 = tid & 3;
    const int r1 = (tid + 256) >> 2,    q1 = (tid + 256) & 3;
    const int nch = K >> 5;

    auto issue = [&](int c, int s) {
        const int kc = c << 5;
        const uint32_t st = sb + s * STAGE_B;
        {
            const uint32_t so = (uint32_t)(r0 * 80 + q0 * 16);
            const size_t ga = (size_t)(brow + r0) * K + kc + q0 * 8;
            const size_t gb = (size_t)(bcol + r0) * K + kc + q0 * 8;
            cpasync16(st + so,              Ah + ga);
            cpasync16(st + TILE_B + so,     Al + ga);
            cpasync16(st + 2*TILE_B + so,   Bh + gb);
            cpasync16(st + 3*TILE_B + so,   Bl + gb);
        }
        {
            const uint32_t so = (uint32_t)(r1 * 80 + q1 * 16);
            const size_t ga = (size_t)(brow + r1) * K + kc + q1 * 8;
            const size_t gb = (size_t)(bcol + r1) * K + kc + q1 * 8;
            cpasync16(st + so,              Ah + ga);
            cpasync16(st + TILE_B + so,     Al + ga);
            cpasync16(st + 2*TILE_B + so,   Bh + gb);
            cpasync16(st + 3*TILE_B + so,   Bl + gb);
        }
        CP_COMMIT();
    };

    issue(0, 0);

    const int a_row = (lane & 15);
    const int a_kof = ((lane >> 4) << 3);
    const int g8    = lane >> 3;
    const int b_nt  = (g8 >> 1) << 3;
    const int b_kof = (g8 & 1) << 3;
    const int b_row = (lane & 7);

    for (int c = 0; c < nch; c++) {
        if (c + 1 < nch) { issue(c + 1, (c + 1) & 1); CP_WAIT(1); }
        else             { CP_WAIT(0); }
        __syncthreads();

        const uint32_t st = sb + (c & 1) * STAGE_B;
        #pragma unroll
        for (int k16 = 0; k16 < 32; k16 += 16) {
            uint32_t aH[4][4], bH[4][2], t[4];
            #pragma unroll
            for (int mt = 0; mt < 4; mt++) {
                uint32_t ad = st + (uint32_t)((wm + mt*16 + a_row) * 80
                                              + (k16 + a_kof) * 2);
                LDSM4(aH[mt], ad);
            }
            #pragma unroll
            for (int p = 0; p < 2; p++) {
                uint32_t ad = st + 2*TILE_B
                    + (uint32_t)((wn + p*16 + b_nt + b_row) * 80
                                 + (k16 + b_kof) * 2);
                LDSM4(t, ad);
                bH[2*p    ][0] = t[0]; bH[2*p    ][1] = t[1];
                bH[2*p + 1][0] = t[2]; bH[2*p + 1][1] = t[3];
            }
            #pragma unroll
            for (int mt = 0; mt < 4; mt++)
                #pragma unroll
                for (int nt = 0; nt < 4; nt++)
                    mma16816(acc[mt][nt], aH[mt], bH[nt]);
            #pragma unroll
            for (int p = 0; p < 2; p++) {
                uint32_t ad = st + 3*TILE_B
                    + (uint32_t)((wn + p*16 + b_nt + b_row) * 80
                                 + (k16 + b_kof) * 2);
                LDSM4(t, ad);
                uint32_t bl0[2] = { t[0], t[1] }, bl1[2] = { t[2], t[3] };
                #pragma unroll
                for (int mt = 0; mt < 4; mt++) {
                    mma16816(acc[mt][2*p    ], aH[mt], bl0);
                    mma16816(acc[mt][2*p + 1], aH[mt], bl1);
                }
            }
            #pragma unroll
            for (int mt = 0; mt < 4; mt++) {
                uint32_t ad = st + TILE_B
                    + (uint32_t)((wm + mt*16 + a_row) * 80
                                 + (k16 + a_kof) * 2);
                LDSM4(t, ad);
                #pragma unroll
                for (int nt = 0; nt < 4; nt++)
                    mma16816(acc[mt][nt], t, bH[nt]);
            }
        }
        __syncthreads();
    }

    const int g  = lane >> 2;
    const int tg = lane & 3;
    #pragma unroll
    for (int mt = 0; mt < 4; mt++) {
        #pragma unroll
        for (int nt = 0; nt < 4; nt++) {
            const int row = brow + wm + mt*16 + g;
            const int col = bcol + wn + nt*8 + tg*2;
            float2 v0, v1;
            v0.x = acc[mt][nt][0]; v0.y = acc[mt][nt][1];
            v1.x = acc[mt][nt][2]; v1.y = acc[mt][nt][3];
            if (bias) {
                float2 bb = *(const float2*)&bias[col];
                v0.x += bb.x; v0.y += bb.y; v1.x += bb.x; v1.y += bb.y;
            }
            if (relu) {
                v0.x = fmaxf(v0.x, 0.f); v0.y = fmaxf(v0.y, 0.f);
                v1.x = fmaxf(v1.x, 0.f); v1.y = fmaxf(v1.y, 0.f);
            }
            *(float2*)&C[(size_t)row * N + col]       = v0;
            *(float2*)&C[(size_t)(row + 8) * N + col] = v1;
        }
    }
}

// ---------------------------------------------------------------------------
// Fused flash attention (tensor cores, split-bf16 QK and PV, online softmax).
// Block: 128 q-rows of one (b,h). 8 warps x 16 q-rows. Loop over 8 k-tiles.
// ---------------------------------------------------------------------------
constexpr int FATT_STR  = 72;                         // bf16 row stride
constexpr int FATT_TB   = 128 * FATT_STR * 2;         // 18432 B per tile
constexpr int FATT_SMEM = 4 * FATT_TB + 512;          // Kh,Kl,Vh,Vl + pad

__global__ __launch_bounds__(256, 1) void flash_attn(
    const float* __restrict__ Qg, const float* __restrict__ Kg,
    const float* __restrict__ Vg, const float* __restrict__ mask,
    const int* __restrict__ pad, float* __restrict__ Og)
{
    extern __shared__ char sm[];
    const uint32_t sb = smem_u32(sm);
    const int tid  = threadIdx.x;
    const int wid  = tid >> 5;
    const int lane = tid & 31;
    const int qy   = blockIdx.x * 128;
    const int bh   = blockIdx.y;
    const int b    = bh >> 4;
    const int hcol = (bh & 15) * HDc;
    const int wq   = wid * 16;

    const uint32_t sKh = sb;                   // aliases Qh during init
    const uint32_t sKl = sb + FATT_TB;         // aliases Ql during init
    const uint32_t sVh = sb + 2 * FATT_TB;
    const uint32_t sVl = sb + 3 * FATT_TB;
    float* spad = (float*)(sm + 4 * FATT_TB);

    // ---- load Q tile (fp32 -> bf16 hi/lo in smem), then to A-fragments ----
    for (int i = tid; i < 2048; i += 256) {        // 128 rows x 16 float4
        const int r = i >> 4, c = (i & 15) << 2;
        float4 v = *(const float4*)&Qg[(size_t)(b*Lc + qy + r) * Dc + hcol + c];
        __nv_bfloat16 h0,l0,h1,l1,h2,l2,h3,l3;
        split1(v.x,h0,l0); split1(v.y,h1,l1); split1(v.z,h2,l2); split1(v.w,h3,l3);
        __nv_bfloat162* ph = (__nv_bfloat162*)(sm + (r*FATT_STR + c)*2);
        __nv_bfloat162* pl = (__nv_bfloat162*)(sm + FATT_TB + (r*FATT_STR + c)*2);
        __nv_bfloat162 t0; t0.x=h0; t0.y=h1;  ph[0]=t0;
        __nv_bfloat162 t1; t1.x=h2; t1.y=h3;  ph[1]=t1;
        __nv_bfloat162 t2; t2.x=l0; t2.y=l1;  pl[0]=t2;
        __nv_bfloat162 t3; t3.x=l2; t3.y=l3;  pl[1]=t3;
    }
    __syncthreads();

    const int a_row = lane & 15;
    const int a_kof = (lane >> 4) << 3;
    uint32_t qh[4][4], ql[4][4];
    #pragma unroll
    for (int kt = 0; kt < 4; kt++) {
        const uint32_t off = (uint32_t)(((wq + a_row)*FATT_STR + kt*16 + a_kof)*2);
        LDSM4(qh[kt], sKh + off);
        LDSM4(ql[kt], sKl + off);
    }

    // online-softmax state + O accumulators
    float m[2] = { -1e30f, -1e30f };
    float l[2] = { 0.f, 0.f };
    float o[8][4];
    #pragma unroll
    for (int i = 0; i < 8; i++)
        #pragma unroll
        for (int j = 0; j < 4; j++) o[i][j] = 0.f;

    const int g    = lane >> 2;
    const int tg   = lane & 3;
    const int g8   = lane >> 3;
    const int b_nt  = (g8 >> 1) << 3;
    const int b_kof = (g8 & 1) << 3;
    const int b_row = lane & 7;
    // V^T (trans ldmatrix) addressing
    const int v_kv = ((lane >> 3) & 1) << 3;
    const int v_d  = (lane >> 4) << 3;

    for (int t = 0; t < 8; t++) {
        const int kx = t * 128;
        __syncthreads();   // prior reads of K/V smem (or Q frags) complete

        // ---- load K and V tiles (fp32 -> split) ----
        for (int i = tid; i < 2048; i += 256) {
            const int r = i >> 4, c = (i & 15) << 2;
            const size_t gidx = (size_t)(b*Lc + kx + r) * Dc + hcol + c;
            const uint32_t so = (uint32_t)((r*FATT_STR + c)*2);
            {
                float4 v = *(const float4*)&Kg[gidx];
                __nv_bfloat16 h0,l0,h1,l1,h2,l2,h3,l3;
                split1(v.x,h0,l0); split1(v.y,h1,l1);
                split1(v.z,h2,l2); split1(v.w,h3,l3);
                __nv_bfloat162 t0; t0.x=h0; t0.y=h1;
                __nv_bfloat162 t1; t1.x=h2; t1.y=h3;
                __nv_bfloat162 t2; t2.x=l0; t2.y=l1;
                __nv_bfloat162 t3; t3.x=l2; t3.y=l3;
                *(__nv_bfloat162*)(sm + so)              = t0;
                *(__nv_bfloat162*)(sm + so + 4)          = t1;
                *(__nv_bfloat162*)(sm + FATT_TB + so)    = t2;
                *(__nv_bfloat162*)(sm + FATT_TB + so + 4)= t3;
            }
            {
                float4 v = *(const float4*)&Vg[gidx];
                __nv_bfloat16 h0,l0,h1,l1,h2,l2,h3,l3;
                split1(v.x,h0,l0); split1(v.y,h1,l1);
                split1(v.z,h2,l2); split1(v.w,h3,l3);
                __nv_bfloat162 t0; t0.x=h0; t0.y=h1;
                __nv_bfloat162 t1; t1.x=h2; t1.y=h3;
                __nv_bfloat162 t2; t2.x=l0; t2.y=l1;
                __nv_bfloat162 t3; t3.x=l2; t3.y=l3;
                *(__nv_bfloat162*)(sm + 2*FATT_TB + so)      = t0;
                *(__nv_bfloat162*)(sm + 2*FATT_TB + so + 4)  = t1;
                *(__nv_bfloat162*)(sm + 3*FATT_TB + so)      = t2;
                *(__nv_bfloat162*)(sm + 3*FATT_TB + so + 4)  = t3;
            }
        }
        if (tid < 128) spad[tid] = (float)pad[b*Lc + kx + tid];
        __syncthreads();

        // ---- S = Q K^T (split, fp32 frags) ----
        float sf[16][4];
        #pragma unroll
        for (int i = 0; i < 16; i++)
            #pragma unroll
            for (int j = 0; j < 4; j++) sf[i][j] = 0.f;

        #pragma unroll
        for (int kst = 0; kst < 4; kst++) {
            uint32_t kb[8][4];
            #pragma unroll
            for (int p = 0; p < 8; p++) {
                const uint32_t ad = sKh + (uint32_t)(((p*16 + b_nt + b_row)*FATT_STR
                                                      + kst*16 + b_kof)*2);
                LDSM4(kb[p], ad);
            }
            #pragma unroll
            for (int p = 0; p < 8; p++) {
                uint32_t b0[2] = { kb[p][0], kb[p][1] };
                uint32_t b1[2] = { kb[p][2], kb[p][3] };
                mma16816(sf[2*p],   qh[kst], b0);
                mma16816(sf[2*p+1], qh[kst], b1);
                mma16816(sf[2*p],   ql[kst], b0);
                mma16816(sf[2*p+1], ql[kst], b1);
            }
            #pragma unroll
            for (int p = 0; p < 8; p++) {
                const uint32_t ad = sKl + (uint32_t)(((p*16 + b_nt + b_row)*FATT_STR
                                                      + kst*16 + b_kof)*2);
                LDSM4(kb[p], ad);
            }
            #pragma unroll
            for (int p = 0; p < 8; p++) {
                uint32_t b0[2] = { kb[p][0], kb[p][1] };
                uint32_t b1[2] = { kb[p][2], kb[p][3] };
                mma16816(sf[2*p],   qh[kst], b0);
                mma16816(sf[2*p+1], qh[kst], b1);
            }
        }

        // ---- scale + mask + pad ----
        const int qg0 = qy + wq + g;
        #pragma unroll
        for (int nt = 0; nt < 16; nt++) {
            const int kvl = nt*8 + tg*2;
            const int kvg = kx + kvl;
            float2 m0 = *(const float2*)&mask[(size_t)qg0 * Lc + kvg];
            float2 m1 = *(const float2*)&mask[(size_t)(qg0 + 8) * Lc + kvg];
            const float p0 = spad[kvl], p1 = spad[kvl + 1];
            sf[nt][0] = sf[nt][0]*0.125f + m0.x + p0;
            sf[nt][1] = sf[nt][1]*0.125f + m0.y + p1;
            sf[nt][2] = sf[nt][2]*0.125f + m1.x + p0;
            sf[nt][3] = sf[nt][3]*0.125f + m1.y + p1;
        }

        // ---- online softmax ----
        float mx0 = m[0], mx1 = m[1];
        #pragma unroll
        for (int nt = 0; nt < 16; nt++) {
            mx0 = fmaxf(mx0, fmaxf(sf[nt][0], sf[nt][1]));
            mx1 = fmaxf(mx1, fmaxf(sf[nt][2], sf[nt][3]));
        }
        mx0 = fmaxf(mx0, __shfl_xor_sync(0xffffffffu, mx0, 1));
        mx0 = fmaxf(mx0, __shfl_xor_sync(0xffffffffu, mx0, 2));
        mx1 = fmaxf(mx1, __shfl_xor_sync(0xffffffffu, mx1, 1));
        mx1 = fmaxf(mx1, __shfl_xor_sync(0xffffffffu, mx1, 2));

        const float al0 = __expf(m[0] - mx0);
        const float al1 = __expf(m[1] - mx1);
        m[0] = mx0; m[1] = mx1;
        #pragma unroll
        for (int nt = 0; nt < 8; nt++) {
            o[nt][0] *= al0; o[nt][1] *= al0;
            o[nt][2] *= al1; o[nt][3] *= al1;
        }

        uint32_t ph[8][4], pl[8][4];
        float s0 = 0.f, s1 = 0.f;
        #pragma unroll
        for (int j = 0; j < 8; j++) {
            float e00 = __expf(sf[2*j][0]   - mx0);
            float e01 = __expf(sf[2*j][1]   - mx0);
            float e10 = __expf(sf[2*j][2]   - mx1);
            float e11 = __expf(sf[2*j][3]   - mx1);
            float e20 = __expf(sf[2*j+1][0] - mx0);
            float e21 = __expf(sf[2*j+1][1] - mx0);
            float e30 = __expf(sf[2*j+1][2] - mx1);
            float e31 = __expf(sf[2*j+1][3] - mx1);
            s0 += e00 + e01 + e20 + e21;
            s1 += e10 + e11 + e30 + e31;
            ph[j][0] = packbf(e00, e01);
            ph[j][1] = packbf(e10, e11);
            ph[j][2] = packbf(e20, e21);
            ph[j][3] = packbf(e30, e31);
            __nv_bfloat162* hp = (__nv_bfloat162*)&ph[j][0];
            pl[j][0] = packbf(e00 - __bfloat162float(hp[0].x),
                              e01 - __bfloat162float(hp[0].y));
            hp = (__nv_bfloat162*)&ph[j][1];
            pl[j][1] = packbf(e10 - __bfloat162float(hp[0].x),
                              e11 - __bfloat162float(hp[0].y));
            hp = (__nv_bfloat162*)&ph[j][2];
            pl[j][2] = packbf(e20 - __bfloat162float(hp[0].x),
                              e21 - __bfloat162float(hp[0].y));
            hp = (__nv_bfloat162*)&ph[j][3];
            pl[j][3] = packbf(e30 - __bfloat162float(hp[0].x),
                              e31 - __bfloat162float(hp[0].y));
        }
        s0 += __shfl_xor_sync(0xffffffffu, s0, 1);
        s0 += __shfl_xor_sync(0xffffffffu, s0, 2);
        s1 += __shfl_xor_sync(0xffffffffu, s1, 1);
        s1 += __shfl_xor_sync(0xffffffffu, s1, 2);
        l[0] = l[0]*al0 + s0;
        l[1] = l[1]*al1 + s1;

        // ---- O += P V (split) ----
        #pragma unroll
        for (int j = 0; j < 8; j++) {
            #pragma unroll
            for (int p = 0; p < 4; p++) {
                uint32_t th[4], tl[4];
                const uint32_t off = (uint32_t)(((j*16 + v_kv + b_row)*FATT_STR
                                                 + p*16 + v_d)*2);
                LDSM4T(th, sVh + off);
                LDSM4T(tl, sVl + off);
                uint32_t bh0[2] = { th[0], th[1] }, bh1[2] = { th[2], th[3] };
                uint32_t bl0[2] = { tl[0], tl[1] }, bl1[2] = { tl[2], tl[3] };
                mma16816(o[2*p],   ph[j], bh0);
                mma16816(o[2*p+1], ph[j], bh1);
                mma16816(o[2*p],   ph[j], bl0);
                mma16816(o[2*p+1], ph[j], bl1);
                mma16816(o[2*p],   pl[j], bh0);
                mma16816(o[2*p+1], pl[j], bh1);
            }
        }
    }

    // ---- finalize: O /= l, write ----
    const float inv0 = 1.f / l[0];
    const float inv1 = 1.f / l[1];
    const int row = b*Lc + qy + wq + g;
    #pragma unroll
    for (int nt = 0; nt < 8; nt++) {
        const int col = hcol + nt*8 + tg*2;
        float2 v0, v1;
        v0.x = o[nt][0]*inv0; v0.y = o[nt][1]*inv0;
        v1.x = o[nt][2]*inv1; v1.y = o[nt][3]*inv1;
        *(float2*)&Og[(size_t)row * Dc + col]       = v0;
        *(float2*)&Og[(size_t)(row + 8) * Dc + col] = v1;
    }
}

// ---------------------------------------------------------------------------
// fp32 -> bf16 hi/lo split
// ---------------------------------------------------------------------------
__global__ __launch_bounds__(256) void split_f32(
    const float* __restrict__ x, __nv_bfloat16* __restrict__ h,
    __nv_bfloat16* __restrict__ l)
{
    const size_t i = ((size_t)blockIdx.x * 256 + threadIdx.x) * 4;
    float4 v = *(const float4*)(x + i);
    __nv_bfloat16 h0, h1, h2, h3, l0, l1, l2, l3;
    split1(v.x, h0, l0); split1(v.y, h1, l1);
    split1(v.z, h2, l2); split1(v.w, h3, l3);
    __nv_bfloat162 hh0; hh0.x = h0; hh0.y = h1;
    __nv_bfloat162 hh1; hh1.x = h2; hh1.y = h3;
    __nv_bfloat162 ll0; ll0.x = l0; ll0.y = l1;
    __nv_bfloat162 ll1; ll1.x = l2; ll1.y = l3;
    *(__nv_bfloat162*)(h + i)     = hh0;
    *(__nv_bfloat162*)(h + i + 2) = hh1;
    *(__nv_bfloat162*)(l + i)     = ll0;
    *(__nv_bfloat162*)(l + i + 2) = ll1;
}

// ---------------------------------------------------------------------------
// W[K,N] fp32 -> Wt[N,K] bf16 hi/lo, batched over blockIdx.z
// ---------------------------------------------------------------------------
__global__ __launch_bounds__(256) void transpose_split(
    const float* __restrict__ W, __nv_bfloat16* __restrict__ h,
    __nv_bfloat16* __restrict__ l, int K, int N)
{
    __shared__ float t[32][33];
    const size_t base = (size_t)blockIdx.z * K * N;
    const int k0 = blockIdx.y * 32, n0 = blockIdx.x * 32;
    const int tx = threadIdx.x & 31, ty = threadIdx.x >> 5;
    #pragma unroll
    for (int r = 0; r < 32; r += 8)
        t[ty + r][tx] = W[base + (size_t)(k0 + ty + r) * N + n0 + tx];
    __syncthreads();
    #pragma unroll
    for (int r = 0; r < 32; r += 8) {
        const float v = t[tx][ty + r];
        const size_t o = base + (size_t)(n0 + ty + r) * K + k0 + tx;
        __nv_bfloat16 hh, ll;
        split1(v, hh, ll);
        h[o] = hh; l[o] = ll;
    }
}

// ---------------------------------------------------------------------------
// y = LayerNorm(x + res) * g + b
// ---------------------------------------------------------------------------
__global__ __launch_bounds__(256) void add_ln(
    const float* __restrict__ x, const float* __restrict__ res,
    const float* __restrict__ g, const float* __restrict__ bta,
    float* __restrict__ y)
{
    __shared__ float rs[8], rq[8];
    const int tid = threadIdx.x;
    const size_t base = (size_t)blockIdx.x * 1024 + tid * 4;

    float4 a = *(const float4*)&x[base];
    float4 r = *(const float4*)&res[base];
    a.x += r.x; a.y += r.y; a.z += r.z; a.w += r.w;

    float s = a.x + a.y + a.z + a.w;
    float q = a.x*a.x + a.y*a.y + a.z*a.z + a.w*a.w;
    #pragma unroll
    for (int o = 16; o > 0; o >>= 1) {
        s += __shfl_xor_sync(0xffffffffu, s, o);
        q += __shfl_xor_sync(0xffffffffu, q, o);
    }
    if ((tid & 31) == 0) { rs[tid >> 5] = s; rq[tid >> 5] = q; }
    __syncthreads();
    s = 0.f; q = 0.f;
    #pragma unroll
    for (int i = 0; i < 8; i++) { s += rs[i]; q += rq[i]; }

    const float mean = s * (1.f / 1024.f);
    const float var  = q * (1.f / 1024.f) - mean * mean;
    const float rstd = rsqrtf(var + 1e-5f);

    const int c = tid * 4;
    float4 gv = *(const float4*)&g[c];
    float4 bv = *(const float4*)&bta[c];
    float4 o;
    o.x = (a.x - mean) * rstd * gv.x + bv.x;
    o.y = (a.y - mean) * rstd * gv.y + bv.y;
    o.z = (a.z - mean) * rstd * gv.z + bv.z;
    o.w = (a.w - mean) * rstd * gv.w + bv.w;
    *(float4*)&y[base] = o;
}

// ---------------------------------------------------------------------------
// Launch orchestration
// ---------------------------------------------------------------------------
extern "C" void kernel_launch(void* const* d_in, const int* in_sizes, int n_in,
                              void* d_out, int out_size)
{
    const float* T    = (const float*)d_in[0];
    const float* A    = (const float*)d_in[1];
    const float* mask = (const float*)d_in[2];
    const int*   pad  = (const int*)  d_in[3];
    const float* Wq   = (const float*)d_in[4];
    const float* bq   = (const float*)d_in[5];
    const float* Wk   = (const float*)d_in[6];
    const float* bk   = (const float*)d_in[7];
    const float* Wv   = (const float*)d_in[8];
    const float* bv   = (const float*)d_in[9];
    const float* Wo   = (const float*)d_in[10];
    const float* ffW1 = (const float*)d_in[11];
    const float* ffb1 = (const float*)d_in[12];
    const float* ffW2 = (const float*)d_in[13];
    const float* ffb2 = (const float*)d_in[14];
    const float* lng  = (const float*)d_in[15];
    const float* lnb  = (const float*)d_in[16];
    float* out = (float*)d_out;

    float *Qb, *Kb, *Vb, *Ob, *Mo, *T1, *A1, *T2, *A2, *Hb;
    cudaGetSymbolAddress((void**)&Qb, g_Q);
    cudaGetSymbolAddress((void**)&Kb, g_K);
    cudaGetSymbolAddress((void**)&Vb, g_V);
    cudaGetSymbolAddress((void**)&Ob, g_O);
    cudaGetSymbolAddress((void**)&Mo, g_M);
    cudaGetSymbolAddress((void**)&T1, g_T1);
    cudaGetSymbolAddress((void**)&A1, g_A1);
    cudaGetSymbolAddress((void**)&T2, g_T2);
    cudaGetSymbolAddress((void**)&A2, g_A2);
    cudaGetSymbolAddress((void**)&Hb, g_FH);

    __nv_bfloat16 *wqh,*wql,*wkh,*wkl,*wvh,*wvl,*woh,*wol;
    __nv_bfloat16 *w1h,*w1l,*w2h,*w2l,*xh1,*xl1,*xh2,*xl2;
    cudaGetSymbolAddress((void**)&wqh, g_wqh);
    cudaGetSymbolAddress((void**)&wql, g_wql);
    cudaGetSymbolAddress((void**)&wkh, g_wkh);
    cudaGetSymbolAddress((void**)&wkl, g_wkl);
    cudaGetSymbolAddress((void**)&wvh, g_wvh);
    cudaGetSymbolAddress((void**)&wvl, g_wvl);
    cudaGetSymbolAddress((void**)&woh, g_woh);
    cudaGetSymbolAddress((void**)&wol, g_wol);
    cudaGetSymbolAddress((void**)&w1h, g_w1h);
    cudaGetSymbolAddress((void**)&w1l, g_w1l);
    cudaGetSymbolAddress((void**)&w2h, g_w2h);
    cudaGetSymbolAddress((void**)&w2l, g_w2l);
    cudaGetSymbolAddress((void**)&xh1, g_xh1);
    cudaGetSymbolAddress((void**)&xl1, g_xl1);
    cudaGetSymbolAddress((void**)&xh2, g_xh2);
    cudaGetSymbolAddress((void**)&xl2, g_xl2);

    cudaFuncSetAttribute(gemm_mma,  cudaFuncAttributeMaxDynamicSharedMemorySize, GEMM_SMEM);
    cudaFuncSetAttribute(flash_attn, cudaFuncAttributeMaxDynamicSharedMemorySize, FATT_SMEM);

    // weight transpose + bf16 split
    transpose_split<<<dim3(Dc/32, Dc/32, 4), 256>>>(Wq,   wqh, wql, Dc, Dc);
    transpose_split<<<dim3(Dc/32, Dc/32, 4), 256>>>(Wk,   wkh, wkl, Dc, Dc);
    transpose_split<<<dim3(Dc/32, Dc/32, 4), 256>>>(Wv,   wvh, wvl, Dc, Dc);
    transpose_split<<<dim3(Dc/32, Dc/32, 4), 256>>>(Wo,   woh, wol, Dc, Dc);
    transpose_split<<<dim3(Fc/32, Dc/32, 2), 256>>>(ffW1, w1h, w1l, Dc, Fc);
    transpose_split<<<dim3(Dc/32, Fc/32, 2), 256>>>(ffW2, w2h, w2l, Fc, Dc);

    auto gemm = [&](const __nv_bfloat16* ah, const __nv_bfloat16* al,
                    const __nv_bfloat16* bh, const __nv_bfloat16* bl,
                    const float* bias, float* c, int M, int N, int K, int relu) {
        gemm_mma<<<dim3(N/128, M/128), 256, GEMM_SMEM>>>(ah, al, bh, bl, bias, c, M, N, K, relu);
    };
    auto split = [&](const float* x, __nv_bfloat16* h, __nv_bfloat16* l, size_t n) {
        split_f32<<<(int)(n / 1024), 256>>>(x, h, l);
    };

    auto mha = [&](int i, const float* xq, const float* xk, float* ob) {
        const size_t wo = (size_t)i * Dc * Dc;
        split(xq, xh1, xl1, (size_t)BLc * Dc);
        gemm(xh1, xl1, wqh + wo, wql + wo, bq + i * Dc, Qb, BLc, Dc, Dc, 0);
        split(xk, xh2, xl2, (size_t)BLc * Dc);
        gemm(xh2, xl2, wkh + wo, wkl + wo, bk + i * Dc, Kb, BLc, Dc, Dc, 0);
        gemm(xh2, xl2, wvh + wo, wvl + wo, bv + i * Dc, Vb, BLc, Dc, Dc, 0);
        flash_attn<<<dim3(Lc/128, Bc*Hc), 256, FATT_SMEM>>>(Qb, Kb, Vb, mask, pad, Ob);
        split(Ob, xh1, xl1, (size_t)BLc * Dc);
        gemm(xh1, xl1, woh + wo, wol + wo, nullptr, ob, BLc, Dc, Dc, 0);
    };

    // Self-attention per modality
    mha(0, T, T, Mo);
    add_ln<<<BLc, 256>>>(T, Mo, lng + 0 * Dc, lnb + 0 * Dc, T1);
    mha(1, A, A, Mo);
    add_ln<<<BLc, 256>>>(A, Mo, lng + 1 * Dc, lnb + 1 * Dc, A1);
    // Cross-attention
    mha(2, T1, A1, Mo);
    add_ln<<<BLc, 256>>>(T1, Mo, lng + 2 * Dc, lnb + 2 * Dc, T2);
    mha(3, A1, T2, Mo);
    add_ln<<<BLc, 256>>>(A1, Mo, lng + 3 * Dc, lnb + 3 * Dc, A2);

    // FFNs -> d_out (T_out then A_out)
    split(T2, xh1, xl1, (size_t)BLc * Dc);
    gemm(xh1, xl1, w1h, w1l, ffb1, Hb, BLc, Fc, Dc, 1);
    split(Hb, xh1, xl1, (size_t)BLc * Fc);
    gemm(xh1, xl1, w2h, w2l, ffb2, out, BLc, Dc, Fc, 0);

    split(A2, xh1, xl1, (size_t)BLc * Dc);
    gemm(xh1, xl1, w1h + (size_t)Dc * Fc, w1l + (size_t)Dc * Fc, ffb1 + Fc, Hb, BLc, Fc, Dc, 1);
    split(Hb, xh1, xl1, (size_t)BLc * Fc);
    gemm(xh1, xl1, w2h + (size_t)Fc * Dc, w2l + (size_t)Fc * Dc, ffb2 + Dc,
         out + (size_t)BLc * Dc, BLc, Dc, Fc, 0);
}

// round 5
// speedup vs baseline: 2.9860x; 1.0840x over previous
#include <cuda_runtime.h>
#include <cuda_bf16.h>
#include <math.h>
#include <stdint.h>

// Problem constants
constexpr int Bc  = 4;
constexpr int Lc  = 1024;
constexpr int Dc  = 1024;
constexpr int Fc  = 4096;
constexpr int Hc  = 16;
constexpr int HDc = 64;
constexpr int BLc = Bc * Lc;          // 4096 rows

// ---------------------------------------------------------------------------
// Scratch (static __device__ arrays — allocation-free per harness rules)
// ---------------------------------------------------------------------------
__device__ float g_M [BLc * Dc];                    // MHA output (post-Wo, fp32)
__device__ float g_T1[BLc * Dc];
__device__ float g_A1[BLc * Dc];

// split-bf16 activations
__device__ __nv_bfloat16 g_iTh[BLc*Dc], g_iTl[BLc*Dc];   // split(T)
__device__ __nv_bfloat16 g_iAh[BLc*Dc], g_iAl[BLc*Dc];   // split(A)
__device__ __nv_bfloat16 g_T1h[BLc*Dc], g_T1l[BLc*Dc];
__device__ __nv_bfloat16 g_A1h[BLc*Dc], g_A1l[BLc*Dc];
__device__ __nv_bfloat16 g_T2h[BLc*Dc], g_T2l[BLc*Dc];
__device__ __nv_bfloat16 g_A2h[BLc*Dc], g_A2l[BLc*Dc];
__device__ __nv_bfloat16 g_Qh [BLc*Dc], g_Ql [BLc*Dc];
__device__ __nv_bfloat16 g_Kh [BLc*Dc], g_Kl [BLc*Dc];
__device__ __nv_bfloat16 g_Vh [BLc*Dc], g_Vl [BLc*Dc];
__device__ __nv_bfloat16 g_Oh [BLc*Dc], g_Ol [BLc*Dc];
__device__ __nv_bfloat16 g_Hh [(size_t)BLc*Fc], g_Hl [(size_t)BLc*Fc];

// bf16 split weights (transposed to [N,K])
__device__ __nv_bfloat16 g_wqh[4*Dc*Dc], g_wql[4*Dc*Dc];
__device__ __nv_bfloat16 g_wkh[4*Dc*Dc], g_wkl[4*Dc*Dc];
__device__ __nv_bfloat16 g_wvh[4*Dc*Dc], g_wvl[4*Dc*Dc];
__device__ __nv_bfloat16 g_woh[4*Dc*Dc], g_wol[4*Dc*Dc];
__device__ __nv_bfloat16 g_w1h[2*Dc*Fc], g_w1l[2*Dc*Fc];   // ff1^T : [F, D]
__device__ __nv_bfloat16 g_w2h[2*Fc*Dc], g_w2l[2*Fc*Dc];   // ff2^T : [D, F]

// ---------------------------------------------------------------------------
// PTX helpers (sm_103 baseline-safe)
// ---------------------------------------------------------------------------
__device__ __forceinline__ uint32_t smem_u32(const void* p) {
    uint32_t a;
    asm("{ .reg .u64 t; cvta.to.shared.u64 t, %1; cvt.u32.u64 %0, t; }" : "=r"(a) : "l"(p));
    return a;
}
__device__ __forceinline__ void cpasync16(uint32_t dst, const void* src) {
    asm volatile("cp.async.cg.shared.global [%0], [%1], 16;" :: "r"(dst), "l"(src));
}
#define CP_COMMIT()  asm volatile("cp.async.commit_group;" ::: "memory")
#define CP_WAIT(n)   asm volatile("cp.async.wait_group %0;" :: "n"(n) : "memory")

#define LDSM4(r, a) \
    asm volatile("ldmatrix.sync.aligned.m8n8.x4.shared.b16 {%0,%1,%2,%3}, [%4];" \
        : "=r"((r)[0]), "=r"((r)[1]), "=r"((r)[2]), "=r"((r)[3]) : "r"(a))
#define LDSM4T(r, a) \
    asm volatile("ldmatrix.sync.aligned.m8n8.x4.trans.shared.b16 {%0,%1,%2,%3}, [%4];" \
        : "=r"((r)[0]), "=r"((r)[1]), "=r"((r)[2]), "=r"((r)[3]) : "r"(a))

__device__ __forceinline__ void mma16816(float* c, const uint32_t* a, const uint32_t* b) {
    asm volatile(
        "mma.sync.aligned.m16n8k16.row.col.f32.bf16.bf16.f32 "
        "{%0,%1,%2,%3}, {%4,%5,%6,%7}, {%8,%9}, {%0,%1,%2,%3};"
        : "+f"(c[0]), "+f"(c[1]), "+f"(c[2]), "+f"(c[3])
        : "r"(a[0]), "r"(a[1]), "r"(a[2]), "r"(a[3]), "r"(b[0]), "r"(b[1]));
}

__device__ __forceinline__ void split1(float v, __nv_bfloat16& h, __nv_bfloat16& l) {
    h = __float2bfloat16(v);
    l = __float2bfloat16(v - __bfloat162float(h));
}
__device__ __forceinline__ uint32_t packbf(float a, float b) {
    __nv_bfloat162 t; t.x = __float2bfloat16(a); t.y = __float2bfloat16(b);
    return *(uint32_t*)&t;
}

// ---------------------------------------------------------------------------
// Tensor-core GEMM with dual output modes:
//   C  != null -> fp32 output
//   Ch != null -> split-bf16 output (Ch/Cl)
// ---------------------------------------------------------------------------
constexpr int GSTR    = 40;
constexpr int TILE_B  = 128 * GSTR * 2;
constexpr int STAGE_B = 4 * TILE_B;
constexpr int GEMM_SMEM = 2 * STAGE_B;

__global__ __launch_bounds__(256, 2) void gemm_mma(
    const __nv_bfloat16* __restrict__ Ah, const __nv_bfloat16* __restrict__ Al,
    const __nv_bfloat16* __restrict__ Bh, const __nv_bfloat16* __restrict__ Bl,
    const float* __restrict__ bias, float* __restrict__ C,
    __nv_bfloat16* __restrict__ Ch, __nv_bfloat16* __restrict__ Cl,
    int M, int N, int K, int relu)
{
    extern __shared__ char sm[];
    const uint32_t sb = smem_u32(sm);
    const int tid  = threadIdx.x;
    const int wid  = tid >> 5;
    const int lane = tid & 31;
    const int brow = blockIdx.y * 128;
    const int bcol = blockIdx.x * 128;
    const int wm   = (wid & 1) * 64;
    const int wn   = (wid >> 1) * 32;

    float acc[4][4][4];
    #pragma unroll
    for (int i = 0; i < 4; i++)
        #pragma unroll
        for (int j = 0; j < 4; j++)
            #pragma unroll
            for (int k = 0; k < 4; k++) acc[i][j][k] = 0.f;

    const int r0 = tid >> 2,            q0 = tid & 3;
    const int r1 = (tid + 256) >> 2,    q1 = (tid + 256) & 3;
    const int nch = K >> 5;

    auto issue = [&](int c, int s) {
        const int kc = c << 5;
        const uint32_t st = sb + s * STAGE_B;
        {
            const uint32_t so = (uint32_t)(r0 * 80 + q0 * 16);
            const size_t ga = (size_t)(brow + r0) * K + kc + q0 * 8;
            const size_t gb = (size_t)(bcol + r0) * K + kc + q0 * 8;
            cpasync16(st + so,              Ah + ga);
            cpasync16(st + TILE_B + so,     Al + ga);
            cpasync16(st + 2*TILE_B + so,   Bh + gb);
            cpasync16(st + 3*TILE_B + so,   Bl + gb);
        }
        {
            const uint32_t so = (uint32_t)(r1 * 80 + q1 * 16);
            const size_t ga = (size_t)(brow + r1) * K + kc + q1 * 8;
            const size_t gb = (size_t)(bcol + r1) * K + kc + q1 * 8;
            cpasync16(st + so,              Ah + ga);
            cpasync16(st + TILE_B + so,     Al + ga);
            cpasync16(st + 2*TILE_B + so,   Bh + gb);
            cpasync16(st + 3*TILE_B + so,   Bl + gb);
        }
        CP_COMMIT();
    };

    issue(0, 0);

    const int a_row = (lane & 15);
    const int a_kof = ((lane >> 4) << 3);
    const int g8    = lane >> 3;
    const int b_nt  = (g8 >> 1) << 3;
    const int b_kof = (g8 & 1) << 3;
    const int b_row = (lane & 7);

    for (int c = 0; c < nch; c++) {
        if (c + 1 < nch) { issue(c + 1, (c + 1) & 1); CP_WAIT(1); }
        else             { CP_WAIT(0); }
        __syncthreads();

        const uint32_t st = sb + (c & 1) * STAGE_B;
        #pragma unroll
        for (int k16 = 0; k16 < 32; k16 += 16) {
            uint32_t aH[4][4], bH[4][2], t[4];
            #pragma unroll
            for (int mt = 0; mt < 4; mt++) {
                uint32_t ad = st + (uint32_t)((wm + mt*16 + a_row) * 80
                                              + (k16 + a_kof) * 2);
                LDSM4(aH[mt], ad);
            }
            #pragma unroll
            for (int p = 0; p < 2; p++) {
                uint32_t ad = st + 2*TILE_B
                    + (uint32_t)((wn + p*16 + b_nt + b_row) * 80
                                 + (k16 + b_kof) * 2);
                LDSM4(t, ad);
                bH[2*p    ][0] = t[0]; bH[2*p    ][1] = t[1];
                bH[2*p + 1][0] = t[2]; bH[2*p + 1][1] = t[3];
            }
            #pragma unroll
            for (int mt = 0; mt < 4; mt++)
                #pragma unroll
                for (int nt = 0; nt < 4; nt++)
                    mma16816(acc[mt][nt], aH[mt], bH[nt]);
            #pragma unroll
            for (int p = 0; p < 2; p++) {
                uint32_t ad = st + 3*TILE_B
                    + (uint32_t)((wn + p*16 + b_nt + b_row) * 80
                                 + (k16 + b_kof) * 2);
                LDSM4(t, ad);
                uint32_t bl0[2] = { t[0], t[1] }, bl1[2] = { t[2], t[3] };
                #pragma unroll
                for (int mt = 0; mt < 4; mt++) {
                    mma16816(acc[mt][2*p    ], aH[mt], bl0);
                    mma16816(acc[mt][2*p + 1], aH[mt], bl1);
                }
            }
            #pragma unroll
            for (int mt = 0; mt < 4; mt++) {
                uint32_t ad = st + TILE_B
                    + (uint32_t)((wm + mt*16 + a_row) * 80
                                 + (k16 + a_kof) * 2);
                LDSM4(t, ad);
                #pragma unroll
                for (int nt = 0; nt < 4; nt++)
                    mma16816(acc[mt][nt], t, bH[nt]);
            }
        }
        __syncthreads();
    }

    const int g  = lane >> 2;
    const int tg = lane & 3;
    #pragma unroll
    for (int mt = 0; mt < 4; mt++) {
        #pragma unroll
        for (int nt = 0; nt < 4; nt++) {
            const int row = brow + wm + mt*16 + g;
            const int col = bcol + wn + nt*8 + tg*2;
            float2 v0, v1;
            v0.x = acc[mt][nt][0]; v0.y = acc[mt][nt][1];
            v1.x = acc[mt][nt][2]; v1.y = acc[mt][nt][3];
            if (bias) {
                float2 bb = *(const float2*)&bias[col];
                v0.x += bb.x; v0.y += bb.y; v1.x += bb.x; v1.y += bb.y;
            }
            if (relu) {
                v0.x = fmaxf(v0.x, 0.f); v0.y = fmaxf(v0.y, 0.f);
                v1.x = fmaxf(v1.x, 0.f); v1.y = fmaxf(v1.y, 0.f);
            }
            if (C) {
                *(float2*)&C[(size_t)row * N + col]       = v0;
                *(float2*)&C[(size_t)(row + 8) * N + col] = v1;
            }
            if (Ch) {
                __nv_bfloat162 hh, ll;
                split1(v0.x, hh.x, ll.x); split1(v0.y, hh.y, ll.y);
                *(__nv_bfloat162*)&Ch[(size_t)row * N + col] = hh;
                *(__nv_bfloat162*)&Cl[(size_t)row * N + col] = ll;
                split1(v1.x, hh.x, ll.x); split1(v1.y, hh.y, ll.y);
                *(__nv_bfloat162*)&Ch[(size_t)(row + 8) * N + col] = hh;
                *(__nv_bfloat162*)&Cl[(size_t)(row + 8) * N + col] = ll;
            }
        }
    }
}

// ---------------------------------------------------------------------------
// Fused flash attention on pre-split bf16 Q/K/V; cp.async double-buffered K/V.
// Block: 128 q-rows of one (b,h). Output: split-bf16 O.
// ---------------------------------------------------------------------------
constexpr int FA_STR   = 72;                      // bf16 row stride
constexpr int FA_TB    = 128 * FA_STR * 2;        // 18432 B per tile
constexpr int FA_STAGE = 4 * FA_TB;               // Kh,Kl,Vh,Vl = 73728 B
constexpr int FA_SMEM  = 2*FA_TB + 2*FA_STAGE + 4096;   // Q + 2 stages + pad

__global__ __launch_bounds__(256, 1) void flash_attn(
    const __nv_bfloat16* __restrict__ Qh, const __nv_bfloat16* __restrict__ Ql,
    const __nv_bfloat16* __restrict__ Kh, const __nv_bfloat16* __restrict__ Kl,
    const __nv_bfloat16* __restrict__ Vh, const __nv_bfloat16* __restrict__ Vl,
    const float* __restrict__ mask, const int* __restrict__ pad,
    __nv_bfloat16* __restrict__ Oh, __nv_bfloat16* __restrict__ Ol)
{
    extern __shared__ char sm[];
    const uint32_t sb = smem_u32(sm);
    const int tid  = threadIdx.x;
    const int wid  = tid >> 5;
    const int lane = tid & 31;
    const int qy   = blockIdx.x * 128;
    const int bh   = blockIdx.y;
    const int b    = bh >> 4;
    const int hcol = (bh & 15) * HDc;
    const int wq   = wid * 16;

    const uint32_t sQh = sb;
    const uint32_t sQl = sb + FA_TB;
    float* spad = (float*)(sm + 2*FA_TB + 2*FA_STAGE);

    // pad row -> smem (once per block)
    for (int i = tid; i < 1024; i += 256)
        spad[i] = (float)pad[b*Lc + i];

    // Q tile cp.async (group 0)
    for (int i = tid; i < 1024; i += 256) {
        const int r = i >> 3, j = i & 7;
        const uint32_t so = (uint32_t)(r * 144 + j * 16);
        const size_t gq = (size_t)(b*Lc + qy + r) * Dc + hcol + j*8;
        cpasync16(sQh + so, Qh + gq);
        cpasync16(sQl + so, Ql + gq);
    }
    CP_COMMIT();

    auto issueKV = [&](int t, int s) {
        const int kx = t * 128;
        const uint32_t base = sb + 2*FA_TB + s * FA_STAGE;
        for (int i = tid; i < 1024; i += 256) {
            const int r = i >> 3, j = i & 7;
            const uint32_t so = (uint32_t)(r * 144 + j * 16);
            const size_t gk = (size_t)(b*Lc + kx + r) * Dc + hcol + j*8;
            cpasync16(base + so,             Kh + gk);
            cpasync16(base + FA_TB + so,     Kl + gk);
            cpasync16(base + 2*FA_TB + so,   Vh + gk);
            cpasync16(base + 3*FA_TB + so,   Vl + gk);
        }
        CP_COMMIT();
    };
    issueKV(0, 0);      // group 1

    CP_WAIT(1);          // Q (group 0) complete
    __syncthreads();

    const int a_row = lane & 15;
    const int a_kof = (lane >> 4) << 3;
    uint32_t qh[4][4], ql[4][4];
    #pragma unroll
    for (int kt = 0; kt < 4; kt++) {
        const uint32_t off = (uint32_t)((wq + a_row)*144 + (kt*16 + a_kof)*2);
        LDSM4(qh[kt], sQh + off);
        LDSM4(ql[kt], sQl + off);
    }

    float m[2] = { -1e30f, -1e30f };
    float l[2] = { 0.f, 0.f };
    float o[8][4];
    #pragma unroll
    for (int i = 0; i < 8; i++)
        #pragma unroll
        for (int j = 0; j < 4; j++) o[i][j] = 0.f;

    const int g    = lane >> 2;
    const int tg   = lane & 3;
    const int g8   = lane >> 3;
    const int b_nt  = (g8 >> 1) << 3;
    const int b_kof = (g8 & 1) << 3;
    const int b_row = lane & 7;
    const int v_kv = ((lane >> 3) & 1) << 3;
    const int v_d  = (lane >> 4) << 3;

    for (int t = 0; t < 8; t++) {
        const int kx = t * 128;
        if (t + 1 < 8) { issueKV(t + 1, (t + 1) & 1); CP_WAIT(1); }
        else           { CP_WAIT(0); }
        __syncthreads();

        const uint32_t stK = sb + 2*FA_TB + (t & 1) * FA_STAGE;
        const uint32_t stKl = stK + FA_TB;
        const uint32_t stVh = stK + 2*FA_TB;
        const uint32_t stVl = stK + 3*FA_TB;

        // ---- S = Q K^T (split) ----
        float sf[16][4];
        #pragma unroll
        for (int i = 0; i < 16; i++)
            #pragma unroll
            for (int j = 0; j < 4; j++) sf[i][j] = 0.f;

        #pragma unroll
        for (int kst = 0; kst < 4; kst++) {
            uint32_t kb[8][4];
            #pragma unroll
            for (int p = 0; p < 8; p++) {
                const uint32_t ad = stK + (uint32_t)((p*16 + b_nt + b_row)*144
                                                     + (kst*16 + b_kof)*2);
                LDSM4(kb[p], ad);
            }
            #pragma unroll
            for (int p = 0; p < 8; p++) {
                uint32_t b0[2] = { kb[p][0], kb[p][1] };
                uint32_t b1[2] = { kb[p][2], kb[p][3] };
                mma16816(sf[2*p],   qh[kst], b0);
                mma16816(sf[2*p+1], qh[kst], b1);
                mma16816(sf[2*p],   ql[kst], b0);
                mma16816(sf[2*p+1], ql[kst], b1);
            }
            #pragma unroll
            for (int p = 0; p < 8; p++) {
                const uint32_t ad = stKl + (uint32_t)((p*16 + b_nt + b_row)*144
                                                      + (kst*16 + b_kof)*2);
                LDSM4(kb[p], ad);
            }
            #pragma unroll
            for (int p = 0; p < 8; p++) {
                uint32_t b0[2] = { kb[p][0], kb[p][1] };
                uint32_t b1[2] = { kb[p][2], kb[p][3] };
                mma16816(sf[2*p],   qh[kst], b0);
                mma16816(sf[2*p+1], qh[kst], b1);
            }
        }

        // ---- scale + mask + pad ----
        const int qg0 = qy + wq + g;
        #pragma unroll
        for (int nt = 0; nt < 16; nt++) {
            const int kvl = nt*8 + tg*2;
            const int kvg = kx + kvl;
            float2 m0 = *(const float2*)&mask[(size_t)qg0 * Lc + kvg];
            float2 m1 = *(const float2*)&mask[(size_t)(qg0 + 8) * Lc + kvg];
            const float p0 = spad[kx + kvl], p1 = spad[kx + kvl + 1];
            sf[nt][0] = sf[nt][0]*0.125f + m0.x + p0;
            sf[nt][1] = sf[nt][1]*0.125f + m0.y + p1;
            sf[nt][2] = sf[nt][2]*0.125f + m1.x + p0;
            sf[nt][3] = sf[nt][3]*0.125f + m1.y + p1;
        }

        // ---- online softmax ----
        float mx0 = m[0], mx1 = m[1];
        #pragma unroll
        for (int nt = 0; nt < 16; nt++) {
            mx0 = fmaxf(mx0, fmaxf(sf[nt][0], sf[nt][1]));
            mx1 = fmaxf(mx1, fmaxf(sf[nt][2], sf[nt][3]));
        }
        mx0 = fmaxf(mx0, __shfl_xor_sync(0xffffffffu, mx0, 1));
        mx0 = fmaxf(mx0, __shfl_xor_sync(0xffffffffu, mx0, 2));
        mx1 = fmaxf(mx1, __shfl_xor_sync(0xffffffffu, mx1, 1));
        mx1 = fmaxf(mx1, __shfl_xor_sync(0xffffffffu, mx1, 2));

        const float al0 = __expf(m[0] - mx0);
        const float al1 = __expf(m[1] - mx1);
        m[0] = mx0; m[1] = mx1;
        #pragma unroll
        for (int nt = 0; nt < 8; nt++) {
            o[nt][0] *= al0; o[nt][1] *= al0;
            o[nt][2] *= al1; o[nt][3] *= al1;
        }

        uint32_t ph[8][4], pl[8][4];
        float s0 = 0.f, s1 = 0.f;
        #pragma unroll
        for (int j = 0; j < 8; j++) {
            float e00 = __expf(sf[2*j][0]   - mx0);
            float e01 = __expf(sf[2*j][1]   - mx0);
            float e10 = __expf(sf[2*j][2]   - mx1);
            float e11 = __expf(sf[2*j][3]   - mx1);
            float e20 = __expf(sf[2*j+1][0] - mx0);
            float e21 = __expf(sf[2*j+1][1] - mx0);
            float e30 = __expf(sf[2*j+1][2] - mx1);
            float e31 = __expf(sf[2*j+1][3] - mx1);
            s0 += e00 + e01 + e20 + e21;
            s1 += e10 + e11 + e30 + e31;
            ph[j][0] = packbf(e00, e01);
            ph[j][1] = packbf(e10, e11);
            ph[j][2] = packbf(e20, e21);
            ph[j][3] = packbf(e30, e31);
            __nv_bfloat162* hp = (__nv_bfloat162*)&ph[j][0];
            pl[j][0] = packbf(e00 - __bfloat162float(hp[0].x),
                              e01 - __bfloat162float(hp[0].y));
            hp = (__nv_bfloat162*)&ph[j][1];
            pl[j][1] = packbf(e10 - __bfloat162float(hp[0].x),
                              e11 - __bfloat162float(hp[0].y));
            hp = (__nv_bfloat162*)&ph[j][2];
            pl[j][2] = packbf(e20 - __bfloat162float(hp[0].x),
                              e21 - __bfloat162float(hp[0].y));
            hp = (__nv_bfloat162*)&ph[j][3];
            pl[j][3] = packbf(e30 - __bfloat162float(hp[0].x),
                              e31 - __bfloat162float(hp[0].y));
        }
        s0 += __shfl_xor_sync(0xffffffffu, s0, 1);
        s0 += __shfl_xor_sync(0xffffffffu, s0, 2);
        s1 += __shfl_xor_sync(0xffffffffu, s1, 1);
        s1 += __shfl_xor_sync(0xffffffffu, s1, 2);
        l[0] = l[0]*al0 + s0;
        l[1] = l[1]*al1 + s1;

        // ---- O += P V (split) ----
        #pragma unroll
        for (int j = 0; j < 8; j++) {
            #pragma unroll
            for (int p = 0; p < 4; p++) {
                uint32_t th[4], tl[4];
                const uint32_t off = (uint32_t)((j*16 + v_kv + b_row)*144
                                                + (p*16 + v_d)*2);
                LDSM4T(th, stVh + off);
                LDSM4T(tl, stVl + off);
                uint32_t bh0[2] = { th[0], th[1] }, bh1[2] = { th[2], th[3] };
                uint32_t bl0[2] = { tl[0], tl[1] }, bl1[2] = { tl[2], tl[3] };
                mma16816(o[2*p],   ph[j], bh0);
                mma16816(o[2*p+1], ph[j], bh1);
                mma16816(o[2*p],   ph[j], bl0);
                mma16816(o[2*p+1], ph[j], bl1);
                mma16816(o[2*p],   pl[j], bh0);
                mma16816(o[2*p+1], pl[j], bh1);
            }
        }
        __syncthreads();
    }

    // ---- finalize: O /= l, write split bf16 ----
    const float inv0 = 1.f / l[0];
    const float inv1 = 1.f / l[1];
    const int row = b*Lc + qy + wq + g;
    #pragma unroll
    for (int nt = 0; nt < 8; nt++) {
        const int col = hcol + nt*8 + tg*2;
        __nv_bfloat162 hh, ll;
        split1(o[nt][0]*inv0, hh.x, ll.x);
        split1(o[nt][1]*inv0, hh.y, ll.y);
        *(__nv_bfloat162*)&Oh[(size_t)row * Dc + col] = hh;
        *(__nv_bfloat162*)&Ol[(size_t)row * Dc + col] = ll;
        split1(o[nt][2]*inv1, hh.x, ll.x);
        split1(o[nt][3]*inv1, hh.y, ll.y);
        *(__nv_bfloat162*)&Oh[(size_t)(row + 8) * Dc + col] = hh;
        *(__nv_bfloat162*)&Ol[(size_t)(row + 8) * Dc + col] = ll;
    }
}

// ---------------------------------------------------------------------------
// fp32 -> bf16 hi/lo split (inputs T, A only)
// ---------------------------------------------------------------------------
__global__ __launch_bounds__(256) void split_f32(
    const float* __restrict__ x, __nv_bfloat16* __restrict__ h,
    __nv_bfloat16* __restrict__ l)
{
    const size_t i = ((size_t)blockIdx.x * 256 + threadIdx.x) * 4;
    float4 v = *(const float4*)(x + i);
    __nv_bfloat162 hh0, hh1, ll0, ll1;
    split1(v.x, hh0.x, ll0.x); split1(v.y, hh0.y, ll0.y);
    split1(v.z, hh1.x, ll1.x); split1(v.w, hh1.y, ll1.y);
    *(__nv_bfloat162*)(h + i)     = hh0;
    *(__nv_bfloat162*)(h + i + 2) = hh1;
    *(__nv_bfloat162*)(l + i)     = ll0;
    *(__nv_bfloat162*)(l + i + 2) = ll1;
}

// ---------------------------------------------------------------------------
// W[K,N] fp32 -> Wt[N,K] bf16 hi/lo, batched over blockIdx.z
// ---------------------------------------------------------------------------
__global__ __launch_bounds__(256) void transpose_split(
    const float* __restrict__ W, __nv_bfloat16* __restrict__ h,
    __nv_bfloat16* __restrict__ l, int K, int N)
{
    __shared__ float t[32][33];
    const size_t base = (size_t)blockIdx.z * K * N;
    const int k0 = blockIdx.y * 32, n0 = blockIdx.x * 32;
    const int tx = threadIdx.x & 31, ty = threadIdx.x >> 5;
    #pragma unroll
    for (int r = 0; r < 32; r += 8)
        t[ty + r][tx] = W[base + (size_t)(k0 + ty + r) * N + n0 + tx];
    __syncthreads();
    #pragma unroll
    for (int r = 0; r < 32; r += 8) {
        const float v = t[tx][ty + r];
        const size_t o = base + (size_t)(n0 + ty + r) * K + k0 + tx;
        __nv_bfloat16 hh, ll;
        split1(v, hh, ll);
        h[o] = hh; l[o] = ll;
    }
}

// ---------------------------------------------------------------------------
// y = LayerNorm(x + res) * g + b  ->  fp32 y AND split-bf16 (yh, yl)
// ---------------------------------------------------------------------------
__global__ __launch_bounds__(256) void add_ln(
    const float* __restrict__ x, const float* __restrict__ res,
    const float* __restrict__ g, const float* __restrict__ bta,
    float* __restrict__ y, __nv_bfloat16* __restrict__ yh,
    __nv_bfloat16* __restrict__ yl)
{
    __shared__ float rs[8], rq[8];
    const int tid = threadIdx.x;
    const size_t base = (size_t)blockIdx.x * 1024 + tid * 4;

    float4 a = *(const float4*)&x[base];
    float4 r = *(const float4*)&res[base];
    a.x += r.x; a.y += r.y; a.z += r.z; a.w += r.w;

    float s = a.x + a.y + a.z + a.w;
    float q = a.x*a.x + a.y*a.y + a.z*a.z + a.w*a.w;
    #pragma unroll
    for (int o = 16; o > 0; o >>= 1) {
        s += __shfl_xor_sync(0xffffffffu, s, o);
        q += __shfl_xor_sync(0xffffffffu, q, o);
    }
    if ((tid & 31) == 0) { rs[tid >> 5] = s; rq[tid >> 5] = q; }
    __syncthreads();
    s = 0.f; q = 0.f;
    #pragma unroll
    for (int i = 0; i < 8; i++) { s += rs[i]; q += rq[i]; }

    const float mean = s * (1.f / 1024.f);
    const float var  = q * (1.f / 1024.f) - mean * mean;
    const float rstd = rsqrtf(var + 1e-5f);

    const int c = tid * 4;
    float4 gv = *(const float4*)&g[c];
    float4 bv = *(const float4*)&bta[c];
    float4 o;
    o.x = (a.x - mean) * rstd * gv.x + bv.x;
    o.y = (a.y - mean) * rstd * gv.y + bv.y;
    o.z = (a.z - mean) * rstd * gv.z + bv.z;
    o.w = (a.w - mean) * rstd * gv.w + bv.w;
    *(float4*)&y[base] = o;

    __nv_bfloat162 hh0, hh1, ll0, ll1;
    split1(o.x, hh0.x, ll0.x); split1(o.y, hh0.y, ll0.y);
    split1(o.z, hh1.x, ll1.x); split1(o.w, hh1.y, ll1.y);
    *(__nv_bfloat162*)&yh[base]     = hh0;
    *(__nv_bfloat162*)&yh[base + 2] = hh1;
    *(__nv_bfloat162*)&yl[base]     = ll0;
    *(__nv_bfloat162*)&yl[base + 2] = ll1;
}

// ---------------------------------------------------------------------------
// Launch orchestration
// ---------------------------------------------------------------------------
extern "C" void kernel_launch(void* const* d_in, const int* in_sizes, int n_in,
                              void* d_out, int out_size)
{
    const float* T    = (const float*)d_in[0];
    const float* A    = (const float*)d_in[1];
    const float* mask = (const float*)d_in[2];
    const int*   pad  = (const int*)  d_in[3];
    const float* Wq   = (const float*)d_in[4];
    const float* bq   = (const float*)d_in[5];
    const float* Wk   = (const float*)d_in[6];
    const float* bk   = (const float*)d_in[7];
    const float* Wv   = (const float*)d_in[8];
    const float* bv   = (const float*)d_in[9];
    const float* Wo   = (const float*)d_in[10];
    const float* ffW1 = (const float*)d_in[11];
    const float* ffb1 = (const float*)d_in[12];
    const float* ffW2 = (const float*)d_in[13];
    const float* ffb2 = (const float*)d_in[14];
    const float* lng  = (const float*)d_in[15];
    const float* lnb  = (const float*)d_in[16];
    float* out = (float*)d_out;

    float *Mo, *T1f, *A1f;
    cudaGetSymbolAddress((void**)&Mo,  g_M);
    cudaGetSymbolAddress((void**)&T1f, g_T1);
    cudaGetSymbolAddress((void**)&A1f, g_A1);

    __nv_bfloat16 *iTh,*iTl,*iAh,*iAl,*T1h,*T1l,*A1h,*A1l,*T2h,*T2l,*A2h,*A2l;
    __nv_bfloat16 *Qh,*Ql,*Kh,*Kl,*Vh,*Vl,*Oh,*Ol,*Hh,*Hl;
    __nv_bfloat16 *wqh,*wql,*wkh,*wkl,*wvh,*wvl,*woh,*wol,*w1h,*w1l,*w2h,*w2l;
    cudaGetSymbolAddress((void**)&iTh, g_iTh); cudaGetSymbolAddress((void**)&iTl, g_iTl);
    cudaGetSymbolAddress((void**)&iAh, g_iAh); cudaGetSymbolAddress((void**)&iAl, g_iAl);
    cudaGetSymbolAddress((void**)&T1h, g_T1h); cudaGetSymbolAddress((void**)&T1l, g_T1l);
    cudaGetSymbolAddress((void**)&A1h, g_A1h); cudaGetSymbolAddress((void**)&A1l, g_A1l);
    cudaGetSymbolAddress((void**)&T2h, g_T2h); cudaGetSymbolAddress((void**)&T2l, g_T2l);
    cudaGetSymbolAddress((void**)&A2h, g_A2h); cudaGetSymbolAddress((void**)&A2l, g_A2l);
    cudaGetSymbolAddress((void**)&Qh,  g_Qh);  cudaGetSymbolAddress((void**)&Ql,  g_Ql);
    cudaGetSymbolAddress((void**)&Kh,  g_Kh);  cudaGetSymbolAddress((void**)&Kl,  g_Kl);
    cudaGetSymbolAddress((void**)&Vh,  g_Vh);  cudaGetSymbolAddress((void**)&Vl,  g_Vl);
    cudaGetSymbolAddress((void**)&Oh,  g_Oh);  cudaGetSymbolAddress((void**)&Ol,  g_Ol);
    cudaGetSymbolAddress((void**)&Hh,  g_Hh);  cudaGetSymbolAddress((void**)&Hl,  g_Hl);
    cudaGetSymbolAddress((void**)&wqh, g_wqh); cudaGetSymbolAddress((void**)&wql, g_wql);
    cudaGetSymbolAddress((void**)&wkh, g_wkh); cudaGetSymbolAddress((void**)&wkl, g_wkl);
    cudaGetSymbolAddress((void**)&wvh, g_wvh); cudaGetSymbolAddress((void**)&wvl, g_wvl);
    cudaGetSymbolAddress((void**)&woh, g_woh); cudaGetSymbolAddress((void**)&wol, g_wol);
    cudaGetSymbolAddress((void**)&w1h, g_w1h); cudaGetSymbolAddress((void**)&w1l, g_w1l);
    cudaGetSymbolAddress((void**)&w2h, g_w2h); cudaGetSymbolAddress((void**)&w2l, g_w2l);

    cudaFuncSetAttribute(gemm_mma,   cudaFuncAttributeMaxDynamicSharedMemorySize, GEMM_SMEM);
    cudaFuncSetAttribute(flash_attn, cudaFuncAttributeMaxDynamicSharedMemorySize, FA_SMEM);

    // weight transpose + bf16 split
    transpose_split<<<dim3(Dc/32, Dc/32, 4), 256>>>(Wq,   wqh, wql, Dc, Dc);
    transpose_split<<<dim3(Dc/32, Dc/32, 4), 256>>>(Wk,   wkh, wkl, Dc, Dc);
    transpose_split<<<dim3(Dc/32, Dc/32, 4), 256>>>(Wv,   wvh, wvl, Dc, Dc);
    transpose_split<<<dim3(Dc/32, Dc/32, 4), 256>>>(Wo,   woh, wol, Dc, Dc);
    transpose_split<<<dim3(Fc/32, Dc/32, 2), 256>>>(ffW1, w1h, w1l, Dc, Fc);
    transpose_split<<<dim3(Dc/32, Fc/32, 2), 256>>>(ffW2, w2h, w2l, Fc, Dc);

    // GEMM -> fp32 output
    auto gemmF = [&](const __nv_bfloat16* ah, const __nv_bfloat16* al,
                     const __nv_bfloat16* bh, const __nv_bfloat16* bl,
                     const float* bias, float* c, int M, int N, int K, int relu) {
        gemm_mma<<<dim3(N/128, M/128), 256, GEMM_SMEM>>>(
            ah, al, bh, bl, bias, c, nullptr, nullptr, M, N, K, relu);
    };
    // GEMM -> split bf16 output
    auto gemmS = [&](const __nv_bfloat16* ah, const __nv_bfloat16* al,
                     const __nv_bfloat16* bh, const __nv_bfloat16* bl,
                     const float* bias, __nv_bfloat16* ch, __nv_bfloat16* cl,
                     int M, int N, int K, int relu) {
        gemm_mma<<<dim3(N/128, M/128), 256, GEMM_SMEM>>>(
            ah, al, bh, bl, bias, nullptr, ch, cl, M, N, K, relu);
    };

    split_f32<<<BLc, 256>>>(T, iTh, iTl);
    split_f32<<<BLc, 256>>>(A, iAh, iAl);

    auto mha = [&](int i, const __nv_bfloat16* xqh, const __nv_bfloat16* xql,
                   const __nv_bfloat16* xkh, const __nv_bfloat16* xkl) {
        const size_t wo = (size_t)i * Dc * Dc;
        gemmS(xqh, xql, wqh + wo, wql + wo, bq + i * Dc, Qh, Ql, BLc, Dc, Dc, 0);
        gemmS(xkh, xkl, wkh + wo, wkl + wo, bk + i * Dc, Kh, Kl, BLc, Dc, Dc, 0);
        gemmS(xkh, xkl, wvh + wo, wvl + wo, bv + i * Dc, Vh, Vl, BLc, Dc, Dc, 0);
        flash_attn<<<dim3(Lc/128, Bc*Hc), 256, FA_SMEM>>>(
            Qh, Ql, Kh, Kl, Vh, Vl, mask, pad, Oh, Ol);
        gemmF(Oh, Ol, woh + wo, wol + wo, nullptr, Mo, BLc, Dc, Dc, 0);
    };

    // Self-attention per modality
    mha(0, iTh, iTl, iTh, iTl);
    add_ln<<<BLc, 256>>>(T, Mo, lng + 0*Dc, lnb + 0*Dc, T1f, T1h, T1l);
    mha(1, iAh, iAl, iAh, iAl);
    add_ln<<<BLc, 256>>>(A, Mo, lng + 1*Dc, lnb + 1*Dc, A1f, A1h, A1l);
    // Cross-attention
    mha(2, T1h, T1l, A1h, A1l);
    add_ln<<<BLc, 256>>>(T1f, Mo, lng + 2*Dc, lnb + 2*Dc, Mo, T2h, T2l);   // careful: Mo reused? No—
    // NOTE: add_ln writes y then mha3 needs T2 split only (xk), residual A1f. Using Mo as
    // y target would race with mha3's Wo output. Use T1f as scratch y for T2 (T1f dead now).
    mha(3, A1h, A1l, T2h, T2l);
    add_ln<<<BLc, 256>>>(A1f, Mo, lng + 3*Dc, lnb + 3*Dc, T1f, A2h, A2l);  // y scratch, only split used

    // FFNs -> d_out (T_out then A_out)
    gemmS(T2h, T2l, w1h, w1l, ffb1, Hh, Hl, BLc, Fc, Dc, 1);
    gemmF(Hh, Hl, w2h, w2l, ffb2, out, BLc, Dc, Fc, 0);
    gemmS(A2h, A2l, w1h + (size_t)Dc*Fc, w1l + (size_t)Dc*Fc, ffb1 + Fc, Hh, Hl, BLc, Fc, Dc, 1);
    gemmF(Hh, Hl, w2h + (size_t)Fc*Dc, w2l + (size_t)Fc*Dc, ffb2 + Dc,
          out + (size_t)BLc*Dc, BLc, Dc, Fc, 0);
}

// round 6
// speedup vs baseline: 3.2804x; 1.0986x over previous
#include <cuda_runtime.h>
#include <cuda_bf16.h>
#include <math.h>
#include <stdint.h>

// Problem constants
constexpr int Bc  = 4;
constexpr int Lc  = 1024;
constexpr int Dc  = 1024;
constexpr int Fc  = 4096;
constexpr int HDc = 64;
constexpr int BLc = Bc * Lc;          // 4096 rows
constexpr int QKVW = 3 * Dc;          // 3072 concat width

// ---------------------------------------------------------------------------
// Scratch (static __device__ arrays — allocation-free per harness rules)
// ---------------------------------------------------------------------------
__device__ float g_Mo0[BLc * Dc];
__device__ float g_Mo1[BLc * Dc];
__device__ float g_T1f[BLc * Dc];
__device__ float g_A1f[BLc * Dc];
__device__ float g_Zf [BLc * Dc];                     // dead fp32 sink

__device__ __nv_bfloat16 g_iTh[BLc*Dc], g_iTl[BLc*Dc];
__device__ __nv_bfloat16 g_iAh[BLc*Dc], g_iAl[BLc*Dc];
__device__ __nv_bfloat16 g_T1h[BLc*Dc], g_T1l[BLc*Dc];
__device__ __nv_bfloat16 g_A1h[BLc*Dc], g_A1l[BLc*Dc];
__device__ __nv_bfloat16 g_T2h[BLc*Dc], g_T2l[BLc*Dc];
__device__ __nv_bfloat16 g_A2h[BLc*Dc], g_A2l[BLc*Dc];
__device__ __nv_bfloat16 g_QKV0h[(size_t)BLc*QKVW], g_QKV0l[(size_t)BLc*QKVW];
__device__ __nv_bfloat16 g_QKV1h[(size_t)BLc*QKVW], g_QKV1l[(size_t)BLc*QKVW];
__device__ __nv_bfloat16 g_O0h[BLc*Dc], g_O0l[BLc*Dc];
__device__ __nv_bfloat16 g_O1h[BLc*Dc], g_O1l[BLc*Dc];
__device__ __nv_bfloat16 g_H0h[(size_t)BLc*Fc], g_H0l[(size_t)BLc*Fc];
__device__ __nv_bfloat16 g_H1h[(size_t)BLc*Fc], g_H1l[(size_t)BLc*Fc];

// weights: concat QKV^T [4][3072,1024]; others [N,K]
__device__ __nv_bfloat16 g_wch[(size_t)4*QKVW*Dc], g_wcl[(size_t)4*QKVW*Dc];
__device__ __nv_bfloat16 g_woh[4*Dc*Dc], g_wol[4*Dc*Dc];
__device__ __nv_bfloat16 g_w1h[2*Dc*Fc], g_w1l[2*Dc*Fc];
__device__ __nv_bfloat16 g_w2h[2*Fc*Dc], g_w2l[2*Fc*Dc];
__device__ float g_bcat[4*QKVW];

// ---------------------------------------------------------------------------
// PTX helpers (sm_103 baseline-safe)
// ---------------------------------------------------------------------------
__device__ __forceinline__ uint32_t smem_u32(const void* p) {
    uint32_t a;
    asm("{ .reg .u64 t; cvta.to.shared.u64 t, %1; cvt.u32.u64 %0, t; }" : "=r"(a) : "l"(p));
    return a;
}
__device__ __forceinline__ void cpasync16(uint32_t dst, const void* src) {
    asm volatile("cp.async.cg.shared.global [%0], [%1], 16;" :: "r"(dst), "l"(src));
}
#define CP_COMMIT()  asm volatile("cp.async.commit_group;" ::: "memory")
#define CP_WAIT(n)   asm volatile("cp.async.wait_group %0;" :: "n"(n) : "memory")

#define LDSM4(r, a) \
    asm volatile("ldmatrix.sync.aligned.m8n8.x4.shared.b16 {%0,%1,%2,%3}, [%4];" \
        : "=r"((r)[0]), "=r"((r)[1]), "=r"((r)[2]), "=r"((r)[3]) : "r"(a))
#define LDSM4T(r, a) \
    asm volatile("ldmatrix.sync.aligned.m8n8.x4.trans.shared.b16 {%0,%1,%2,%3}, [%4];" \
        : "=r"((r)[0]), "=r"((r)[1]), "=r"((r)[2]), "=r"((r)[3]) : "r"(a))

__device__ __forceinline__ void mma16816(float* c, const uint32_t* a, const uint32_t* b) {
    asm volatile(
        "mma.sync.aligned.m16n8k16.row.col.f32.bf16.bf16.f32 "
        "{%0,%1,%2,%3}, {%4,%5,%6,%7}, {%8,%9}, {%0,%1,%2,%3};"
        : "+f"(c[0]), "+f"(c[1]), "+f"(c[2]), "+f"(c[3])
        : "r"(a[0]), "r"(a[1]), "r"(a[2]), "r"(a[3]), "r"(b[0]), "r"(b[1]));
}

__device__ __forceinline__ void split1(float v, __nv_bfloat16& h, __nv_bfloat16& l) {
    h = __float2bfloat16(v);
    l = __float2bfloat16(v - __bfloat162float(h));
}
__device__ __forceinline__ uint32_t packbf(float a, float b) {
    __nv_bfloat162 t; t.x = __float2bfloat16(a); t.y = __float2bfloat16(b);
    return *(uint32_t*)&t;
}

// ---------------------------------------------------------------------------
// Tensor-core GEMM. Output: fp32 (C) or split-bf16 (Ch/Cl); stride ldc, col
// offset coff (for writing sub-ranges of a wider concat buffer).
// ---------------------------------------------------------------------------
constexpr int GSTR    = 40;
constexpr int TILE_B  = 128 * GSTR * 2;
constexpr int STAGE_B = 4 * TILE_B;
constexpr int GEMM_SMEM = 2 * STAGE_B;

__global__ __launch_bounds__(256, 2) void gemm_mma(
    const __nv_bfloat16* __restrict__ Ah, const __nv_bfloat16* __restrict__ Al,
    const __nv_bfloat16* __restrict__ Bh, const __nv_bfloat16* __restrict__ Bl,
    const float* __restrict__ bias, float* __restrict__ C,
    __nv_bfloat16* __restrict__ Ch, __nv_bfloat16* __restrict__ Cl,
    int M, int N, int K, int ldc, int coff, int relu)
{
    extern __shared__ char sm[];
    const uint32_t sb = smem_u32(sm);
    const int tid  = threadIdx.x;
    const int wid  = tid >> 5;
    const int lane = tid & 31;
    const int brow = blockIdx.y * 128;
    const int bcol = blockIdx.x * 128;
    const int wm   = (wid & 1) * 64;
    const int wn   = (wid >> 1) * 32;

    float acc[4][4][4];
    #pragma unroll
    for (int i = 0; i < 4; i++)
        #pragma unroll
        for (int j = 0; j < 4; j++)
            #pragma unroll
            for (int k = 0; k < 4; k++) acc[i][j][k] = 0.f;

    const int r0 = tid >> 2,            q0 = tid & 3;
    const int r1 = (tid + 256) >> 2,    q1 = (tid + 256) & 3;
    const int nch = K >> 5;

    auto issue = [&](int c, int s) {
        const int kc = c << 5;
        const uint32_t st = sb + s * STAGE_B;
        {
            const uint32_t so = (uint32_t)(r0 * 80 + q0 * 16);
            const size_t ga = (size_t)(brow + r0) * K + kc + q0 * 8;
            const size_t gb = (size_t)(bcol + r0) * K + kc + q0 * 8;
            cpasync16(st + so,              Ah + ga);
            cpasync16(st + TILE_B + so,     Al + ga);
            cpasync16(st + 2*TILE_B + so,   Bh + gb);
            cpasync16(st + 3*TILE_B + so,   Bl + gb);
        }
        {
            const uint32_t so = (uint32_t)(r1 * 80 + q1 * 16);
            const size_t ga = (size_t)(brow + r1) * K + kc + q1 * 8;
            const size_t gb = (size_t)(bcol + r1) * K + kc + q1 * 8;
            cpasync16(st + so,              Ah + ga);
            cpasync16(st + TILE_B + so,     Al + ga);
            cpasync16(st + 2*TILE_B + so,   Bh + gb);
            cpasync16(st + 3*TILE_B + so,   Bl + gb);
        }
        CP_COMMIT();
    };

    issue(0, 0);

    const int a_row = (lane & 15);
    const int a_kof = ((lane >> 4) << 3);
    const int g8    = lane >> 3;
    const int b_nt  = (g8 >> 1) << 3;
    const int b_kof = (g8 & 1) << 3;
    const int b_row = (lane & 7);

    for (int c = 0; c < nch; c++) {
        if (c + 1 < nch) { issue(c + 1, (c + 1) & 1); CP_WAIT(1); }
        else             { CP_WAIT(0); }
        __syncthreads();

        const uint32_t st = sb + (c & 1) * STAGE_B;
        #pragma unroll
        for (int k16 = 0; k16 < 32; k16 += 16) {
            uint32_t aH[4][4], bH[4][2], t[4];
            #pragma unroll
            for (int mt = 0; mt < 4; mt++) {
                uint32_t ad = st + (uint32_t)((wm + mt*16 + a_row) * 80
                                              + (k16 + a_kof) * 2);
                LDSM4(aH[mt], ad);
            }
            #pragma unroll
            for (int p = 0; p < 2; p++) {
                uint32_t ad = st + 2*TILE_B
                    + (uint32_t)((wn + p*16 + b_nt + b_row) * 80
                                 + (k16 + b_kof) * 2);
                LDSM4(t, ad);
                bH[2*p    ][0] = t[0]; bH[2*p    ][1] = t[1];
                bH[2*p + 1][0] = t[2]; bH[2*p + 1][1] = t[3];
            }
            #pragma unroll
            for (int mt = 0; mt < 4; mt++)
                #pragma unroll
                for (int nt = 0; nt < 4; nt++)
                    mma16816(acc[mt][nt], aH[mt], bH[nt]);
            #pragma unroll
            for (int p = 0; p < 2; p++) {
                uint32_t ad = st + 3*TILE_B
                    + (uint32_t)((wn + p*16 + b_nt + b_row) * 80
                                 + (k16 + b_kof) * 2);
                LDSM4(t, ad);
                uint32_t bl0[2] = { t[0], t[1] }, bl1[2] = { t[2], t[3] };
                #pragma unroll
                for (int mt = 0; mt < 4; mt++) {
                    mma16816(acc[mt][2*p    ], aH[mt], bl0);
                    mma16816(acc[mt][2*p + 1], aH[mt], bl1);
                }
            }
            #pragma unroll
            for (int mt = 0; mt < 4; mt++) {
                uint32_t ad = st + TILE_B
                    + (uint32_t)((wm + mt*16 + a_row) * 80
                                 + (k16 + a_kof) * 2);
                LDSM4(t, ad);
                #pragma unroll
                for (int nt = 0; nt < 4; nt++)
                    mma16816(acc[mt][nt], t, bH[nt]);
            }
        }
        __syncthreads();
    }

    const int g  = lane >> 2;
    const int tg = lane & 3;
    #pragma unroll
    for (int mt = 0; mt < 4; mt++) {
        #pragma unroll
        for (int nt = 0; nt < 4; nt++) {
            const int row = brow + wm + mt*16 + g;
            const int col = bcol + wn + nt*8 + tg*2;
            float2 v0, v1;
            v0.x = acc[mt][nt][0]; v0.y = acc[mt][nt][1];
            v1.x = acc[mt][nt][2]; v1.y = acc[mt][nt][3];
            if (bias) {
                float2 bb = *(const float2*)&bias[col];
                v0.x += bb.x; v0.y += bb.y; v1.x += bb.x; v1.y += bb.y;
            }
            if (relu) {
                v0.x = fmaxf(v0.x, 0.f); v0.y = fmaxf(v0.y, 0.f);
                v1.x = fmaxf(v1.x, 0.f); v1.y = fmaxf(v1.y, 0.f);
            }
            const size_t o0 = (size_t)row * ldc + coff + col;
            const size_t o1 = (size_t)(row + 8) * ldc + coff + col;
            if (C) {
                *(float2*)&C[o0] = v0;
                *(float2*)&C[o1] = v1;
            }
            if (Ch) {
                __nv_bfloat162 hh, ll;
                split1(v0.x, hh.x, ll.x); split1(v0.y, hh.y, ll.y);
                *(__nv_bfloat162*)&Ch[o0] = hh;
                *(__nv_bfloat162*)&Cl[o0] = ll;
                split1(v1.x, hh.x, ll.x); split1(v1.y, hh.y, ll.y);
                *(__nv_bfloat162*)&Ch[o1] = hh;
                *(__nv_bfloat162*)&Cl[o1] = ll;
            }
        }
    }
}

// ---------------------------------------------------------------------------
// Fused flash attention on concat [BL, 3072] split-bf16 QKV buffer.
// Q at col 0+hcol, K at 1024+hcol, V at 2048+hcol. Output: split-bf16 O.
// ---------------------------------------------------------------------------
constexpr int FA_STR   = 72;
constexpr int FA_TB    = 128 * FA_STR * 2;
constexpr int FA_STAGE = 4 * FA_TB;
constexpr int FA_SMEM  = 2*FA_TB + 2*FA_STAGE + 4096;

__global__ __launch_bounds__(256, 1) void flash_attn(
    const __nv_bfloat16* __restrict__ Xh, const __nv_bfloat16* __restrict__ Xl,
    const float* __restrict__ mask, const int* __restrict__ pad,
    __nv_bfloat16* __restrict__ Oh, __nv_bfloat16* __restrict__ Ol)
{
    extern __shared__ char sm[];
    const uint32_t sb = smem_u32(sm);
    const int tid  = threadIdx.x;
    const int wid  = tid >> 5;
    const int lane = tid & 31;
    const int qy   = blockIdx.x * 128;
    const int bh   = blockIdx.y;
    const int b    = bh >> 4;
    const int hcol = (bh & 15) * HDc;
    const int wq   = wid * 16;

    const uint32_t sQh = sb;
    const uint32_t sQl = sb + FA_TB;
    float* spad = (float*)(sm + 2*FA_TB + 2*FA_STAGE);

    for (int i = tid; i < 1024; i += 256)
        spad[i] = (float)pad[b*Lc + i];

    for (int i = tid; i < 1024; i += 256) {
        const int r = i >> 3, j = i & 7;
        const uint32_t so = (uint32_t)(r * 144 + j * 16);
        const size_t gq = (size_t)(b*Lc + qy + r) * QKVW + hcol + j*8;
        cpasync16(sQh + so, Xh + gq);
        cpasync16(sQl + so, Xl + gq);
    }
    CP_COMMIT();

    auto issueKV = [&](int t, int s) {
        const int kx = t * 128;
        const uint32_t base = sb + 2*FA_TB + s * FA_STAGE;
        for (int i = tid; i < 1024; i += 256) {
            const int r = i >> 3, j = i & 7;
            const uint32_t so = (uint32_t)(r * 144 + j * 16);
            const size_t gk = (size_t)(b*Lc + kx + r) * QKVW + 1024 + hcol + j*8;
            const size_t gv = gk + 1024;
            cpasync16(base + so,             Xh + gk);
            cpasync16(base + FA_TB + so,     Xl + gk);
            cpasync16(base + 2*FA_TB + so,   Xh + gv);
            cpasync16(base + 3*FA_TB + so,   Xl + gv);
        }
        CP_COMMIT();
    };
    issueKV(0, 0);

    CP_WAIT(1);
    __syncthreads();

    const int a_row = lane & 15;
    const int a_kof = (lane >> 4) << 3;
    uint32_t qh[4][4], ql[4][4];
    #pragma unroll
    for (int kt = 0; kt < 4; kt++) {
        const uint32_t off = (uint32_t)((wq + a_row)*144 + (kt*16 + a_kof)*2);
        LDSM4(qh[kt], sQh + off);
        LDSM4(ql[kt], sQl + off);
    }

    float m[2] = { -1e30f, -1e30f };
    float l[2] = { 0.f, 0.f };
    float o[8][4];
    #pragma unroll
    for (int i = 0; i < 8; i++)
        #pragma unroll
        for (int j = 0; j < 4; j++) o[i][j] = 0.f;

    const int g    = lane >> 2;
    const int tg   = lane & 3;
    const int g8   = lane >> 3;
    const int b_nt  = (g8 >> 1) << 3;
    const int b_kof = (g8 & 1) << 3;
    const int b_row = lane & 7;
    const int v_kv = ((lane >> 3) & 1) << 3;
    const int v_d  = (lane >> 4) << 3;

    for (int t = 0; t < 8; t++) {
        const int kx = t * 128;
        if (t + 1 < 8) { issueKV(t + 1, (t + 1) & 1); CP_WAIT(1); }
        else           { CP_WAIT(0); }
        __syncthreads();

        const uint32_t stK  = sb + 2*FA_TB + (t & 1) * FA_STAGE;
        const uint32_t stKl = stK + FA_TB;
        const uint32_t stVh = stK + 2*FA_TB;
        const uint32_t stVl = stK + 3*FA_TB;

        float sf[16][4];
        #pragma unroll
        for (int i = 0; i < 16; i++)
            #pragma unroll
            for (int j = 0; j < 4; j++) sf[i][j] = 0.f;

        #pragma unroll
        for (int kst = 0; kst < 4; kst++) {
            uint32_t kb[8][4];
            #pragma unroll
            for (int p = 0; p < 8; p++) {
                const uint32_t ad = stK + (uint32_t)((p*16 + b_nt + b_row)*144
                                                     + (kst*16 + b_kof)*2);
                LDSM4(kb[p], ad);
            }
            #pragma unroll
            for (int p = 0; p < 8; p++) {
                uint32_t b0[2] = { kb[p][0], kb[p][1] };
                uint32_t b1[2] = { kb[p][2], kb[p][3] };
                mma16816(sf[2*p],   qh[kst], b0);
                mma16816(sf[2*p+1], qh[kst], b1);
                mma16816(sf[2*p],   ql[kst], b0);
                mma16816(sf[2*p+1], ql[kst], b1);
            }
            #pragma unroll
            for (int p = 0; p < 8; p++) {
                const uint32_t ad = stKl + (uint32_t)((p*16 + b_nt + b_row)*144
                                                      + (kst*16 + b_kof)*2);
                LDSM4(kb[p], ad);
            }
            #pragma unroll
            for (int p = 0; p < 8; p++) {
                uint32_t b0[2] = { kb[p][0], kb[p][1] };
                uint32_t b1[2] = { kb[p][2], kb[p][3] };
                mma16816(sf[2*p],   qh[kst], b0);
                mma16816(sf[2*p+1], qh[kst], b1);
            }
        }

        const int qg0 = qy + wq + g;
        #pragma unroll
        for (int nt = 0; nt < 16; nt++) {
            const int kvl = nt*8 + tg*2;
            const int kvg = kx + kvl;
            float2 m0 = *(const float2*)&mask[(size_t)qg0 * Lc + kvg];
            float2 m1 = *(const float2*)&mask[(size_t)(qg0 + 8) * Lc + kvg];
            const float p0 = spad[kx + kvl], p1 = spad[kx + kvl + 1];
            sf[nt][0] = sf[nt][0]*0.125f + m0.x + p0;
            sf[nt][1] = sf[nt][1]*0.125f + m0.y + p1;
            sf[nt][2] = sf[nt][2]*0.125f + m1.x + p0;
            sf[nt][3] = sf[nt][3]*0.125f + m1.y + p1;
        }

        float mx0 = m[0], mx1 = m[1];
        #pragma unroll
        for (int nt = 0; nt < 16; nt++) {
            mx0 = fmaxf(mx0, fmaxf(sf[nt][0], sf[nt][1]));
            mx1 = fmaxf(mx1, fmaxf(sf[nt][2], sf[nt][3]));
        }
        mx0 = fmaxf(mx0, __shfl_xor_sync(0xffffffffu, mx0, 1));
        mx0 = fmaxf(mx0, __shfl_xor_sync(0xffffffffu, mx0, 2));
        mx1 = fmaxf(mx1, __shfl_xor_sync(0xffffffffu, mx1, 1));
        mx1 = fmaxf(mx1, __shfl_xor_sync(0xffffffffu, mx1, 2));

        const float al0 = __expf(m[0] - mx0);
        const float al1 = __expf(m[1] - mx1);
        m[0] = mx0; m[1] = mx1;
        #pragma unroll
        for (int nt = 0; nt < 8; nt++) {
            o[nt][0] *= al0; o[nt][1] *= al0;
            o[nt][2] *= al1; o[nt][3] *= al1;
        }

        uint32_t ph[8][4], pl[8][4];
        float s0 = 0.f, s1 = 0.f;
        #pragma unroll
        for (int j = 0; j < 8; j++) {
            float e00 = __expf(sf[2*j][0]   - mx0);
            float e01 = __expf(sf[2*j][1]   - mx0);
            float e10 = __expf(sf[2*j][2]   - mx1);
            float e11 = __expf(sf[2*j][3]   - mx1);
            float e20 = __expf(sf[2*j+1][0] - mx0);
            float e21 = __expf(sf[2*j+1][1] - mx0);
            float e30 = __expf(sf[2*j+1][2] - mx1);
            float e31 = __expf(sf[2*j+1][3] - mx1);
            s0 += e00 + e01 + e20 + e21;
            s1 += e10 + e11 + e30 + e31;
            ph[j][0] = packbf(e00, e01);
            ph[j][1] = packbf(e10, e11);
            ph[j][2] = packbf(e20, e21);
            ph[j][3] = packbf(e30, e31);
            __nv_bfloat162* hp = (__nv_bfloat162*)&ph[j][0];
            pl[j][0] = packbf(e00 - __bfloat162float(hp[0].x),
                              e01 - __bfloat162float(hp[0].y));
            hp = (__nv_bfloat162*)&ph[j][1];
            pl[j][1] = packbf(e10 - __bfloat162float(hp[0].x),
                              e11 - __bfloat162float(hp[0].y));
            hp = (__nv_bfloat162*)&ph[j][2];
            pl[j][2] = packbf(e20 - __bfloat162float(hp[0].x),
                              e21 - __bfloat162float(hp[0].y));
            hp = (__nv_bfloat162*)&ph[j][3];
            pl[j][3] = packbf(e30 - __bfloat162float(hp[0].x),
                              e31 - __bfloat162float(hp[0].y));
        }
        s0 += __shfl_xor_sync(0xffffffffu, s0, 1);
        s0 += __shfl_xor_sync(0xffffffffu, s0, 2);
        s1 += __shfl_xor_sync(0xffffffffu, s1, 1);
        s1 += __shfl_xor_sync(0xffffffffu, s1, 2);
        l[0] = l[0]*al0 + s0;
        l[1] = l[1]*al1 + s1;

        #pragma unroll
        for (int j = 0; j < 8; j++) {
            #pragma unroll
            for (int p = 0; p < 4; p++) {
                uint32_t th[4], tl[4];
                const uint32_t off = (uint32_t)((j*16 + v_kv + b_row)*144
                                                + (p*16 + v_d)*2);
                LDSM4T(th, stVh + off);
                LDSM4T(tl, stVl + off);
                uint32_t bh0[2] = { th[0], th[1] }, bh1[2] = { th[2], th[3] };
                uint32_t bl0[2] = { tl[0], tl[1] }, bl1[2] = { tl[2], tl[3] };
                mma16816(o[2*p],   ph[j], bh0);
                mma16816(o[2*p+1], ph[j], bh1);
                mma16816(o[2*p],   ph[j], bl0);
                mma16816(o[2*p+1], ph[j], bl1);
                mma16816(o[2*p],   pl[j], bh0);
                mma16816(o[2*p+1], pl[j], bh1);
            }
        }
        __syncthreads();
    }

    const float inv0 = 1.f / l[0];
    const float inv1 = 1.f / l[1];
    const int row = b*Lc + qy + wq + g;
    #pragma unroll
    for (int nt = 0; nt < 8; nt++) {
        const int col = hcol + nt*8 + tg*2;
        __nv_bfloat162 hh, ll;
        split1(o[nt][0]*inv0, hh.x, ll.x);
        split1(o[nt][1]*inv0, hh.y, ll.y);
        *(__nv_bfloat162*)&Oh[(size_t)row * Dc + col] = hh;
        *(__nv_bfloat162*)&Ol[(size_t)row * Dc + col] = ll;
        split1(o[nt][2]*inv1, hh.x, ll.x);
        split1(o[nt][3]*inv1, hh.y, ll.y);
        *(__nv_bfloat162*)&Oh[(size_t)(row + 8) * Dc + col] = hh;
        *(__nv_bfloat162*)&Ol[(size_t)(row + 8) * Dc + col] = ll;
    }
}

// ---------------------------------------------------------------------------
// small kernels
// ---------------------------------------------------------------------------
__global__ __launch_bounds__(256) void split_f32(
    const float* __restrict__ x, __nv_bfloat16* __restrict__ h,
    __nv_bfloat16* __restrict__ l)
{
    const size_t i = ((size_t)blockIdx.x * 256 + threadIdx.x) * 4;
    float4 v = *(const float4*)(x + i);
    __nv_bfloat162 hh0, hh1, ll0, ll1;
    split1(v.x, hh0.x, ll0.x); split1(v.y, hh0.y, ll0.y);
    split1(v.z, hh1.x, ll1.x); split1(v.w, hh1.y, ll1.y);
    *(__nv_bfloat162*)(h + i)     = hh0;
    *(__nv_bfloat162*)(h + i + 2) = hh1;
    *(__nv_bfloat162*)(l + i)     = ll0;
    *(__nv_bfloat162*)(l + i + 2) = ll1;
}

// W[z][K,N] fp32 -> out[z*ostrideZ + n*K + k] bf16 hi/lo (transpose to [N,K])
__global__ __launch_bounds__(256) void transpose_split(
    const float* __restrict__ W, __nv_bfloat16* __restrict__ h,
    __nv_bfloat16* __restrict__ l, int K, int N, size_t ostrideZ)
{
    __shared__ float t[32][33];
    const size_t ibase = (size_t)blockIdx.z * K * N;
    const size_t obase = (size_t)blockIdx.z * ostrideZ;
    const int k0 = blockIdx.y * 32, n0 = blockIdx.x * 32;
    const int tx = threadIdx.x & 31, ty = threadIdx.x >> 5;
    #pragma unroll
    for (int r = 0; r < 32; r += 8)
        t[ty + r][tx] = W[ibase + (size_t)(k0 + ty + r) * N + n0 + tx];
    __syncthreads();
    #pragma unroll
    for (int r = 0; r < 32; r += 8) {
        const float v = t[tx][ty + r];
        const size_t o = obase + (size_t)(n0 + ty + r) * K + k0 + tx;
        __nv_bfloat16 hh, ll;
        split1(v, hh, ll);
        h[o] = hh; l[o] = ll;
    }
}

// bcat[i*3072 + seg*1024 + j] = {bq,bk,bv}[i*1024 + j]
__global__ void bias_cat(const float* __restrict__ bq, const float* __restrict__ bk,
                         const float* __restrict__ bv, float* __restrict__ o)
{
    const int i = blockIdx.x, seg = blockIdx.y, j = threadIdx.x;
    const float* src = (seg == 0) ? bq : (seg == 1) ? bk : bv;
    o[i*QKVW + seg*1024 + j] = src[i*1024 + j];
}

__global__ __launch_bounds__(256) void add_ln(
    const float* __restrict__ x, const float* __restrict__ res,
    const float* __restrict__ g, const float* __restrict__ bta,
    float* __restrict__ y, __nv_bfloat16* __restrict__ yh,
    __nv_bfloat16* __restrict__ yl)
{
    __shared__ float rs[8], rq[8];
    const int tid = threadIdx.x;
    const size_t base = (size_t)blockIdx.x * 1024 + tid * 4;

    float4 a = *(const float4*)&x[base];
    float4 r = *(const float4*)&res[base];
    a.x += r.x; a.y += r.y; a.z += r.z; a.w += r.w;

    float s = a.x + a.y + a.z + a.w;
    float q = a.x*a.x + a.y*a.y + a.z*a.z + a.w*a.w;
    #pragma unroll
    for (int o = 16; o > 0; o >>= 1) {
        s += __shfl_xor_sync(0xffffffffu, s, o);
        q += __shfl_xor_sync(0xffffffffu, q, o);
    }
    if ((tid & 31) == 0) { rs[tid >> 5] = s; rq[tid >> 5] = q; }
    __syncthreads();
    s = 0.f; q = 0.f;
    #pragma unroll
    for (int i = 0; i < 8; i++) { s += rs[i]; q += rq[i]; }

    const float mean = s * (1.f / 1024.f);
    const float var  = q * (1.f / 1024.f) - mean * mean;
    const float rstd = rsqrtf(var + 1e-5f);

    const int c = tid * 4;
    float4 gv = *(const float4*)&g[c];
    float4 bv = *(const float4*)&bta[c];
    float4 o;
    o.x = (a.x - mean) * rstd * gv.x + bv.x;
    o.y = (a.y - mean) * rstd * gv.y + bv.y;
    o.z = (a.z - mean) * rstd * gv.z + bv.z;
    o.w = (a.w - mean) * rstd * gv.w + bv.w;
    *(float4*)&y[base] = o;

    __nv_bfloat162 hh0, hh1, ll0, ll1;
    split1(o.x, hh0.x, ll0.x); split1(o.y, hh0.y, ll0.y);
    split1(o.z, hh1.x, ll1.x); split1(o.w, hh1.y, ll1.y);
    *(__nv_bfloat162*)&yh[base]     = hh0;
    *(__nv_bfloat162*)&yh[base + 2] = hh1;
    *(__nv_bfloat162*)&yl[base]     = ll0;
    *(__nv_bfloat162*)&yl[base + 2] = ll1;
}

// ---------------------------------------------------------------------------
// Launch orchestration (two-stream fork/join; capture-legal event pattern)
// ---------------------------------------------------------------------------
extern "C" void kernel_launch(void* const* d_in, const int* in_sizes, int n_in,
                              void* d_out, int out_size)
{
    const float* T    = (const float*)d_in[0];
    const float* A    = (const float*)d_in[1];
    const float* mask = (const float*)d_in[2];
    const int*   pad  = (const int*)  d_in[3];
    const float* Wq   = (const float*)d_in[4];
    const float* bq   = (const float*)d_in[5];
    const float* Wk   = (const float*)d_in[6];
    const float* bk   = (const float*)d_in[7];
    const float* Wv   = (const float*)d_in[8];
    const float* bv   = (const float*)d_in[9];
    const float* Wo   = (const float*)d_in[10];
    const float* ffW1 = (const float*)d_in[11];
    const float* ffb1 = (const float*)d_in[12];
    const float* ffW2 = (const float*)d_in[13];
    const float* ffb2 = (const float*)d_in[14];
    const float* lng  = (const float*)d_in[15];
    const float* lnb  = (const float*)d_in[16];
    float* out = (float*)d_out;

    // streams/events created once (host objects, not device memory)
    static cudaStream_t sA = nullptr, sB = nullptr;
    static cudaEvent_t  eF = nullptr, eA = nullptr, eB = nullptr;
    if (!sA) {
        cudaStreamCreateWithFlags(&sA, cudaStreamNonBlocking);
        cudaStreamCreateWithFlags(&sB, cudaStreamNonBlocking);
        cudaEventCreateWithFlags(&eF, cudaEventDisableTiming);
        cudaEventCreateWithFlags(&eA, cudaEventDisableTiming);
        cudaEventCreateWithFlags(&eB, cudaEventDisableTiming);
    }
    auto fork = [&]() {
        cudaEventRecord(eF, 0);
        cudaStreamWaitEvent(sA, eF, 0);
        cudaStreamWaitEvent(sB, eF, 0);
    };
    auto join = [&]() {
        cudaEventRecord(eA, sA);
        cudaEventRecord(eB, sB);
        cudaStreamWaitEvent(0, eA, 0);
        cudaStreamWaitEvent(0, eB, 0);
    };

    float *Mo0, *Mo1, *T1f, *A1f, *Zf;
    cudaGetSymbolAddress((void**)&Mo0, g_Mo0);
    cudaGetSymbolAddress((void**)&Mo1, g_Mo1);
    cudaGetSymbolAddress((void**)&T1f, g_T1f);
    cudaGetSymbolAddress((void**)&A1f, g_A1f);
    cudaGetSymbolAddress((void**)&Zf,  g_Zf);

    __nv_bfloat16 *iTh,*iTl,*iAh,*iAl,*T1h,*T1l,*A1h,*A1l,*T2h,*T2l,*A2h,*A2l;
    __nv_bfloat16 *QKV0h,*QKV0l,*QKV1h,*QKV1l,*O0h,*O0l,*O1h,*O1l;
    __nv_bfloat16 *H0h,*H0l,*H1h,*H1l;
    __nv_bfloat16 *wch,*wcl,*woh,*wol,*w1h,*w1l,*w2h,*w2l;
    float* bcat;
    cudaGetSymbolAddress((void**)&iTh, g_iTh); cudaGetSymbolAddress((void**)&iTl, g_iTl);
    cudaGetSymbolAddress((void**)&iAh, g_iAh); cudaGetSymbolAddress((void**)&iAl, g_iAl);
    cudaGetSymbolAddress((void**)&T1h, g_T1h); cudaGetSymbolAddress((void**)&T1l, g_T1l);
    cudaGetSymbolAddress((void**)&A1h, g_A1h); cudaGetSymbolAddress((void**)&A1l, g_A1l);
    cudaGetSymbolAddress((void**)&T2h, g_T2h); cudaGetSymbolAddress((void**)&T2l, g_T2l);
    cudaGetSymbolAddress((void**)&A2h, g_A2h); cudaGetSymbolAddress((void**)&A2l, g_A2l);
    cudaGetSymbolAddress((void**)&QKV0h, g_QKV0h); cudaGetSymbolAddress((void**)&QKV0l, g_QKV0l);
    cudaGetSymbolAddress((void**)&QKV1h, g_QKV1h); cudaGetSymbolAddress((void**)&QKV1l, g_QKV1l);
    cudaGetSymbolAddress((void**)&O0h, g_O0h); cudaGetSymbolAddress((void**)&O0l, g_O0l);
    cudaGetSymbolAddress((void**)&O1h, g_O1h); cudaGetSymbolAddress((void**)&O1l, g_O1l);
    cudaGetSymbolAddress((void**)&H0h, g_H0h); cudaGetSymbolAddress((void**)&H0l, g_H0l);
    cudaGetSymbolAddress((void**)&H1h, g_H1h); cudaGetSymbolAddress((void**)&H1l, g_H1l);
    cudaGetSymbolAddress((void**)&wch, g_wch); cudaGetSymbolAddress((void**)&wcl, g_wcl);
    cudaGetSymbolAddress((void**)&woh, g_woh); cudaGetSymbolAddress((void**)&wol, g_wol);
    cudaGetSymbolAddress((void**)&w1h, g_w1h); cudaGetSymbolAddress((void**)&w1l, g_w1l);
    cudaGetSymbolAddress((void**)&w2h, g_w2h); cudaGetSymbolAddress((void**)&w2l, g_w2l);
    cudaGetSymbolAddress((void**)&bcat, g_bcat);

    cudaFuncSetAttribute(gemm_mma,   cudaFuncAttributeMaxDynamicSharedMemorySize, GEMM_SMEM);
    cudaFuncSetAttribute(flash_attn, cudaFuncAttributeMaxDynamicSharedMemorySize, FA_SMEM);

    const size_t DD = (size_t)Dc * Dc;           // 1M
    const size_t WCZ = (size_t)QKVW * Dc;        // 3M per-i concat stride

    auto gemm = [&](cudaStream_t st,
                    const __nv_bfloat16* ah, const __nv_bfloat16* al,
                    const __nv_bfloat16* bh, const __nv_bfloat16* bl,
                    const float* bias, float* c, __nv_bfloat16* ch, __nv_bfloat16* cl,
                    int M, int N, int K, int ldc, int coff, int relu) {
        gemm_mma<<<dim3(N/128, M/128), 256, GEMM_SMEM, st>>>(
            ah, al, bh, bl, bias, c, ch, cl, M, N, K, ldc, coff, relu);
    };

    // ---------------- Phase 0: weight prep + input splits ----------------
    fork();
    transpose_split<<<dim3(32,32,4), 256, 0, sA>>>(Wq, wch,        wcl,        Dc, Dc, WCZ);
    transpose_split<<<dim3(32,32,4), 256, 0, sA>>>(Wk, wch + DD,   wcl + DD,   Dc, Dc, WCZ);
    transpose_split<<<dim3(32,32,4), 256, 0, sA>>>(Wv, wch + 2*DD, wcl + 2*DD, Dc, Dc, WCZ);
    bias_cat<<<dim3(4,3), 1024, 0, sA>>>(bq, bk, bv, bcat);
    split_f32<<<BLc, 256, 0, sA>>>(T, iTh, iTl);
    transpose_split<<<dim3(32,32,4),  256, 0, sB>>>(Wo,   woh, wol, Dc, Dc, DD);
    transpose_split<<<dim3(128,32,2), 256, 0, sB>>>(ffW1, w1h, w1l, Dc, Fc, (size_t)Dc*Fc);
    transpose_split<<<dim3(32,128,2), 256, 0, sB>>>(ffW2, w2h, w2l, Fc, Dc, (size_t)Fc*Dc);
    split_f32<<<BLc, 256, 0, sB>>>(A, iAh, iAl);
    join();

    // ---------------- Phase 1: mha0 (T, sA) || mha1 (A, sB) ----------------
    fork();
    // sA: T self-attention
    gemm(sA, iTh, iTl, wch, wcl, bcat, nullptr, QKV0h, QKV0l,
         BLc, QKVW, Dc, QKVW, 0, 0);
    flash_attn<<<dim3(Lc/128, 64), 256, FA_SMEM, sA>>>(QKV0h, QKV0l, mask, pad, O0h, O0l);
    gemm(sA, O0h, O0l, woh, wol, nullptr, Mo0, nullptr, nullptr,
         BLc, Dc, Dc, Dc, 0, 0);
    add_ln<<<BLc, 256, 0, sA>>>(T, Mo0, lng, lnb, T1f, T1h, T1l);
    // sB: A self-attention
    gemm(sB, iAh, iAl, wch + WCZ, wcl + WCZ, bcat + QKVW, nullptr, QKV1h, QKV1l,
         BLc, QKVW, Dc, QKVW, 0, 0);
    flash_attn<<<dim3(Lc/128, 64), 256, FA_SMEM, sB>>>(QKV1h, QKV1l, mask, pad, O1h, O1l);
    gemm(sB, O1h, O1l, woh + DD, wol + DD, nullptr, Mo1, nullptr, nullptr,
         BLc, Dc, Dc, Dc, 0, 0);
    add_ln<<<BLc, 256, 0, sB>>>(A, Mo1, lng + Dc, lnb + Dc, A1f, A1h, A1l);
    join();

    // ---------------- Phase 2: mha2 (Q from T1, KV from A1) ----------------
    fork();
    gemm(sA, T1h, T1l, wch + 2*WCZ, wcl + 2*WCZ, bcat + 2*QKVW,
         nullptr, QKV0h, QKV0l, BLc, Dc, Dc, QKVW, 0, 0);            // Q cols 0..1023
    gemm(sB, A1h, A1l, wch + 2*WCZ + DD, wcl + 2*WCZ + DD, bcat + 2*QKVW + 1024,
         nullptr, QKV0h, QKV0l, BLc, 2*Dc, Dc, QKVW, 1024, 0);       // KV cols 1024..3071
    join();
    flash_attn<<<dim3(Lc/128, 64), 256, FA_SMEM>>>(QKV0h, QKV0l, mask, pad, O0h, O0l);
    gemm(0, O0h, O0l, woh + 2*DD, wol + 2*DD, nullptr, Mo0, nullptr, nullptr,
         BLc, Dc, Dc, Dc, 0, 0);
    add_ln<<<BLc, 256>>>(T1f, Mo0, lng + 2*Dc, lnb + 2*Dc, Zf, T2h, T2l);

    // ---------------- Phase 3: mha3 (Q from A1, KV from T2) ----------------
    fork();
    gemm(sA, A1h, A1l, wch + 3*WCZ, wcl + 3*WCZ, bcat + 3*QKVW,
         nullptr, QKV0h, QKV0l, BLc, Dc, Dc, QKVW, 0, 0);
    gemm(sB, T2h, T2l, wch + 3*WCZ + DD, wcl + 3*WCZ + DD, bcat + 3*QKVW + 1024,
         nullptr, QKV0h, QKV0l, BLc, 2*Dc, Dc, QKVW, 1024, 0);
    join();
    flash_attn<<<dim3(Lc/128, 64), 256, FA_SMEM>>>(QKV0h, QKV0l, mask, pad, O0h, O0l);
    gemm(0, O0h, O0l, woh + 3*DD, wol + 3*DD, nullptr, Mo0, nullptr, nullptr,
         BLc, Dc, Dc, Dc, 0, 0);
    add_ln<<<BLc, 256>>>(A1f, Mo0, lng + 3*Dc, lnb + 3*Dc, Zf, A2h, A2l);

    // ---------------- Phase 4: FFN-T (sA) || FFN-A (sB) ----------------
    fork();
    gemm(sA, T2h, T2l, w1h, w1l, ffb1, nullptr, H0h, H0l, BLc, Fc, Dc, Fc, 0, 1);
    gemm(sA, H0h, H0l, w2h, w2l, ffb2, out, nullptr, nullptr, BLc, Dc, Fc, Dc, 0, 0);
    gemm(sB, A2h, A2l, w1h + (size_t)Dc*Fc, w1l + (size_t)Dc*Fc, ffb1 + Fc,
         nullptr, H1h, H1l, BLc, Fc, Dc, Fc, 0, 1);
    gemm(sB, H1h, H1l, w2h + (size_t)Fc*Dc, w2l + (size_t)Fc*Dc, ffb2 + Dc,
         out + (size_t)BLc*Dc, nullptr, nullptr, BLc, Dc, Fc, Dc, 0, 0);
    join();
}

// round 7
// speedup vs baseline: 3.3459x; 1.0200x over previous
#include <cuda_runtime.h>
#include <cuda_bf16.h>
#include <math.h>
#include <stdint.h>

// Problem constants
constexpr int Bc  = 4;
constexpr int Lc  = 1024;
constexpr int Dc  = 1024;
constexpr int Fc  = 4096;
constexpr int HDc = 64;
constexpr int BLc = Bc * Lc;          // 4096 rows
constexpr int QKVW = 3 * Dc;          // 3072 concat width

// ---------------------------------------------------------------------------
// Scratch (static __device__ arrays — allocation-free per harness rules)
// ---------------------------------------------------------------------------
__device__ float g_Mo0[BLc * Dc];
__device__ float g_Mo1[BLc * Dc];
__device__ float g_T1f[BLc * Dc];
__device__ float g_A1f[BLc * Dc];

__device__ __nv_bfloat16 g_iTh[BLc*Dc], g_iTl[BLc*Dc];
__device__ __nv_bfloat16 g_iAh[BLc*Dc], g_iAl[BLc*Dc];
__device__ __nv_bfloat16 g_T1h[BLc*Dc], g_T1l[BLc*Dc];
__device__ __nv_bfloat16 g_A1h[BLc*Dc], g_A1l[BLc*Dc];
__device__ __nv_bfloat16 g_T2h[BLc*Dc], g_T2l[BLc*Dc];
__device__ __nv_bfloat16 g_A2h[BLc*Dc], g_A2l[BLc*Dc];
__device__ __nv_bfloat16 g_QKV0h[(size_t)BLc*QKVW], g_QKV0l[(size_t)BLc*QKVW];
__device__ __nv_bfloat16 g_QKV1h[(size_t)BLc*QKVW], g_QKV1l[(size_t)BLc*QKVW];
__device__ __nv_bfloat16 g_O0h[BLc*Dc], g_O0l[BLc*Dc];
__device__ __nv_bfloat16 g_O1h[BLc*Dc], g_O1l[BLc*Dc];
__device__ __nv_bfloat16 g_H0h[(size_t)BLc*Fc], g_H0l[(size_t)BLc*Fc];
__device__ __nv_bfloat16 g_H1h[(size_t)BLc*Fc], g_H1l[(size_t)BLc*Fc];

// weights: concat QKV^T [4][3072,1024]; others [N,K]
__device__ __nv_bfloat16 g_wch[(size_t)4*QKVW*Dc], g_wcl[(size_t)4*QKVW*Dc];
__device__ __nv_bfloat16 g_woh[4*Dc*Dc], g_wol[4*Dc*Dc];
__device__ __nv_bfloat16 g_w1h[2*Dc*Fc], g_w1l[2*Dc*Fc];
__device__ __nv_bfloat16 g_w2h[2*Fc*Dc], g_w2l[2*Fc*Dc];
__device__ float g_bcat[4*QKVW];

// ---------------------------------------------------------------------------
// PTX helpers (sm_103 baseline-safe)
// ---------------------------------------------------------------------------
__device__ __forceinline__ uint32_t smem_u32(const void* p) {
    uint32_t a;
    asm("{ .reg .u64 t; cvta.to.shared.u64 t, %1; cvt.u32.u64 %0, t; }" : "=r"(a) : "l"(p));
    return a;
}
__device__ __forceinline__ void cpasync16(uint32_t dst, const void* src) {
    asm volatile("cp.async.cg.shared.global [%0], [%1], 16;" :: "r"(dst), "l"(src));
}
#define CP_COMMIT()  asm volatile("cp.async.commit_group;" ::: "memory")
#define CP_WAIT(n)   asm volatile("cp.async.wait_group %0;" :: "n"(n) : "memory")

#define LDSM4(r, a) \
    asm volatile("ldmatrix.sync.aligned.m8n8.x4.shared.b16 {%0,%1,%2,%3}, [%4];" \
        : "=r"((r)[0]), "=r"((r)[1]), "=r"((r)[2]), "=r"((r)[3]) : "r"(a))
#define LDSM4T(r, a) \
    asm volatile("ldmatrix.sync.aligned.m8n8.x4.trans.shared.b16 {%0,%1,%2,%3}, [%4];" \
        : "=r"((r)[0]), "=r"((r)[1]), "=r"((r)[2]), "=r"((r)[3]) : "r"(a))

__device__ __forceinline__ void mma16816(float* c, const uint32_t* a, const uint32_t* b) {
    asm volatile(
        "mma.sync.aligned.m16n8k16.row.col.f32.bf16.bf16.f32 "
        "{%0,%1,%2,%3}, {%4,%5,%6,%7}, {%8,%9}, {%0,%1,%2,%3};"
        : "+f"(c[0]), "+f"(c[1]), "+f"(c[2]), "+f"(c[3])
        : "r"(a[0]), "r"(a[1]), "r"(a[2]), "r"(a[3]), "r"(b[0]), "r"(b[1]));
}

__device__ __forceinline__ void split1(float v, __nv_bfloat16& h, __nv_bfloat16& l) {
    h = __float2bfloat16(v);
    l = __float2bfloat16(v - __bfloat162float(h));
}
__device__ __forceinline__ uint32_t packbf(float a, float b) {
    __nv_bfloat162 t; t.x = __float2bfloat16(a); t.y = __float2bfloat16(b);
    return *(uint32_t*)&t;
}
#define FSW(o) ((o) ^ (((o) >> 3) & 0x70))     // SW128 swizzle for 128B rows

// ---------------------------------------------------------------------------
// Tensor-core GEMM (unchanged from round 6 — passing). Output: fp32 (C) or
// split-bf16 (Ch/Cl); stride ldc, col offset coff.
// ---------------------------------------------------------------------------
constexpr int GSTR    = 40;
constexpr int TILE_B  = 128 * GSTR * 2;
constexpr int STAGE_B = 4 * TILE_B;
constexpr int GEMM_SMEM = 2 * STAGE_B;

__global__ __launch_bounds__(256, 2) void gemm_mma(
    const __nv_bfloat16* __restrict__ Ah, const __nv_bfloat16* __restrict__ Al,
    const __nv_bfloat16* __restrict__ Bh, const __nv_bfloat16* __restrict__ Bl,
    const float* __restrict__ bias, float* __restrict__ C,
    __nv_bfloat16* __restrict__ Ch, __nv_bfloat16* __restrict__ Cl,
    int M, int N, int K, int ldc, int coff, int relu)
{
    extern __shared__ char sm[];
    const uint32_t sb = smem_u32(sm);
    const int tid  = threadIdx.x;
    const int wid  = tid >> 5;
    const int lane = tid & 31;
    const int brow = blockIdx.y * 128;
    const int bcol = blockIdx.x * 128;
    const int wm   = (wid & 1) * 64;
    const int wn   = (wid >> 1) * 32;

    float acc[4][4][4];
    #pragma unroll
    for (int i = 0; i < 4; i++)
        #pragma unroll
        for (int j = 0; j < 4; j++)
            #pragma unroll
            for (int k = 0; k < 4; k++) acc[i][j][k] = 0.f;

    const int r0 = tid >> 2,            q0 = tid & 3;
    const int r1 = (tid + 256) >> 2,    q1 = (tid + 256) & 3;
    const int nch = K >> 5;

    auto issue = [&](int c, int s) {
        const int kc = c << 5;
        const uint32_t st = sb + s * STAGE_B;
        {
            const uint32_t so = (uint32_t)(r0 * 80 + q0 * 16);
            const size_t ga = (size_t)(brow + r0) * K + kc + q0 * 8;
            const size_t gb = (size_t)(bcol + r0) * K + kc + q0 * 8;
            cpasync16(st + so,              Ah + ga);
            cpasync16(st + TILE_B + so,     Al + ga);
            cpasync16(st + 2*TILE_B + so,   Bh + gb);
            cpasync16(st + 3*TILE_B + so,   Bl + gb);
        }
        {
            const uint32_t so = (uint32_t)(r1 * 80 + q1 * 16);
            const size_t ga = (size_t)(brow + r1) * K + kc + q1 * 8;
            const size_t gb = (size_t)(bcol + r1) * K + kc + q1 * 8;
            cpasync16(st + so,              Ah + ga);
            cpasync16(st + TILE_B + so,     Al + ga);
            cpasync16(st + 2*TILE_B + so,   Bh + gb);
            cpasync16(st + 3*TILE_B + so,   Bl + gb);
        }
        CP_COMMIT();
    };

    issue(0, 0);

    const int a_row = (lane & 15);
    const int a_kof = ((lane >> 4) << 3);
    const int g8    = lane >> 3;
    const int b_nt  = (g8 >> 1) << 3;
    const int b_kof = (g8 & 1) << 3;
    const int b_row = (lane & 7);

    for (int c = 0; c < nch; c++) {
        if (c + 1 < nch) { issue(c + 1, (c + 1) & 1); CP_WAIT(1); }
        else             { CP_WAIT(0); }
        __syncthreads();

        const uint32_t st = sb + (c & 1) * STAGE_B;
        #pragma unroll
        for (int k16 = 0; k16 < 32; k16 += 16) {
            uint32_t aH[4][4], bH[4][2], t[4];
            #pragma unroll
            for (int mt = 0; mt < 4; mt++) {
                uint32_t ad = st + (uint32_t)((wm + mt*16 + a_row) * 80
                                              + (k16 + a_kof) * 2);
                LDSM4(aH[mt], ad);
            }
            #pragma unroll
            for (int p = 0; p < 2; p++) {
                uint32_t ad = st + 2*TILE_B
                    + (uint32_t)((wn + p*16 + b_nt + b_row) * 80
                                 + (k16 + b_kof) * 2);
                LDSM4(t, ad);
                bH[2*p    ][0] = t[0]; bH[2*p    ][1] = t[1];
                bH[2*p + 1][0] = t[2]; bH[2*p + 1][1] = t[3];
            }
            #pragma unroll
            for (int mt = 0; mt < 4; mt++)
                #pragma unroll
                for (int nt = 0; nt < 4; nt++)
                    mma16816(acc[mt][nt], aH[mt], bH[nt]);
            #pragma unroll
            for (int p = 0; p < 2; p++) {
                uint32_t ad = st + 3*TILE_B
                    + (uint32_t)((wn + p*16 + b_nt + b_row) * 80
                                 + (k16 + b_kof) * 2);
                LDSM4(t, ad);
                uint32_t bl0[2] = { t[0], t[1] }, bl1[2] = { t[2], t[3] };
                #pragma unroll
                for (int mt = 0; mt < 4; mt++) {
                    mma16816(acc[mt][2*p    ], aH[mt], bl0);
                    mma16816(acc[mt][2*p + 1], aH[mt], bl1);
                }
            }
            #pragma unroll
            for (int mt = 0; mt < 4; mt++) {
                uint32_t ad = st + TILE_B
                    + (uint32_t)((wm + mt*16 + a_row) * 80
                                 + (k16 + a_kof) * 2);
                LDSM4(t, ad);
                #pragma unroll
                for (int nt = 0; nt < 4; nt++)
                    mma16816(acc[mt][nt], t, bH[nt]);
            }
        }
        __syncthreads();
    }

    const int g  = lane >> 2;
    const int tg = lane & 3;
    #pragma unroll
    for (int mt = 0; mt < 4; mt++) {
        #pragma unroll
        for (int nt = 0; nt < 4; nt++) {
            const int row = brow + wm + mt*16 + g;
            const int col = bcol + wn + nt*8 + tg*2;
            float2 v0, v1;
            v0.x = acc[mt][nt][0]; v0.y = acc[mt][nt][1];
            v1.x = acc[mt][nt][2]; v1.y = acc[mt][nt][3];
            if (bias) {
                float2 bb = *(const float2*)&bias[col];
                v0.x += bb.x; v0.y += bb.y; v1.x += bb.x; v1.y += bb.y;
            }
            if (relu) {
                v0.x = fmaxf(v0.x, 0.f); v0.y = fmaxf(v0.y, 0.f);
                v1.x = fmaxf(v1.x, 0.f); v1.y = fmaxf(v1.y, 0.f);
            }
            const size_t o0 = (size_t)row * ldc + coff + col;
            const size_t o1 = (size_t)(row + 8) * ldc + coff + col;
            if (C) {
                *(float2*)&C[o0] = v0;
                *(float2*)&C[o1] = v1;
            }
            if (Ch) {
                __nv_bfloat162 hh, ll;
                split1(v0.x, hh.x, ll.x); split1(v0.y, hh.y, ll.y);
                *(__nv_bfloat162*)&Ch[o0] = hh;
                *(__nv_bfloat162*)&Cl[o0] = ll;
                split1(v1.x, hh.x, ll.x); split1(v1.y, hh.y, ll.y);
                *(__nv_bfloat162*)&Ch[o1] = hh;
                *(__nv_bfloat162*)&Cl[o1] = ll;
            }
        }
    }
}

// ---------------------------------------------------------------------------
// Fused flash attention, OCCUPANCY 2: 64-row K/V tiles in SW128-swizzled
// 128B rows (8KB/tile, 32KB/stage, 2 stages) + Q at stride 144.
// Block: 128 q-rows of one (b,h); 16 k-tiles of 64. Split-bf16 throughout.
// ---------------------------------------------------------------------------
constexpr int FA_QTB   = 128 * 144;               // 18432 B per Q tile (h or l)
constexpr int FA_KTB   = 64 * 128;                // 8192 B per K/V tile
constexpr int FA_STAGE = 4 * FA_KTB;              // 32768 B
constexpr int FA_SMEM  = 2*FA_QTB + 2*FA_STAGE + 4096;   // 106496 B

__global__ __launch_bounds__(256, 2) void flash_attn(
    const __nv_bfloat16* __restrict__ Xh, const __nv_bfloat16* __restrict__ Xl,
    const float* __restrict__ mask, const int* __restrict__ pad,
    __nv_bfloat16* __restrict__ Oh, __nv_bfloat16* __restrict__ Ol)
{
    extern __shared__ char sm[];
    const uint32_t sb = smem_u32(sm);
    const int tid  = threadIdx.x;
    const int wid  = tid >> 5;
    const int lane = tid & 31;
    const int qy   = blockIdx.x * 128;
    const int bh   = blockIdx.y;
    const int b    = bh >> 4;
    const int hcol = (bh & 15) * HDc;
    const int wq   = wid * 16;

    const uint32_t sQh    = sb;
    const uint32_t sQl    = sb + FA_QTB;
    const uint32_t sStage = sb + 2*FA_QTB;
    float* spad = (float*)(sm + 2*FA_QTB + 2*FA_STAGE);

    for (int i = tid; i < 1024; i += 256)
        spad[i] = (float)pad[b*Lc + i];

    // Q tile cp.async (group 0), stride 144 (unswizzled, conflict-free)
    for (int i = tid; i < 1024; i += 256) {
        const int r = i >> 3, j = i & 7;
        const uint32_t so = (uint32_t)(r * 144 + j * 16);
        const size_t gq = (size_t)(b*Lc + qy + r) * QKVW + hcol + j*8;
        cpasync16(sQh + so, Xh + gq);
        cpasync16(sQl + so, Xl + gq);
    }
    CP_COMMIT();

    auto issueKV = [&](int t, int s) {
        const int kx = t * 64;
        const uint32_t base = sStage + s * FA_STAGE;
        for (int i = tid; i < 512; i += 256) {
            const int r = i >> 3, j = i & 7;
            const uint32_t so = FSW((uint32_t)(r * 128 + j * 16));
            const size_t gk = (size_t)(b*Lc + kx + r) * QKVW + 1024 + hcol + j*8;
            cpasync16(base + so,             Xh + gk);
            cpasync16(base + FA_KTB + so,    Xl + gk);
            cpasync16(base + 2*FA_KTB + so,  Xh + gk + 1024);
            cpasync16(base + 3*FA_KTB + so,  Xl + gk + 1024);
        }
        CP_COMMIT();
    };
    issueKV(0, 0);

    CP_WAIT(1);          // Q complete
    __syncthreads();

    const int a_row = lane & 15;
    const int a_kof = (lane >> 4) << 3;
    uint32_t qh[4][4];                      // Q-hi persistent; Q-lo reloaded
    #pragma unroll
    for (int kt = 0; kt < 4; kt++)
        LDSM4(qh[kt], sQh + (uint32_t)((wq + a_row)*144 + (kt*16 + a_kof)*2));

    float m[2] = { -1e30f, -1e30f };
    float l[2] = { 0.f, 0.f };
    float o[8][4];
    #pragma unroll
    for (int i = 0; i < 8; i++)
        #pragma unroll
        for (int j = 0; j < 4; j++) o[i][j] = 0.f;

    const int g    = lane >> 2;
    const int tg   = lane & 3;
    const int g8   = lane >> 3;
    const int b_nt  = (g8 >> 1) << 3;
    const int b_kof = (g8 & 1) << 3;
    const int b_row = lane & 7;
    const int v_kv = ((lane >> 3) & 1) << 3;
    const int v_d  = (lane >> 4) << 3;

    for (int t = 0; t < 16; t++) {
        const int kx = t * 64;
        if (t + 1 < 16) { issueKV(t + 1, (t + 1) & 1); CP_WAIT(1); }
        else            { CP_WAIT(0); }
        __syncthreads();

        const uint32_t stK  = sStage + (t & 1) * FA_STAGE;
        const uint32_t stKl = stK + FA_KTB;
        const uint32_t stVh = stK + 2*FA_KTB;
        const uint32_t stVl = stK + 3*FA_KTB;

        // ---- S = Q K^T (split): 64 keys ----
        float sf[8][4];
        #pragma unroll
        for (int i = 0; i < 8; i++)
            #pragma unroll
            for (int j = 0; j < 4; j++) sf[i][j] = 0.f;

        #pragma unroll
        for (int kst = 0; kst < 4; kst++) {
            uint32_t qlf[4];
            LDSM4(qlf, sQl + (uint32_t)((wq + a_row)*144 + (kst*16 + a_kof)*2));
            uint32_t kb[4][4];
            #pragma unroll
            for (int p = 0; p < 4; p++) {
                const uint32_t ad = stK + FSW((uint32_t)((p*16 + b_nt + b_row)*128
                                                          + kst*32 + b_kof*2));
                LDSM4(kb[p], ad);
            }
            #pragma unroll
            for (int p = 0; p < 4; p++) {
                uint32_t b0[2] = { kb[p][0], kb[p][1] };
                uint32_t b1[2] = { kb[p][2], kb[p][3] };
                mma16816(sf[2*p],   qh[kst], b0);
                mma16816(sf[2*p+1], qh[kst], b1);
                mma16816(sf[2*p],   qlf, b0);
                mma16816(sf[2*p+1], qlf, b1);
            }
            #pragma unroll
            for (int p = 0; p < 4; p++) {
                const uint32_t ad = stKl + FSW((uint32_t)((p*16 + b_nt + b_row)*128
                                                           + kst*32 + b_kof*2));
                LDSM4(kb[p], ad);
            }
            #pragma unroll
            for (int p = 0; p < 4; p++) {
                uint32_t b0[2] = { kb[p][0], kb[p][1] };
                uint32_t b1[2] = { kb[p][2], kb[p][3] };
                mma16816(sf[2*p],   qh[kst], b0);
                mma16816(sf[2*p+1], qh[kst], b1);
            }
        }

        // ---- scale + mask + pad ----
        const int qg0 = qy + wq + g;
        #pragma unroll
        for (int nt = 0; nt < 8; nt++) {
            const int kvl = nt*8 + tg*2;
            const int kvg = kx + kvl;
            float2 m0 = *(const float2*)&mask[(size_t)qg0 * Lc + kvg];
            float2 m1 = *(const float2*)&mask[(size_t)(qg0 + 8) * Lc + kvg];
            const float p0 = spad[kvg], p1 = spad[kvg + 1];
            sf[nt][0] = sf[nt][0]*0.125f + m0.x + p0;
            sf[nt][1] = sf[nt][1]*0.125f + m0.y + p1;
            sf[nt][2] = sf[nt][2]*0.125f + m1.x + p0;
            sf[nt][3] = sf[nt][3]*0.125f + m1.y + p1;
        }

        // ---- online softmax ----
        float mx0 = m[0], mx1 = m[1];
        #pragma unroll
        for (int nt = 0; nt < 8; nt++) {
            mx0 = fmaxf(mx0, fmaxf(sf[nt][0], sf[nt][1]));
            mx1 = fmaxf(mx1, fmaxf(sf[nt][2], sf[nt][3]));
        }
        mx0 = fmaxf(mx0, __shfl_xor_sync(0xffffffffu, mx0, 1));
        mx0 = fmaxf(mx0, __shfl_xor_sync(0xffffffffu, mx0, 2));
        mx1 = fmaxf(mx1, __shfl_xor_sync(0xffffffffu, mx1, 1));
        mx1 = fmaxf(mx1, __shfl_xor_sync(0xffffffffu, mx1, 2));

        const float al0 = __expf(m[0] - mx0);
        const float al1 = __expf(m[1] - mx1);
        m[0] = mx0; m[1] = mx1;
        #pragma unroll
        for (int nt = 0; nt < 8; nt++) {
            o[nt][0] *= al0; o[nt][1] *= al0;
            o[nt][2] *= al1; o[nt][3] *= al1;
        }

        uint32_t ph[4][4], pl[4][4];
        float s0 = 0.f, s1 = 0.f;
        #pragma unroll
        for (int j = 0; j < 4; j++) {
            float e00 = __expf(sf[2*j][0]   - mx0);
            float e01 = __expf(sf[2*j][1]   - mx0);
            float e10 = __expf(sf[2*j][2]   - mx1);
            float e11 = __expf(sf[2*j][3]   - mx1);
            float e20 = __expf(sf[2*j+1][0] - mx0);
            float e21 = __expf(sf[2*j+1][1] - mx0);
            float e30 = __expf(sf[2*j+1][2] - mx1);
            float e31 = __expf(sf[2*j+1][3] - mx1);
            s0 += e00 + e01 + e20 + e21;
            s1 += e10 + e11 + e30 + e31;
            ph[j][0] = packbf(e00, e01);
            ph[j][1] = packbf(e10, e11);
            ph[j][2] = packbf(e20, e21);
            ph[j][3] = packbf(e30, e31);
            __nv_bfloat162* hp = (__nv_bfloat162*)&ph[j][0];
            pl[j][0] = packbf(e00 - __bfloat162float(hp[0].x),
                              e01 - __bfloat162float(hp[0].y));
            hp = (__nv_bfloat162*)&ph[j][1];
            pl[j][1] = packbf(e10 - __bfloat162float(hp[0].x),
                              e11 - __bfloat162float(hp[0].y));
            hp = (__nv_bfloat162*)&ph[j][2];
            pl[j][2] = packbf(e20 - __bfloat162float(hp[0].x),
                              e21 - __bfloat162float(hp[0].y));
            hp = (__nv_bfloat162*)&ph[j][3];
            pl[j][3] = packbf(e30 - __bfloat162float(hp[0].x),
                              e31 - __bfloat162float(hp[0].y));
        }
        s0 += __shfl_xor_sync(0xffffffffu, s0, 1);
        s0 += __shfl_xor_sync(0xffffffffu, s0, 2);
        s1 += __shfl_xor_sync(0xffffffffu, s1, 1);
        s1 += __shfl_xor_sync(0xffffffffu, s1, 2);
        l[0] = l[0]*al0 + s0;
        l[1] = l[1]*al1 + s1;

        // ---- O += P V (split): 64 kv rows ----
        #pragma unroll
        for (int j = 0; j < 4; j++) {
            #pragma unroll
            for (int p = 0; p < 4; p++) {
                uint32_t th[4], tl[4];
                const uint32_t off = FSW((uint32_t)((j*16 + v_kv + b_row)*128
                                                     + p*32 + v_d*2));
                LDSM4T(th, stVh + off);
                LDSM4T(tl, stVl + off);
                uint32_t bh0[2] = { th[0], th[1] }, bh1[2] = { th[2], th[3] };
                uint32_t bl0[2] = { tl[0], tl[1] }, bl1[2] = { tl[2], tl[3] };
                mma16816(o[2*p],   ph[j], bh0);
                mma16816(o[2*p+1], ph[j], bh1);
                mma16816(o[2*p],   ph[j], bl0);
                mma16816(o[2*p+1], ph[j], bl1);
                mma16816(o[2*p],   pl[j], bh0);
                mma16816(o[2*p+1], pl[j], bh1);
            }
        }
        __syncthreads();
    }

    const float inv0 = 1.f / l[0];
    const float inv1 = 1.f / l[1];
    const int row = b*Lc + qy + wq + g;
    #pragma unroll
    for (int nt = 0; nt < 8; nt++) {
        const int col = hcol + nt*8 + tg*2;
        __nv_bfloat162 hh, ll;
        split1(o[nt][0]*inv0, hh.x, ll.x);
        split1(o[nt][1]*inv0, hh.y, ll.y);
        *(__nv_bfloat162*)&Oh[(size_t)row * Dc + col] = hh;
        *(__nv_bfloat162*)&Ol[(size_t)row * Dc + col] = ll;
        split1(o[nt][2]*inv1, hh.x, ll.x);
        split1(o[nt][3]*inv1, hh.y, ll.y);
        *(__nv_bfloat162*)&Oh[(size_t)(row + 8) * Dc + col] = hh;
        *(__nv_bfloat162*)&Ol[(size_t)(row + 8) * Dc + col] = ll;
    }
}

// ---------------------------------------------------------------------------
// small kernels
// ---------------------------------------------------------------------------
__global__ __launch_bounds__(256) void split_f32(
    const float* __restrict__ x, __nv_bfloat16* __restrict__ h,
    __nv_bfloat16* __restrict__ l)
{
    const size_t i = ((size_t)blockIdx.x * 256 + threadIdx.x) * 4;
    float4 v = *(const float4*)(x + i);
    __nv_bfloat162 hh0, hh1, ll0, ll1;
    split1(v.x, hh0.x, ll0.x); split1(v.y, hh0.y, ll0.y);
    split1(v.z, hh1.x, ll1.x); split1(v.w, hh1.y, ll1.y);
    *(__nv_bfloat162*)(h + i)     = hh0;
    *(__nv_bfloat162*)(h + i + 2) = hh1;
    *(__nv_bfloat162*)(l + i)     = ll0;
    *(__nv_bfloat162*)(l + i + 2) = ll1;
}

__global__ __launch_bounds__(256) void transpose_split(
    const float* __restrict__ W, __nv_bfloat16* __restrict__ h,
    __nv_bfloat16* __restrict__ l, int K, int N, size_t ostrideZ)
{
    __shared__ float t[32][33];
    const size_t ibase = (size_t)blockIdx.z * K * N;
    const size_t obase = (size_t)blockIdx.z * ostrideZ;
    const int k0 = blockIdx.y * 32, n0 = blockIdx.x * 32;
    const int tx = threadIdx.x & 31, ty = threadIdx.x >> 5;
    #pragma unroll
    for (int r = 0; r < 32; r += 8)
        t[ty + r][tx] = W[ibase + (size_t)(k0 + ty + r) * N + n0 + tx];
    __syncthreads();
    #pragma unroll
    for (int r = 0; r < 32; r += 8) {
        const float v = t[tx][ty + r];
        const size_t o = obase + (size_t)(n0 + ty + r) * K + k0 + tx;
        __nv_bfloat16 hh, ll;
        split1(v, hh, ll);
        h[o] = hh; l[o] = ll;
    }
}

__global__ void bias_cat(const float* __restrict__ bq, const float* __restrict__ bk,
                         const float* __restrict__ bv, float* __restrict__ o)
{
    const int i = blockIdx.x, seg = blockIdx.y, j = threadIdx.x;
    const float* src = (seg == 0) ? bq : (seg == 1) ? bk : bv;
    o[i*QKVW + seg*1024 + j] = src[i*1024 + j];
}

// y (fp32) is optional (nullable); split output always written
__global__ __launch_bounds__(256) void add_ln(
    const float* __restrict__ x, const float* __restrict__ res,
    const float* __restrict__ g, const float* __restrict__ bta,
    float* __restrict__ y, __nv_bfloat16* __restrict__ yh,
    __nv_bfloat16* __restrict__ yl)
{
    __shared__ float rs[8], rq[8];
    const int tid = threadIdx.x;
    const size_t base = (size_t)blockIdx.x * 1024 + tid * 4;

    float4 a = *(const float4*)&x[base];
    float4 r = *(const float4*)&res[base];
    a.x += r.x; a.y += r.y; a.z += r.z; a.w += r.w;

    float s = a.x + a.y + a.z + a.w;
    float q = a.x*a.x + a.y*a.y + a.z*a.z + a.w*a.w;
    #pragma unroll
    for (int o = 16; o > 0; o >>= 1) {
        s += __shfl_xor_sync(0xffffffffu, s, o);
        q += __shfl_xor_sync(0xffffffffu, q, o);
    }
    if ((tid & 31) == 0) { rs[tid >> 5] = s; rq[tid >> 5] = q; }
    __syncthreads();
    s = 0.f; q = 0.f;
    #pragma unroll
    for (int i = 0; i < 8; i++) { s += rs[i]; q += rq[i]; }

    const float mean = s * (1.f / 1024.f);
    const float var  = q * (1.f / 1024.f) - mean * mean;
    const float rstd = rsqrtf(var + 1e-5f);

    const int c = tid * 4;
    float4 gv = *(const float4*)&g[c];
    float4 bv = *(const float4*)&bta[c];
    float4 o;
    o.x = (a.x - mean) * rstd * gv.x + bv.x;
    o.y = (a.y - mean) * rstd * gv.y + bv.y;
    o.z = (a.z - mean) * rstd * gv.z + bv.z;
    o.w = (a.w - mean) * rstd * gv.w + bv.w;
    if (y) *(float4*)&y[base] = o;

    __nv_bfloat162 hh0, hh1, ll0, ll1;
    split1(o.x, hh0.x, ll0.x); split1(o.y, hh0.y, ll0.y);
    split1(o.z, hh1.x, ll1.x); split1(o.w, hh1.y, ll1.y);
    *(__nv_bfloat162*)&yh[base]     = hh0;
    *(__nv_bfloat162*)&yh[base + 2] = hh1;
    *(__nv_bfloat162*)&yl[base]     = ll0;
    *(__nv_bfloat162*)&yl[base + 2] = ll1;
}

// ---------------------------------------------------------------------------
// Launch orchestration (two-stream fork/join)
// ---------------------------------------------------------------------------
extern "C" void kernel_launch(void* const* d_in, const int* in_sizes, int n_in,
                              void* d_out, int out_size)
{
    const float* T    = (const float*)d_in[0];
    const float* A    = (const float*)d_in[1];
    const float* mask = (const float*)d_in[2];
    const int*   pad  = (const int*)  d_in[3];
    const float* Wq   = (const float*)d_in[4];
    const float* bq   = (const float*)d_in[5];
    const float* Wk   = (const float*)d_in[6];
    const float* bk   = (const float*)d_in[7];
    const float* Wv   = (const float*)d_in[8];
    const float* bv   = (const float*)d_in[9];
    const float* Wo   = (const float*)d_in[10];
    const float* ffW1 = (const float*)d_in[11];
    const float* ffb1 = (const float*)d_in[12];
    const float* ffW2 = (const float*)d_in[13];
    const float* ffb2 = (const float*)d_in[14];
    const float* lng  = (const float*)d_in[15];
    const float* lnb  = (const float*)d_in[16];
    float* out = (float*)d_out;

    static cudaStream_t sA = nullptr, sB = nullptr;
    static cudaEvent_t  eF = nullptr, eA = nullptr, eB = nullptr;
    if (!sA) {
        cudaStreamCreateWithFlags(&sA, cudaStreamNonBlocking);
        cudaStreamCreateWithFlags(&sB, cudaStreamNonBlocking);
        cudaEventCreateWithFlags(&eF, cudaEventDisableTiming);
        cudaEventCreateWithFlags(&eA, cudaEventDisableTiming);
        cudaEventCreateWithFlags(&eB, cudaEventDisableTiming);
    }
    auto fork = [&]() {
        cudaEventRecord(eF, 0);
        cudaStreamWaitEvent(sA, eF, 0);
        cudaStreamWaitEvent(sB, eF, 0);
    };
    auto join = [&]() {
        cudaEventRecord(eA, sA);
        cudaEventRecord(eB, sB);
        cudaStreamWaitEvent(0, eA, 0);
        cudaStreamWaitEvent(0, eB, 0);
    };

    float *Mo0, *Mo1, *T1f, *A1f;
    cudaGetSymbolAddress((void**)&Mo0, g_Mo0);
    cudaGetSymbolAddress((void**)&Mo1, g_Mo1);
    cudaGetSymbolAddress((void**)&T1f, g_T1f);
    cudaGetSymbolAddress((void**)&A1f, g_A1f);

    __nv_bfloat16 *iTh,*iTl,*iAh,*iAl,*T1h,*T1l,*A1h,*A1l,*T2h,*T2l,*A2h,*A2l;
    __nv_bfloat16 *QKV0h,*QKV0l,*QKV1h,*QKV1l,*O0h,*O0l,*O1h,*O1l;
    __nv_bfloat16 *H0h,*H0l,*H1h,*H1l;
    __nv_bfloat16 *wch,*wcl,*woh,*wol,*w1h,*w1l,*w2h,*w2l;
    float* bcat;
    cudaGetSymbolAddress((void**)&iTh, g_iTh); cudaGetSymbolAddress((void**)&iTl, g_iTl);
    cudaGetSymbolAddress((void**)&iAh, g_iAh); cudaGetSymbolAddress((void**)&iAl, g_iAl);
    cudaGetSymbolAddress((void**)&T1h, g_T1h); cudaGetSymbolAddress((void**)&T1l, g_T1l);
    cudaGetSymbolAddress((void**)&A1h, g_A1h); cudaGetSymbolAddress((void**)&A1l, g_A1l);
    cudaGetSymbolAddress((void**)&T2h, g_T2h); cudaGetSymbolAddress((void**)&T2l, g_T2l);
    cudaGetSymbolAddress((void**)&A2h, g_A2h); cudaGetSymbolAddress((void**)&A2l, g_A2l);
    cudaGetSymbolAddress((void**)&QKV0h, g_QKV0h); cudaGetSymbolAddress((void**)&QKV0l, g_QKV0l);
    cudaGetSymbolAddress((void**)&QKV1h, g_QKV1h); cudaGetSymbolAddress((void**)&QKV1l, g_QKV1l);
    cudaGetSymbolAddress((void**)&O0h, g_O0h); cudaGetSymbolAddress((void**)&O0l, g_O0l);
    cudaGetSymbolAddress((void**)&O1h, g_O1h); cudaGetSymbolAddress((void**)&O1l, g_O1l);
    cudaGetSymbolAddress((void**)&H0h, g_H0h); cudaGetSymbolAddress((void**)&H0l, g_H0l);
    cudaGetSymbolAddress((void**)&H1h, g_H1h); cudaGetSymbolAddress((void**)&H1l, g_H1l);
    cudaGetSymbolAddress((void**)&wch, g_wch); cudaGetSymbolAddress((void**)&wcl, g_wcl);
    cudaGetSymbolAddress((void**)&woh, g_woh); cudaGetSymbolAddress((void**)&wol, g_wol);
    cudaGetSymbolAddress((void**)&w1h, g_w1h); cudaGetSymbolAddress((void**)&w1l, g_w1l);
    cudaGetSymbolAddress((void**)&w2h, g_w2h); cudaGetSymbolAddress((void**)&w2l, g_w2l);
    cudaGetSymbolAddress((void**)&bcat, g_bcat);

    cudaFuncSetAttribute(gemm_mma,   cudaFuncAttributeMaxDynamicSharedMemorySize, GEMM_SMEM);
    cudaFuncSetAttribute(flash_attn, cudaFuncAttributeMaxDynamicSharedMemorySize, FA_SMEM);

    const size_t DD = (size_t)Dc * Dc;
    const size_t WCZ = (size_t)QKVW * Dc;

    auto gemm = [&](cudaStream_t st,
                    const __nv_bfloat16* ah, const __nv_bfloat16* al,
                    const __nv_bfloat16* bh, const __nv_bfloat16* bl,
                    const float* bias, float* c, __nv_bfloat16* ch, __nv_bfloat16* cl,
                    int M, int N, int K, int ldc, int coff, int relu) {
        gemm_mma<<<dim3(N/128, M/128), 256, GEMM_SMEM, st>>>(
            ah, al, bh, bl, bias, c, ch, cl, M, N, K, ldc, coff, relu);
    };

    // ---------------- Phase 0: weight prep + input splits ----------------
    fork();
    transpose_split<<<dim3(32,32,4), 256, 0, sA>>>(Wq, wch,        wcl,        Dc, Dc, WCZ);
    transpose_split<<<dim3(32,32,4), 256, 0, sA>>>(Wk, wch + DD,   wcl + DD,   Dc, Dc, WCZ);
    transpose_split<<<dim3(32,32,4), 256, 0, sA>>>(Wv, wch + 2*DD, wcl + 2*DD, Dc, Dc, WCZ);
    bias_cat<<<dim3(4,3), 1024, 0, sA>>>(bq, bk, bv, bcat);
    split_f32<<<BLc, 256, 0, sA>>>(T, iTh, iTl);
    transpose_split<<<dim3(32,32,4),  256, 0, sB>>>(Wo,   woh, wol, Dc, Dc, DD);
    transpose_split<<<dim3(128,32,2), 256, 0, sB>>>(ffW1, w1h, w1l, Dc, Fc, (size_t)Dc*Fc);
    transpose_split<<<dim3(32,128,2), 256, 0, sB>>>(ffW2, w2h, w2l, Fc, Dc, (size_t)Fc*Dc);
    split_f32<<<BLc, 256, 0, sB>>>(A, iAh, iAl);
    join();

    // ---------------- Phase 1: mha0 (T, sA) || mha1 (A, sB) ----------------
    fork();
    gemm(sA, iTh, iTl, wch, wcl, bcat, nullptr, QKV0h, QKV0l,
         BLc, QKVW, Dc, QKVW, 0, 0);
    flash_attn<<<dim3(Lc/128, 64), 256, FA_SMEM, sA>>>(QKV0h, QKV0l, mask, pad, O0h, O0l);
    gemm(sA, O0h, O0l, woh, wol, nullptr, Mo0, nullptr, nullptr,
         BLc, Dc, Dc, Dc, 0, 0);
    add_ln<<<BLc, 256, 0, sA>>>(T, Mo0, lng, lnb, T1f, T1h, T1l);
    gemm(sB, iAh, iAl, wch + WCZ, wcl + WCZ, bcat + QKVW, nullptr, QKV1h, QKV1l,
         BLc, QKVW, Dc, QKVW, 0, 0);
    flash_attn<<<dim3(Lc/128, 64), 256, FA_SMEM, sB>>>(QKV1h, QKV1l, mask, pad, O1h, O1l);
    gemm(sB, O1h, O1l, woh + DD, wol + DD, nullptr, Mo1, nullptr, nullptr,
         BLc, Dc, Dc, Dc, 0, 0);
    add_ln<<<BLc, 256, 0, sB>>>(A, Mo1, lng + Dc, lnb + Dc, A1f, A1h, A1l);
    join();

    // ---------------- Phase 2: mha2 (Q from T1, KV from A1) ----------------
    fork();
    gemm(sA, T1h, T1l, wch + 2*WCZ, wcl + 2*WCZ, bcat + 2*QKVW,
         nullptr, QKV0h, QKV0l, BLc, Dc, Dc, QKVW, 0, 0);
    gemm(sB, A1h, A1l, wch + 2*WCZ + DD, wcl + 2*WCZ + DD, bcat + 2*QKVW + 1024,
         nullptr, QKV0h, QKV0l, BLc, 2*Dc, Dc, QKVW, 1024, 0);
    join();
    flash_attn<<<dim3(Lc/128, 64), 256, FA_SMEM>>>(QKV0h, QKV0l, mask, pad, O0h, O0l);
    gemm(0, O0h, O0l, woh + 2*DD, wol + 2*DD, nullptr, Mo0, nullptr, nullptr,
         BLc, Dc, Dc, Dc, 0, 0);
    add_ln<<<BLc, 256>>>(T1f, Mo0, lng + 2*Dc, lnb + 2*Dc, nullptr, T2h, T2l);

    // ---------------- Phase 3: mha3 (Q from A1, KV from T2) ----------------
    fork();
    gemm(sA, A1h, A1l, wch + 3*WCZ, wcl + 3*WCZ, bcat + 3*QKVW,
         nullptr, QKV0h, QKV0l, BLc, Dc, Dc, QKVW, 0, 0);
    gemm(sB, T2h, T2l, wch + 3*WCZ + DD, wcl + 3*WCZ + DD, bcat + 3*QKVW + 1024,
         nullptr, QKV0h, QKV0l, BLc, 2*Dc, Dc, QKVW, 1024, 0);
    join();
    flash_attn<<<dim3(Lc/128, 64), 256, FA_SMEM>>>(QKV0h, QKV0l, mask, pad, O0h, O0l);
    gemm(0, O0h, O0l, woh + 3*DD, wol + 3*DD, nullptr, Mo0, nullptr, nullptr,
         BLc, Dc, Dc, Dc, 0, 0);
    add_ln<<<BLc, 256>>>(A1f, Mo0, lng + 3*Dc, lnb + 3*Dc, nullptr, A2h, A2l);

    // ---------------- Phase 4: FFN-T (sA) || FFN-A (sB) ----------------
    fork();
    gemm(sA, T2h, T2l, w1h, w1l, ffb1, nullptr, H0h, H0l, BLc, Fc, Dc, Fc, 0, 1);
    gemm(sA, H0h, H0l, w2h, w2l, ffb2, out, nullptr, nullptr, BLc, Dc, Fc, Dc, 0, 0);
    gemm(sB, A2h, A2l, w1h + (size_t)Dc*Fc, w1l + (size_t)Dc*Fc, ffb1 + Fc,
         nullptr, H1h, H1l, BLc, Fc, Dc, Fc, 0, 1);
    gemm(sB, H1h, H1l, w2h + (size_t)Fc*Dc, w2l + (size_t)Fc*Dc, ffb2 + Dc,
         out + (size_t)BLc*Dc, nullptr, nullptr, BLc, Dc, Fc, Dc, 0, 0);
    join();
}

// round 8
// speedup vs baseline: 3.4457x; 1.0298x over previous
#include <cuda_runtime.h>
#include <cuda_bf16.h>
#include <math.h>
#include <stdint.h>

// Problem constants
constexpr int Bc  = 4;
constexpr int Lc  = 1024;
constexpr int Dc  = 1024;
constexpr int Fc  = 4096;
constexpr int HDc = 64;
constexpr int BLc = Bc * Lc;          // 4096 rows
constexpr int QKVW = 3 * Dc;          // 3072 concat width

// ---------------------------------------------------------------------------
// Scratch (static __device__ arrays — allocation-free per harness rules)
// ---------------------------------------------------------------------------
__device__ float g_Mo0[BLc * Dc];
__device__ float g_Mo1[BLc * Dc];
__device__ float g_T1f[BLc * Dc];
__device__ float g_A1f[BLc * Dc];

__device__ __nv_bfloat16 g_iTh[BLc*Dc], g_iTl[BLc*Dc];
__device__ __nv_bfloat16 g_iAh[BLc*Dc], g_iAl[BLc*Dc];
__device__ __nv_bfloat16 g_T1h[BLc*Dc], g_T1l[BLc*Dc];
__device__ __nv_bfloat16 g_A1h[BLc*Dc], g_A1l[BLc*Dc];
__device__ __nv_bfloat16 g_T2h[BLc*Dc], g_T2l[BLc*Dc];
__device__ __nv_bfloat16 g_A2h[BLc*Dc], g_A2l[BLc*Dc];
__device__ __nv_bfloat16 g_QKV0h[(size_t)BLc*QKVW], g_QKV0l[(size_t)BLc*QKVW];
__device__ __nv_bfloat16 g_QKV1h[(size_t)BLc*QKVW], g_QKV1l[(size_t)BLc*QKVW];
__device__ __nv_bfloat16 g_O0h[BLc*Dc], g_O0l[BLc*Dc];
__device__ __nv_bfloat16 g_O1h[BLc*Dc], g_O1l[BLc*Dc];
__device__ __nv_bfloat16 g_H0h[(size_t)BLc*Fc], g_H0l[(size_t)BLc*Fc];
__device__ __nv_bfloat16 g_H1h[(size_t)BLc*Fc], g_H1l[(size_t)BLc*Fc];

// weights: concat QKV^T [4][3072,1024]; others [N,K]
__device__ __nv_bfloat16 g_wch[(size_t)4*QKVW*Dc], g_wcl[(size_t)4*QKVW*Dc];
__device__ __nv_bfloat16 g_woh[4*Dc*Dc], g_wol[4*Dc*Dc];
__device__ __nv_bfloat16 g_w1h[2*Dc*Fc], g_w1l[2*Dc*Fc];
__device__ __nv_bfloat16 g_w2h[2*Fc*Dc], g_w2l[2*Fc*Dc];
__device__ float g_bcat[4*QKVW];

// ---------------------------------------------------------------------------
// PTX helpers (sm_103 baseline-safe)
// ---------------------------------------------------------------------------
__device__ __forceinline__ uint32_t smem_u32(const void* p) {
    uint32_t a;
    asm("{ .reg .u64 t; cvta.to.shared.u64 t, %1; cvt.u32.u64 %0, t; }" : "=r"(a) : "l"(p));
    return a;
}
__device__ __forceinline__ void cpasync16(uint32_t dst, const void* src) {
    asm volatile("cp.async.cg.shared.global [%0], [%1], 16;" :: "r"(dst), "l"(src));
}
#define CP_COMMIT()  asm volatile("cp.async.commit_group;" ::: "memory")
#define CP_WAIT(n)   asm volatile("cp.async.wait_group %0;" :: "n"(n) : "memory")

#define LDSM4(r, a) \
    asm volatile("ldmatrix.sync.aligned.m8n8.x4.shared.b16 {%0,%1,%2,%3}, [%4];" \
        : "=r"((r)[0]), "=r"((r)[1]), "=r"((r)[2]), "=r"((r)[3]) : "r"(a))
#define LDSM4T(r, a) \
    asm volatile("ldmatrix.sync.aligned.m8n8.x4.trans.shared.b16 {%0,%1,%2,%3}, [%4];" \
        : "=r"((r)[0]), "=r"((r)[1]), "=r"((r)[2]), "=r"((r)[3]) : "r"(a))

__device__ __forceinline__ void mma16816(float* c, const uint32_t* a, const uint32_t* b) {
    asm volatile(
        "mma.sync.aligned.m16n8k16.row.col.f32.bf16.bf16.f32 "
        "{%0,%1,%2,%3}, {%4,%5,%6,%7}, {%8,%9}, {%0,%1,%2,%3};"
        : "+f"(c[0]), "+f"(c[1]), "+f"(c[2]), "+f"(c[3])
        : "r"(a[0]), "r"(a[1]), "r"(a[2]), "r"(a[3]), "r"(b[0]), "r"(b[1]));
}

__device__ __forceinline__ void split1(float v, __nv_bfloat16& h, __nv_bfloat16& l) {
    h = __float2bfloat16(v);
    l = __float2bfloat16(v - __bfloat162float(h));
}
__device__ __forceinline__ uint32_t packbf(float a, float b) {
    __nv_bfloat162 t; t.x = __float2bfloat16(a); t.y = __float2bfloat16(b);
    return *(uint32_t*)&t;
}
#define FSW(o) ((o) ^ (((o) >> 3) & 0x70))     // SW128 swizzle for 128B rows

// ---------------------------------------------------------------------------
// Tensor-core GEMM (unchanged — passing). Output: fp32 (C) or split-bf16
// (Ch/Cl); stride ldc, col offset coff.
// ---------------------------------------------------------------------------
constexpr int GSTR    = 40;
constexpr int TILE_B  = 128 * GSTR * 2;
constexpr int STAGE_B = 4 * TILE_B;
constexpr int GEMM_SMEM = 2 * STAGE_B;

__global__ __launch_bounds__(256, 2) void gemm_mma(
    const __nv_bfloat16* __restrict__ Ah, const __nv_bfloat16* __restrict__ Al,
    const __nv_bfloat16* __restrict__ Bh, const __nv_bfloat16* __restrict__ Bl,
    const float* __restrict__ bias, float* __restrict__ C,
    __nv_bfloat16* __restrict__ Ch, __nv_bfloat16* __restrict__ Cl,
    int M, int N, int K, int ldc, int coff, int relu)
{
    extern __shared__ char sm[];
    const uint32_t sb = smem_u32(sm);
    const int tid  = threadIdx.x;
    const int wid  = tid >> 5;
    const int lane = tid & 31;
    const int brow = blockIdx.y * 128;
    const int bcol = blockIdx.x * 128;
    const int wm   = (wid & 1) * 64;
    const int wn   = (wid >> 1) * 32;

    float acc[4][4][4];
    #pragma unroll
    for (int i = 0; i < 4; i++)
        #pragma unroll
        for (int j = 0; j < 4; j++)
            #pragma unroll
            for (int k = 0; k < 4; k++) acc[i][j][k] = 0.f;

    const int r0 = tid >> 2,            q0 = tid & 3;
    const int r1 = (tid + 256) >> 2,    q1 = (tid + 256) & 3;
    const int nch = K >> 5;

    auto issue = [&](int c, int s) {
        const int kc = c << 5;
        const uint32_t st = sb + s * STAGE_B;
        {
            const uint32_t so = (uint32_t)(r0 * 80 + q0 * 16);
            const size_t ga = (size_t)(brow + r0) * K + kc + q0 * 8;
            const size_t gb = (size_t)(bcol + r0) * K + kc + q0 * 8;
            cpasync16(st + so,              Ah + ga);
            cpasync16(st + TILE_B + so,     Al + ga);
            cpasync16(st + 2*TILE_B + so,   Bh + gb);
            cpasync16(st + 3*TILE_B + so,   Bl + gb);
        }
        {
            const uint32_t so = (uint32_t)(r1 * 80 + q1 * 16);
            const size_t ga = (size_t)(brow + r1) * K + kc + q1 * 8;
            const size_t gb = (size_t)(bcol + r1) * K + kc + q1 * 8;
            cpasync16(st + so,              Ah + ga);
            cpasync16(st + TILE_B + so,     Al + ga);
            cpasync16(st + 2*TILE_B + so,   Bh + gb);
            cpasync16(st + 3*TILE_B + so,   Bl + gb);
        }
        CP_COMMIT();
    };

    issue(0, 0);

    const int a_row = (lane & 15);
    const int a_kof = ((lane >> 4) << 3);
    const int g8    = lane >> 3;
    const int b_nt  = (g8 >> 1) << 3;
    const int b_kof = (g8 & 1) << 3;
    const int b_row = (lane & 7);

    for (int c = 0; c < nch; c++) {
        if (c + 1 < nch) { issue(c + 1, (c + 1) & 1); CP_WAIT(1); }
        else             { CP_WAIT(0); }
        __syncthreads();

        const uint32_t st = sb + (c & 1) * STAGE_B;
        #pragma unroll
        for (int k16 = 0; k16 < 32; k16 += 16) {
            uint32_t aH[4][4], bH[4][2], t[4];
            #pragma unroll
            for (int mt = 0; mt < 4; mt++) {
                uint32_t ad = st + (uint32_t)((wm + mt*16 + a_row) * 80
                                              + (k16 + a_kof) * 2);
                LDSM4(aH[mt], ad);
            }
            #pragma unroll
            for (int p = 0; p < 2; p++) {
                uint32_t ad = st + 2*TILE_B
                    + (uint32_t)((wn + p*16 + b_nt + b_row) * 80
                                 + (k16 + b_kof) * 2);
                LDSM4(t, ad);
                bH[2*p    ][0] = t[0]; bH[2*p    ][1] = t[1];
                bH[2*p + 1][0] = t[2]; bH[2*p + 1][1] = t[3];
            }
            #pragma unroll
            for (int mt = 0; mt < 4; mt++)
                #pragma unroll
                for (int nt = 0; nt < 4; nt++)
                    mma16816(acc[mt][nt], aH[mt], bH[nt]);
            #pragma unroll
            for (int p = 0; p < 2; p++) {
                uint32_t ad = st + 3*TILE_B
                    + (uint32_t)((wn + p*16 + b_nt + b_row) * 80
                                 + (k16 + b_kof) * 2);
                LDSM4(t, ad);
                uint32_t bl0[2] = { t[0], t[1] }, bl1[2] = { t[2], t[3] };
                #pragma unroll
                for (int mt = 0; mt < 4; mt++) {
                    mma16816(acc[mt][2*p    ], aH[mt], bl0);
                    mma16816(acc[mt][2*p + 1], aH[mt], bl1);
                }
            }
            #pragma unroll
            for (int mt = 0; mt < 4; mt++) {
                uint32_t ad = st + TILE_B
                    + (uint32_t)((wm + mt*16 + a_row) * 80
                                 + (k16 + a_kof) * 2);
                LDSM4(t, ad);
                #pragma unroll
                for (int nt = 0; nt < 4; nt++)
                    mma16816(acc[mt][nt], t, bH[nt]);
            }
        }
        __syncthreads();
    }

    const int g  = lane >> 2;
    const int tg = lane & 3;
    #pragma unroll
    for (int mt = 0; mt < 4; mt++) {
        #pragma unroll
        for (int nt = 0; nt < 4; nt++) {
            const int row = brow + wm + mt*16 + g;
            const int col = bcol + wn + nt*8 + tg*2;
            float2 v0, v1;
            v0.x = acc[mt][nt][0]; v0.y = acc[mt][nt][1];
            v1.x = acc[mt][nt][2]; v1.y = acc[mt][nt][3];
            if (bias) {
                float2 bb = *(const float2*)&bias[col];
                v0.x += bb.x; v0.y += bb.y; v1.x += bb.x; v1.y += bb.y;
            }
            if (relu) {
                v0.x = fmaxf(v0.x, 0.f); v0.y = fmaxf(v0.y, 0.f);
                v1.x = fmaxf(v1.x, 0.f); v1.y = fmaxf(v1.y, 0.f);
            }
            const size_t o0 = (size_t)row * ldc + coff + col;
            const size_t o1 = (size_t)(row + 8) * ldc + coff + col;
            if (C) {
                *(float2*)&C[o0] = v0;
                *(float2*)&C[o1] = v1;
            }
            if (Ch) {
                __nv_bfloat162 hh, ll;
                split1(v0.x, hh.x, ll.x); split1(v0.y, hh.y, ll.y);
                *(__nv_bfloat162*)&Ch[o0] = hh;
                *(__nv_bfloat162*)&Cl[o0] = ll;
                split1(v1.x, hh.x, ll.x); split1(v1.y, hh.y, ll.y);
                *(__nv_bfloat162*)&Ch[o1] = hh;
                *(__nv_bfloat162*)&Cl[o1] = ll;
            }
        }
    }
}

// ---------------------------------------------------------------------------
// Fused flash attention (unchanged — occupancy 2, SW128 64-row K/V tiles)
// ---------------------------------------------------------------------------
constexpr int FA_QTB   = 128 * 144;
constexpr int FA_KTB   = 64 * 128;
constexpr int FA_STAGE = 4 * FA_KTB;
constexpr int FA_SMEM  = 2*FA_QTB + 2*FA_STAGE + 4096;

__global__ __launch_bounds__(256, 2) void flash_attn(
    const __nv_bfloat16* __restrict__ Xh, const __nv_bfloat16* __restrict__ Xl,
    const float* __restrict__ mask, const int* __restrict__ pad,
    __nv_bfloat16* __restrict__ Oh, __nv_bfloat16* __restrict__ Ol)
{
    extern __shared__ char sm[];
    const uint32_t sb = smem_u32(sm);
    const int tid  = threadIdx.x;
    const int wid  = tid >> 5;
    const int lane = tid & 31;
    const int qy   = blockIdx.x * 128;
    const int bh   = blockIdx.y;
    const int b    = bh >> 4;
    const int hcol = (bh & 15) * HDc;
    const int wq   = wid * 16;

    const uint32_t sQh    = sb;
    const uint32_t sQl    = sb + FA_QTB;
    const uint32_t sStage = sb + 2*FA_QTB;
    float* spad = (float*)(sm + 2*FA_QTB + 2*FA_STAGE);

    for (int i = tid; i < 1024; i += 256)
        spad[i] = (float)pad[b*Lc + i];

    for (int i = tid; i < 1024; i += 256) {
        const int r = i >> 3, j = i & 7;
        const uint32_t so = (uint32_t)(r * 144 + j * 16);
        const size_t gq = (size_t)(b*Lc + qy + r) * QKVW + hcol + j*8;
        cpasync16(sQh + so, Xh + gq);
        cpasync16(sQl + so, Xl + gq);
    }
    CP_COMMIT();

    auto issueKV = [&](int t, int s) {
        const int kx = t * 64;
        const uint32_t base = sStage + s * FA_STAGE;
        for (int i = tid; i < 512; i += 256) {
            const int r = i >> 3, j = i & 7;
            const uint32_t so = FSW((uint32_t)(r * 128 + j * 16));
            const size_t gk = (size_t)(b*Lc + kx + r) * QKVW + 1024 + hcol + j*8;
            cpasync16(base + so,             Xh + gk);
            cpasync16(base + FA_KTB + so,    Xl + gk);
            cpasync16(base + 2*FA_KTB + so,  Xh + gk + 1024);
            cpasync16(base + 3*FA_KTB + so,  Xl + gk + 1024);
        }
        CP_COMMIT();
    };
    issueKV(0, 0);

    CP_WAIT(1);
    __syncthreads();

    const int a_row = lane & 15;
    const int a_kof = (lane >> 4) << 3;
    uint32_t qh[4][4];
    #pragma unroll
    for (int kt = 0; kt < 4; kt++)
        LDSM4(qh[kt], sQh + (uint32_t)((wq + a_row)*144 + (kt*16 + a_kof)*2));

    float m[2] = { -1e30f, -1e30f };
    float l[2] = { 0.f, 0.f };
    float o[8][4];
    #pragma unroll
    for (int i = 0; i < 8; i++)
        #pragma unroll
        for (int j = 0; j < 4; j++) o[i][j] = 0.f;

    const int g    = lane >> 2;
    const int tg   = lane & 3;
    const int g8   = lane >> 3;
    const int b_nt  = (g8 >> 1) << 3;
    const int b_kof = (g8 & 1) << 3;
    const int b_row = lane & 7;
    const int v_kv = ((lane >> 3) & 1) << 3;
    const int v_d  = (lane >> 4) << 3;

    for (int t = 0; t < 16; t++) {
        const int kx = t * 64;
        if (t + 1 < 16) { issueKV(t + 1, (t + 1) & 1); CP_WAIT(1); }
        else            { CP_WAIT(0); }
        __syncthreads();

        const uint32_t stK  = sStage + (t & 1) * FA_STAGE;
        const uint32_t stKl = stK + FA_KTB;
        const uint32_t stVh = stK + 2*FA_KTB;
        const uint32_t stVl = stK + 3*FA_KTB;

        float sf[8][4];
        #pragma unroll
        for (int i = 0; i < 8; i++)
            #pragma unroll
            for (int j = 0; j < 4; j++) sf[i][j] = 0.f;

        #pragma unroll
        for (int kst = 0; kst < 4; kst++) {
            uint32_t qlf[4];
            LDSM4(qlf, sQl + (uint32_t)((wq + a_row)*144 + (kst*16 + a_kof)*2));
            uint32_t kb[4][4];
            #pragma unroll
            for (int p = 0; p < 4; p++) {
                const uint32_t ad = stK + FSW((uint32_t)((p*16 + b_nt + b_row)*128
                                                          + kst*32 + b_kof*2));
                LDSM4(kb[p], ad);
            }
            #pragma unroll
            for (int p = 0; p < 4; p++) {
                uint32_t b0[2] = { kb[p][0], kb[p][1] };
                uint32_t b1[2] = { kb[p][2], kb[p][3] };
                mma16816(sf[2*p],   qh[kst], b0);
                mma16816(sf[2*p+1], qh[kst], b1);
                mma16816(sf[2*p],   qlf, b0);
                mma16816(sf[2*p+1], qlf, b1);
            }
            #pragma unroll
            for (int p = 0; p < 4; p++) {
                const uint32_t ad = stKl + FSW((uint32_t)((p*16 + b_nt + b_row)*128
                                                           + kst*32 + b_kof*2));
                LDSM4(kb[p], ad);
            }
            #pragma unroll
            for (int p = 0; p < 4; p++) {
                uint32_t b0[2] = { kb[p][0], kb[p][1] };
                uint32_t b1[2] = { kb[p][2], kb[p][3] };
                mma16816(sf[2*p],   qh[kst], b0);
                mma16816(sf[2*p+1], qh[kst], b1);
            }
        }

        const int qg0 = qy + wq + g;
        #pragma unroll
        for (int nt = 0; nt < 8; nt++) {
            const int kvl = nt*8 + tg*2;
            const int kvg = kx + kvl;
            float2 m0 = *(const float2*)&mask[(size_t)qg0 * Lc + kvg];
            float2 m1 = *(const float2*)&mask[(size_t)(qg0 + 8) * Lc + kvg];
            const float p0 = spad[kvg], p1 = spad[kvg + 1];
            sf[nt][0] = sf[nt][0]*0.125f + m0.x + p0;
            sf[nt][1] = sf[nt][1]*0.125f + m0.y + p1;
            sf[nt][2] = sf[nt][2]*0.125f + m1.x + p0;
            sf[nt][3] = sf[nt][3]*0.125f + m1.y + p1;
        }

        float mx0 = m[0], mx1 = m[1];
        #pragma unroll
        for (int nt = 0; nt < 8; nt++) {
            mx0 = fmaxf(mx0, fmaxf(sf[nt][0], sf[nt][1]));
            mx1 = fmaxf(mx1, fmaxf(sf[nt][2], sf[nt][3]));
        }
        mx0 = fmaxf(mx0, __shfl_xor_sync(0xffffffffu, mx0, 1));
        mx0 = fmaxf(mx0, __shfl_xor_sync(0xffffffffu, mx0, 2));
        mx1 = fmaxf(mx1, __shfl_xor_sync(0xffffffffu, mx1, 1));
        mx1 = fmaxf(mx1, __shfl_xor_sync(0xffffffffu, mx1, 2));

        const float al0 = __expf(m[0] - mx0);
        const float al1 = __expf(m[1] - mx1);
        m[0] = mx0; m[1] = mx1;
        #pragma unroll
        for (int nt = 0; nt < 8; nt++) {
            o[nt][0] *= al0; o[nt][1] *= al0;
            o[nt][2] *= al1; o[nt][3] *= al1;
        }

        uint32_t ph[4][4], pl[4][4];
        float s0 = 0.f, s1 = 0.f;
        #pragma unroll
        for (int j = 0; j < 4; j++) {
            float e00 = __expf(sf[2*j][0]   - mx0);
            float e01 = __expf(sf[2*j][1]   - mx0);
            float e10 = __expf(sf[2*j][2]   - mx1);
            float e11 = __expf(sf[2*j][3]   - mx1);
            float e20 = __expf(sf[2*j+1][0] - mx0);
            float e21 = __expf(sf[2*j+1][1] - mx0);
            float e30 = __expf(sf[2*j+1][2] - mx1);
            float e31 = __expf(sf[2*j+1][3] - mx1);
            s0 += e00 + e01 + e20 + e21;
            s1 += e10 + e11 + e30 + e31;
            ph[j][0] = packbf(e00, e01);
            ph[j][1] = packbf(e10, e11);
            ph[j][2] = packbf(e20, e21);
            ph[j][3] = packbf(e30, e31);
            __nv_bfloat162* hp = (__nv_bfloat162*)&ph[j][0];
            pl[j][0] = packbf(e00 - __bfloat162float(hp[0].x),
                              e01 - __bfloat162float(hp[0].y));
            hp = (__nv_bfloat162*)&ph[j][1];
            pl[j][1] = packbf(e10 - __bfloat162float(hp[0].x),
                              e11 - __bfloat162float(hp[0].y));
            hp = (__nv_bfloat162*)&ph[j][2];
            pl[j][2] = packbf(e20 - __bfloat162float(hp[0].x),
                              e21 - __bfloat162float(hp[0].y));
            hp = (__nv_bfloat162*)&ph[j][3];
            pl[j][3] = packbf(e30 - __bfloat162float(hp[0].x),
                              e31 - __bfloat162float(hp[0].y));
        }
        s0 += __shfl_xor_sync(0xffffffffu, s0, 1);
        s0 += __shfl_xor_sync(0xffffffffu, s0, 2);
        s1 += __shfl_xor_sync(0xffffffffu, s1, 1);
        s1 += __shfl_xor_sync(0xffffffffu, s1, 2);
        l[0] = l[0]*al0 + s0;
        l[1] = l[1]*al1 + s1;

        #pragma unroll
        for (int j = 0; j < 4; j++) {
            #pragma unroll
            for (int p = 0; p < 4; p++) {
                uint32_t th[4], tl[4];
                const uint32_t off = FSW((uint32_t)((j*16 + v_kv + b_row)*128
                                                     + p*32 + v_d*2));
                LDSM4T(th, stVh + off);
                LDSM4T(tl, stVl + off);
                uint32_t bh0[2] = { th[0], th[1] }, bh1[2] = { th[2], th[3] };
                uint32_t bl0[2] = { tl[0], tl[1] }, bl1[2] = { tl[2], tl[3] };
                mma16816(o[2*p],   ph[j], bh0);
                mma16816(o[2*p+1], ph[j], bh1);
                mma16816(o[2*p],   ph[j], bl0);
                mma16816(o[2*p+1], ph[j], bl1);
                mma16816(o[2*p],   pl[j], bh0);
                mma16816(o[2*p+1], pl[j], bh1);
            }
        }
        __syncthreads();
    }

    const float inv0 = 1.f / l[0];
    const float inv1 = 1.f / l[1];
    const int row = b*Lc + qy + wq + g;
    #pragma unroll
    for (int nt = 0; nt < 8; nt++) {
        const int col = hcol + nt*8 + tg*2;
        __nv_bfloat162 hh, ll;
        split1(o[nt][0]*inv0, hh.x, ll.x);
        split1(o[nt][1]*inv0, hh.y, ll.y);
        *(__nv_bfloat162*)&Oh[(size_t)row * Dc + col] = hh;
        *(__nv_bfloat162*)&Ol[(size_t)row * Dc + col] = ll;
        split1(o[nt][2]*inv1, hh.x, ll.x);
        split1(o[nt][3]*inv1, hh.y, ll.y);
        *(__nv_bfloat162*)&Oh[(size_t)(row + 8) * Dc + col] = hh;
        *(__nv_bfloat162*)&Ol[(size_t)(row + 8) * Dc + col] = ll;
    }
}

// ---------------------------------------------------------------------------
// small kernels (unchanged)
// ---------------------------------------------------------------------------
__global__ __launch_bounds__(256) void split_f32(
    const float* __restrict__ x, __nv_bfloat16* __restrict__ h,
    __nv_bfloat16* __restrict__ l)
{
    const size_t i = ((size_t)blockIdx.x * 256 + threadIdx.x) * 4;
    float4 v = *(const float4*)(x + i);
    __nv_bfloat162 hh0, hh1, ll0, ll1;
    split1(v.x, hh0.x, ll0.x); split1(v.y, hh0.y, ll0.y);
    split1(v.z, hh1.x, ll1.x); split1(v.w, hh1.y, ll1.y);
    *(__nv_bfloat162*)(h + i)     = hh0;
    *(__nv_bfloat162*)(h + i + 2) = hh1;
    *(__nv_bfloat162*)(l + i)     = ll0;
    *(__nv_bfloat162*)(l + i + 2) = ll1;
}

__global__ __launch_bounds__(256) void transpose_split(
    const float* __restrict__ W, __nv_bfloat16* __restrict__ h,
    __nv_bfloat16* __restrict__ l, int K, int N, size_t ostrideZ)
{
    __shared__ float t[32][33];
    const size_t ibase = (size_t)blockIdx.z * K * N;
    const size_t obase = (size_t)blockIdx.z * ostrideZ;
    const int k0 = blockIdx.y * 32, n0 = blockIdx.x * 32;
    const int tx = threadIdx.x & 31, ty = threadIdx.x >> 5;
    #pragma unroll
    for (int r = 0; r < 32; r += 8)
        t[ty + r][tx] = W[ibase + (size_t)(k0 + ty + r) * N + n0 + tx];
    __syncthreads();
    #pragma unroll
    for (int r = 0; r < 32; r += 8) {
        const float v = t[tx][ty + r];
        const size_t o = obase + (size_t)(n0 + ty + r) * K + k0 + tx;
        __nv_bfloat16 hh, ll;
        split1(v, hh, ll);
        h[o] = hh; l[o] = ll;
    }
}

__global__ void bias_cat(const float* __restrict__ bq, const float* __restrict__ bk,
                         const float* __restrict__ bv, float* __restrict__ o)
{
    const int i = blockIdx.x, seg = blockIdx.y, j = threadIdx.x;
    const float* src = (seg == 0) ? bq : (seg == 1) ? bk : bv;
    o[i*QKVW + seg*1024 + j] = src[i*1024 + j];
}

__global__ __launch_bounds__(256) void add_ln(
    const float* __restrict__ x, const float* __restrict__ res,
    const float* __restrict__ g, const float* __restrict__ bta,
    float* __restrict__ y, __nv_bfloat16* __restrict__ yh,
    __nv_bfloat16* __restrict__ yl)
{
    __shared__ float rs[8], rq[8];
    const int tid = threadIdx.x;
    const size_t base = (size_t)blockIdx.x * 1024 + tid * 4;

    float4 a = *(const float4*)&x[base];
    float4 r = *(const float4*)&res[base];
    a.x += r.x; a.y += r.y; a.z += r.z; a.w += r.w;

    float s = a.x + a.y + a.z + a.w;
    float q = a.x*a.x + a.y*a.y + a.z*a.z + a.w*a.w;
    #pragma unroll
    for (int o = 16; o > 0; o >>= 1) {
        s += __shfl_xor_sync(0xffffffffu, s, o);
        q += __shfl_xor_sync(0xffffffffu, q, o);
    }
    if ((tid & 31) == 0) { rs[tid >> 5] = s; rq[tid >> 5] = q; }
    __syncthreads();
    s = 0.f; q = 0.f;
    #pragma unroll
    for (int i = 0; i < 8; i++) { s += rs[i]; q += rq[i]; }

    const float mean = s * (1.f / 1024.f);
    const float var  = q * (1.f / 1024.f) - mean * mean;
    const float rstd = rsqrtf(var + 1e-5f);

    const int c = tid * 4;
    float4 gv = *(const float4*)&g[c];
    float4 bv = *(const float4*)&bta[c];
    float4 o;
    o.x = (a.x - mean) * rstd * gv.x + bv.x;
    o.y = (a.y - mean) * rstd * gv.y + bv.y;
    o.z = (a.z - mean) * rstd * gv.z + bv.z;
    o.w = (a.w - mean) * rstd * gv.w + bv.w;
    if (y) *(float4*)&y[base] = o;

    __nv_bfloat162 hh0, hh1, ll0, ll1;
    split1(o.x, hh0.x, ll0.x); split1(o.y, hh0.y, ll0.y);
    split1(o.z, hh1.x, ll1.x); split1(o.w, hh1.y, ll1.y);
    *(__nv_bfloat162*)&yh[base]     = hh0;
    *(__nv_bfloat162*)&yh[base + 2] = hh1;
    *(__nv_bfloat162*)&yl[base]     = ll0;
    *(__nv_bfloat162*)&yl[base + 2] = ll1;
}

// ---------------------------------------------------------------------------
// Launch orchestration — restructured DAG:
//   * phase-3 Q-projection hoisted into phase 2 (into QKV1)
//   * FFN-T overlapped with the entire phase-3 chain + FFN-A
// ---------------------------------------------------------------------------
extern "C" void kernel_launch(void* const* d_in, const int* in_sizes, int n_in,
                              void* d_out, int out_size)
{
    const float* T    = (const float*)d_in[0];
    const float* A    = (const float*)d_in[1];
    const float* mask = (const float*)d_in[2];
    const int*   pad  = (const int*)  d_in[3];
    const float* Wq   = (const float*)d_in[4];
    const float* bq   = (const float*)d_in[5];
    const float* Wk   = (const float*)d_in[6];
    const float* bk   = (const float*)d_in[7];
    const float* Wv   = (const float*)d_in[8];
    const float* bv   = (const float*)d_in[9];
    const float* Wo   = (const float*)d_in[10];
    const float* ffW1 = (const float*)d_in[11];
    const float* ffb1 = (const float*)d_in[12];
    const float* ffW2 = (const float*)d_in[13];
    const float* ffb2 = (const float*)d_in[14];
    const float* lng  = (const float*)d_in[15];
    const float* lnb  = (const float*)d_in[16];
    float* out = (float*)d_out;

    static cudaStream_t sA = nullptr, sB = nullptr;
    static cudaEvent_t  eF = nullptr, eA = nullptr, eB = nullptr;
    if (!sA) {
        cudaStreamCreateWithFlags(&sA, cudaStreamNonBlocking);
        cudaStreamCreateWithFlags(&sB, cudaStreamNonBlocking);
        cudaEventCreateWithFlags(&eF, cudaEventDisableTiming);
        cudaEventCreateWithFlags(&eA, cudaEventDisableTiming);
        cudaEventCreateWithFlags(&eB, cudaEventDisableTiming);
    }
    auto fork = [&]() {
        cudaEventRecord(eF, 0);
        cudaStreamWaitEvent(sA, eF, 0);
        cudaStreamWaitEvent(sB, eF, 0);
    };
    auto join = [&]() {
        cudaEventRecord(eA, sA);
        cudaEventRecord(eB, sB);
        cudaStreamWaitEvent(0, eA, 0);
        cudaStreamWaitEvent(0, eB, 0);
    };

    float *Mo0, *Mo1, *T1f, *A1f;
    cudaGetSymbolAddress((void**)&Mo0, g_Mo0);
    cudaGetSymbolAddress((void**)&Mo1, g_Mo1);
    cudaGetSymbolAddress((void**)&T1f, g_T1f);
    cudaGetSymbolAddress((void**)&A1f, g_A1f);

    __nv_bfloat16 *iTh,*iTl,*iAh,*iAl,*T1h,*T1l,*A1h,*A1l,*T2h,*T2l,*A2h,*A2l;
    __nv_bfloat16 *QKV0h,*QKV0l,*QKV1h,*QKV1l,*O0h,*O0l,*O1h,*O1l;
    __nv_bfloat16 *H0h,*H0l,*H1h,*H1l;
    __nv_bfloat16 *wch,*wcl,*woh,*wol,*w1h,*w1l,*w2h,*w2l;
    float* bcat;
    cudaGetSymbolAddress((void**)&iTh, g_iTh); cudaGetSymbolAddress((void**)&iTl, g_iTl);
    cudaGetSymbolAddress((void**)&iAh, g_iAh); cudaGetSymbolAddress((void**)&iAl, g_iAl);
    cudaGetSymbolAddress((void**)&T1h, g_T1h); cudaGetSymbolAddress((void**)&T1l, g_T1l);
    cudaGetSymbolAddress((void**)&A1h, g_A1h); cudaGetSymbolAddress((void**)&A1l, g_A1l);
    cudaGetSymbolAddress((void**)&T2h, g_T2h); cudaGetSymbolAddress((void**)&T2l, g_T2l);
    cudaGetSymbolAddress((void**)&A2h, g_A2h); cudaGetSymbolAddress((void**)&A2l, g_A2l);
    cudaGetSymbolAddress((void**)&QKV0h, g_QKV0h); cudaGetSymbolAddress((void**)&QKV0l, g_QKV0l);
    cudaGetSymbolAddress((void**)&QKV1h, g_QKV1h); cudaGetSymbolAddress((void**)&QKV1l, g_QKV1l);
    cudaGetSymbolAddress((void**)&O0h, g_O0h); cudaGetSymbolAddress((void**)&O0l, g_O0l);
    cudaGetSymbolAddress((void**)&O1h, g_O1h); cudaGetSymbolAddress((void**)&O1l, g_O1l);
    cudaGetSymbolAddress((void**)&H0h, g_H0h); cudaGetSymbolAddress((void**)&H0l, g_H0l);
    cudaGetSymbolAddress((void**)&H1h, g_H1h); cudaGetSymbolAddress((void**)&H1l, g_H1l);
    cudaGetSymbolAddress((void**)&wch, g_wch); cudaGetSymbolAddress((void**)&wcl, g_wcl);
    cudaGetSymbolAddress((void**)&woh, g_woh); cudaGetSymbolAddress((void**)&wol, g_wol);
    cudaGetSymbolAddress((void**)&w1h, g_w1h); cudaGetSymbolAddress((void**)&w1l, g_w1l);
    cudaGetSymbolAddress((void**)&w2h, g_w2h); cudaGetSymbolAddress((void**)&w2l, g_w2l);
    cudaGetSymbolAddress((void**)&bcat, g_bcat);

    cudaFuncSetAttribute(gemm_mma,   cudaFuncAttributeMaxDynamicSharedMemorySize, GEMM_SMEM);
    cudaFuncSetAttribute(flash_attn, cudaFuncAttributeMaxDynamicSharedMemorySize, FA_SMEM);

    const size_t DD = (size_t)Dc * Dc;
    const size_t WCZ = (size_t)QKVW * Dc;

    auto gemm = [&](cudaStream_t st,
                    const __nv_bfloat16* ah, const __nv_bfloat16* al,
                    const __nv_bfloat16* bh, const __nv_bfloat16* bl,
                    const float* bias, float* c, __nv_bfloat16* ch, __nv_bfloat16* cl,
                    int M, int N, int K, int ldc, int coff, int relu) {
        gemm_mma<<<dim3(N/128, M/128), 256, GEMM_SMEM, st>>>(
            ah, al, bh, bl, bias, c, ch, cl, M, N, K, ldc, coff, relu);
    };

    // ---------------- Phase 0: weight prep + input splits ----------------
    fork();
    transpose_split<<<dim3(32,32,4), 256, 0, sA>>>(Wq, wch,        wcl,        Dc, Dc, WCZ);
    transpose_split<<<dim3(32,32,4), 256, 0, sA>>>(Wk, wch + DD,   wcl + DD,   Dc, Dc, WCZ);
    transpose_split<<<dim3(32,32,4), 256, 0, sA>>>(Wv, wch + 2*DD, wcl + 2*DD, Dc, Dc, WCZ);
    bias_cat<<<dim3(4,3), 1024, 0, sA>>>(bq, bk, bv, bcat);
    split_f32<<<BLc, 256, 0, sA>>>(T, iTh, iTl);
    transpose_split<<<dim3(32,32,4),  256, 0, sB>>>(Wo,   woh, wol, Dc, Dc, DD);
    transpose_split<<<dim3(128,32,2), 256, 0, sB>>>(ffW1, w1h, w1l, Dc, Fc, (size_t)Dc*Fc);
    transpose_split<<<dim3(32,128,2), 256, 0, sB>>>(ffW2, w2h, w2l, Fc, Dc, (size_t)Fc*Dc);
    split_f32<<<BLc, 256, 0, sB>>>(A, iAh, iAl);
    join();

    // ---------------- Phase 1: mha0 (T, sA) || mha1 (A, sB) ----------------
    fork();
    gemm(sA, iTh, iTl, wch, wcl, bcat, nullptr, QKV0h, QKV0l,
         BLc, QKVW, Dc, QKVW, 0, 0);
    flash_attn<<<dim3(Lc/128, 64), 256, FA_SMEM, sA>>>(QKV0h, QKV0l, mask, pad, O0h, O0l);
    gemm(sA, O0h, O0l, woh, wol, nullptr, Mo0, nullptr, nullptr,
         BLc, Dc, Dc, Dc, 0, 0);
    add_ln<<<BLc, 256, 0, sA>>>(T, Mo0, lng, lnb, T1f, T1h, T1l);
    gemm(sB, iAh, iAl, wch + WCZ, wcl + WCZ, bcat + QKVW, nullptr, QKV1h, QKV1l,
         BLc, QKVW, Dc, QKVW, 0, 0);
    flash_attn<<<dim3(Lc/128, 64), 256, FA_SMEM, sB>>>(QKV1h, QKV1l, mask, pad, O1h, O1l);
    gemm(sB, O1h, O1l, woh + DD, wol + DD, nullptr, Mo1, nullptr, nullptr,
         BLc, Dc, Dc, Dc, 0, 0);
    add_ln<<<BLc, 256, 0, sB>>>(A, Mo1, lng + Dc, lnb + Dc, A1f, A1h, A1l);
    join();

    // ------- Phase 2: mha2 projections + EARLY mha3 Q-projection -------
    // sA: KV2 (A1 -> QKV0 cols 1024..3071)
    // sB: Q2 (T1 -> QKV0 cols 0..1023), then Q3 (A1 -> QKV1 cols 0..1023)
    fork();
    gemm(sA, A1h, A1l, wch + 2*WCZ + DD, wcl + 2*WCZ + DD, bcat + 2*QKVW + 1024,
         nullptr, QKV0h, QKV0l, BLc, 2*Dc, Dc, QKVW, 1024, 0);
    gemm(sB, T1h, T1l, wch + 2*WCZ, wcl + 2*WCZ, bcat + 2*QKVW,
         nullptr, QKV0h, QKV0l, BLc, Dc, Dc, QKVW, 0, 0);
    gemm(sB, A1h, A1l, wch + 3*WCZ, wcl + 3*WCZ, bcat + 3*QKVW,
         nullptr, QKV1h, QKV1l, BLc, Dc, Dc, QKVW, 0, 0);
    join();

    // mha2 tail (default stream): flash2 -> Wo2 -> LN2 (-> T2 split)
    flash_attn<<<dim3(Lc/128, 64), 256, FA_SMEM>>>(QKV0h, QKV0l, mask, pad, O0h, O0l);
    gemm(0, O0h, O0l, woh + 2*DD, wol + 2*DD, nullptr, Mo0, nullptr, nullptr,
         BLc, Dc, Dc, Dc, 0, 0);
    add_ln<<<BLc, 256>>>(T1f, Mo0, lng + 2*Dc, lnb + 2*Dc, nullptr, T2h, T2l);

    // ------- Phase 3: mha3 chain + FFN-A (sA)  ||  FFN-T (sB) -------
    fork();
    // sA: KV3 (T2 -> QKV1 cols 1024..3071) -> flash3 -> Wo3 -> LN3 -> FFN-A
    gemm(sA, T2h, T2l, wch + 3*WCZ + DD, wcl + 3*WCZ + DD, bcat + 3*QKVW + 1024,
         nullptr, QKV1h, QKV1l, BLc, 2*Dc, Dc, QKVW, 1024, 0);
    flash_attn<<<dim3(Lc/128, 64), 256, FA_SMEM, sA>>>(QKV1h, QKV1l, mask, pad, O0h, O0l);
    gemm(sA, O0h, O0l, woh + 3*DD, wol + 3*DD, nullptr, Mo0, nullptr, nullptr,
         BLc, Dc, Dc, Dc, 0, 0);
    add_ln<<<BLc, 256, 0, sA>>>(A1f, Mo0, lng + 3*Dc, lnb + 3*Dc, nullptr, A2h, A2l);
    gemm(sA, A2h, A2l, w1h + (size_t)Dc*Fc, w1l + (size_t)Dc*Fc, ffb1 + Fc,
         nullptr, H1h, H1l, BLc, Fc, Dc, Fc, 0, 1);
    gemm(sA, H1h, H1l, w2h + (size_t)Fc*Dc, w2l + (size_t)Fc*Dc, ffb2 + Dc,
         out + (size_t)BLc*Dc, nullptr, nullptr, BLc, Dc, Fc, Dc, 0, 0);
    // sB: FFN-T (T2 ready) — overlaps the whole sA chain
    gemm(sB, T2h, T2l, w1h, w1l, ffb1, nullptr, H0h, H0l, BLc, Fc, Dc, Fc, 0, 1);
    gemm(sB, H0h, H0l, w2h, w2l, ffb2, out, nullptr, nullptr, BLc, Dc, Fc, Dc, 0, 0);
    join();
}

// round 9
// speedup vs baseline: 3.4687x; 1.0067x over previous
#include <cuda_runtime.h>
#include <cuda_bf16.h>
#include <math.h>
#include <stdint.h>

// Problem constants
constexpr int Bc  = 4;
constexpr int Lc  = 1024;
constexpr int Dc  = 1024;
constexpr int Fc  = 4096;
constexpr int HDc = 64;
constexpr int BLc = Bc * Lc;          // 4096 rows
constexpr int QKVW = 3 * Dc;          // 3072 concat width

// ---------------------------------------------------------------------------
// Scratch (static __device__ arrays — allocation-free per harness rules)
// ---------------------------------------------------------------------------
__device__ float g_Mo0[BLc * Dc];
__device__ float g_Mo1[BLc * Dc];
__device__ float g_T1f[BLc * Dc];
__device__ float g_A1f[BLc * Dc];

__device__ __nv_bfloat16 g_iTh[BLc*Dc], g_iTl[BLc*Dc];
__device__ __nv_bfloat16 g_iAh[BLc*Dc], g_iAl[BLc*Dc];
__device__ __nv_bfloat16 g_T1h[BLc*Dc], g_T1l[BLc*Dc];
__device__ __nv_bfloat16 g_A1h[BLc*Dc], g_A1l[BLc*Dc];
__device__ __nv_bfloat16 g_T2h[BLc*Dc], g_T2l[BLc*Dc];
__device__ __nv_bfloat16 g_A2h[BLc*Dc], g_A2l[BLc*Dc];
__device__ __nv_bfloat16 g_QKV0h[(size_t)BLc*QKVW], g_QKV0l[(size_t)BLc*QKVW];
__device__ __nv_bfloat16 g_QKV1h[(size_t)BLc*QKVW], g_QKV1l[(size_t)BLc*QKVW];
__device__ __nv_bfloat16 g_O0h[BLc*Dc], g_O0l[BLc*Dc];
__device__ __nv_bfloat16 g_O1h[BLc*Dc], g_O1l[BLc*Dc];
__device__ __nv_bfloat16 g_H0h[(size_t)BLc*Fc], g_H0l[(size_t)BLc*Fc];
__device__ __nv_bfloat16 g_H1h[(size_t)BLc*Fc], g_H1l[(size_t)BLc*Fc];

// weights: concat QKV^T [4][3072,1024]; others [N,K]
__device__ __nv_bfloat16 g_wch[(size_t)4*QKVW*Dc], g_wcl[(size_t)4*QKVW*Dc];
__device__ __nv_bfloat16 g_woh[4*Dc*Dc], g_wol[4*Dc*Dc];
__device__ __nv_bfloat16 g_w1h[2*Dc*Fc], g_w1l[2*Dc*Fc];
__device__ __nv_bfloat16 g_w2h[2*Fc*Dc], g_w2l[2*Fc*Dc];
__device__ float g_bcat[4*QKVW];

// ---------------------------------------------------------------------------
// PTX helpers (sm_103 baseline-safe)
// ---------------------------------------------------------------------------
__device__ __forceinline__ uint32_t smem_u32(const void* p) {
    uint32_t a;
    asm("{ .reg .u64 t; cvta.to.shared.u64 t, %1; cvt.u32.u64 %0, t; }" : "=r"(a) : "l"(p));
    return a;
}
__device__ __forceinline__ void cpasync16(uint32_t dst, const void* src) {
    asm volatile("cp.async.cg.shared.global [%0], [%1], 16;" :: "r"(dst), "l"(src));
}
#define CP_COMMIT()  asm volatile("cp.async.commit_group;" ::: "memory")
#define CP_WAIT(n)   asm volatile("cp.async.wait_group %0;" :: "n"(n) : "memory")

#define LDSM4(r, a) \
    asm volatile("ldmatrix.sync.aligned.m8n8.x4.shared.b16 {%0,%1,%2,%3}, [%4];" \
        : "=r"((r)[0]), "=r"((r)[1]), "=r"((r)[2]), "=r"((r)[3]) : "r"(a))
#define LDSM4T(r, a) \
    asm volatile("ldmatrix.sync.aligned.m8n8.x4.trans.shared.b16 {%0,%1,%2,%3}, [%4];" \
        : "=r"((r)[0]), "=r"((r)[1]), "=r"((r)[2]), "=r"((r)[3]) : "r"(a))

__device__ __forceinline__ void mma16816(float* c, const uint32_t* a, const uint32_t* b) {
    asm volatile(
        "mma.sync.aligned.m16n8k16.row.col.f32.bf16.bf16.f32 "
        "{%0,%1,%2,%3}, {%4,%5,%6,%7}, {%8,%9}, {%0,%1,%2,%3};"
        : "+f"(c[0]), "+f"(c[1]), "+f"(c[2]), "+f"(c[3])
        : "r"(a[0]), "r"(a[1]), "r"(a[2]), "r"(a[3]), "r"(b[0]), "r"(b[1]));
}

__device__ __forceinline__ void split1(float v, __nv_bfloat16& h, __nv_bfloat16& l) {
    h = __float2bfloat16(v);
    l = __float2bfloat16(v - __bfloat162float(h));
}
__device__ __forceinline__ uint32_t packbf(float a, float b) {
    __nv_bfloat162 t; t.x = __float2bfloat16(a); t.y = __float2bfloat16(b);
    return *(uint32_t*)&t;
}
#define FSW(o) ((o) ^ (((o) >> 3) & 0x70))     // SW128 swizzle for 128B rows

// ---------------------------------------------------------------------------
// Tensor-core GEMM (unchanged — passing)
// ---------------------------------------------------------------------------
constexpr int GSTR    = 40;
constexpr int TILE_B  = 128 * GSTR * 2;
constexpr int STAGE_B = 4 * TILE_B;
constexpr int GEMM_SMEM = 2 * STAGE_B;

__global__ __launch_bounds__(256, 2) void gemm_mma(
    const __nv_bfloat16* __restrict__ Ah, const __nv_bfloat16* __restrict__ Al,
    const __nv_bfloat16* __restrict__ Bh, const __nv_bfloat16* __restrict__ Bl,
    const float* __restrict__ bias, float* __restrict__ C,
    __nv_bfloat16* __restrict__ Ch, __nv_bfloat16* __restrict__ Cl,
    int M, int N, int K, int ldc, int coff, int relu)
{
    extern __shared__ char sm[];
    const uint32_t sb = smem_u32(sm);
    const int tid  = threadIdx.x;
    const int wid  = tid >> 5;
    const int lane = tid & 31;
    const int brow = blockIdx.y * 128;
    const int bcol = blockIdx.x * 128;
    const int wm   = (wid & 1) * 64;
    const int wn   = (wid >> 1) * 32;

    float acc[4][4][4];
    #pragma unroll
    for (int i = 0; i < 4; i++)
        #pragma unroll
        for (int j = 0; j < 4; j++)
            #pragma unroll
            for (int k = 0; k < 4; k++) acc[i][j][k] = 0.f;

    const int r0 = tid >> 2,            q0 = tid & 3;
    const int r1 = (tid + 256) >> 2,    q1 = (tid + 256) & 3;
    const int nch = K >> 5;

    auto issue = [&](int c, int s) {
        const int kc = c << 5;
        const uint32_t st = sb + s * STAGE_B;
        {
            const uint32_t so = (uint32_t)(r0 * 80 + q0 * 16);
            const size_t ga = (size_t)(brow + r0) * K + kc + q0 * 8;
            const size_t gb = (size_t)(bcol + r0) * K + kc + q0 * 8;
            cpasync16(st + so,              Ah + ga);
            cpasync16(st + TILE_B + so,     Al + ga);
            cpasync16(st + 2*TILE_B + so,   Bh + gb);
            cpasync16(st + 3*TILE_B + so,   Bl + gb);
        }
        {
            const uint32_t so = (uint32_t)(r1 * 80 + q1 * 16);
            const size_t ga = (size_t)(brow + r1) * K + kc + q1 * 8;
            const size_t gb = (size_t)(bcol + r1) * K + kc + q1 * 8;
            cpasync16(st + so,              Ah + ga);
            cpasync16(st + TILE_B + so,     Al + ga);
            cpasync16(st + 2*TILE_B + so,   Bh + gb);
            cpasync16(st + 3*TILE_B + so,   Bl + gb);
        }
        CP_COMMIT();
    };

    issue(0, 0);

    const int a_row = (lane & 15);
    const int a_kof = ((lane >> 4) << 3);
    const int g8    = lane >> 3;
    const int b_nt  = (g8 >> 1) << 3;
    const int b_kof = (g8 & 1) << 3;
    const int b_row = (lane & 7);

    for (int c = 0; c < nch; c++) {
        if (c + 1 < nch) { issue(c + 1, (c + 1) & 1); CP_WAIT(1); }
        else             { CP_WAIT(0); }
        __syncthreads();

        const uint32_t st = sb + (c & 1) * STAGE_B;
        #pragma unroll
        for (int k16 = 0; k16 < 32; k16 += 16) {
            uint32_t aH[4][4], bH[4][2], t[4];
            #pragma unroll
            for (int mt = 0; mt < 4; mt++) {
                uint32_t ad = st + (uint32_t)((wm + mt*16 + a_row) * 80
                                              + (k16 + a_kof) * 2);
                LDSM4(aH[mt], ad);
            }
            #pragma unroll
            for (int p = 0; p < 2; p++) {
                uint32_t ad = st + 2*TILE_B
                    + (uint32_t)((wn + p*16 + b_nt + b_row) * 80
                                 + (k16 + b_kof) * 2);
                LDSM4(t, ad);
                bH[2*p    ][0] = t[0]; bH[2*p    ][1] = t[1];
                bH[2*p + 1][0] = t[2]; bH[2*p + 1][1] = t[3];
            }
            #pragma unroll
            for (int mt = 0; mt < 4; mt++)
                #pragma unroll
                for (int nt = 0; nt < 4; nt++)
                    mma16816(acc[mt][nt], aH[mt], bH[nt]);
            #pragma unroll
            for (int p = 0; p < 2; p++) {
                uint32_t ad = st + 3*TILE_B
                    + (uint32_t)((wn + p*16 + b_nt + b_row) * 80
                                 + (k16 + b_kof) * 2);
                LDSM4(t, ad);
                uint32_t bl0[2] = { t[0], t[1] }, bl1[2] = { t[2], t[3] };
                #pragma unroll
                for (int mt = 0; mt < 4; mt++) {
                    mma16816(acc[mt][2*p    ], aH[mt], bl0);
                    mma16816(acc[mt][2*p + 1], aH[mt], bl1);
                }
            }
            #pragma unroll
            for (int mt = 0; mt < 4; mt++) {
                uint32_t ad = st + TILE_B
                    + (uint32_t)((wm + mt*16 + a_row) * 80
                                 + (k16 + a_kof) * 2);
                LDSM4(t, ad);
                #pragma unroll
                for (int nt = 0; nt < 4; nt++)
                    mma16816(acc[mt][nt], t, bH[nt]);
            }
        }
        __syncthreads();
    }

    const int g  = lane >> 2;
    const int tg = lane & 3;
    #pragma unroll
    for (int mt = 0; mt < 4; mt++) {
        #pragma unroll
        for (int nt = 0; nt < 4; nt++) {
            const int row = brow + wm + mt*16 + g;
            const int col = bcol + wn + nt*8 + tg*2;
            float2 v0, v1;
            v0.x = acc[mt][nt][0]; v0.y = acc[mt][nt][1];
            v1.x = acc[mt][nt][2]; v1.y = acc[mt][nt][3];
            if (bias) {
                float2 bb = *(const float2*)&bias[col];
                v0.x += bb.x; v0.y += bb.y; v1.x += bb.x; v1.y += bb.y;
            }
            if (relu) {
                v0.x = fmaxf(v0.x, 0.f); v0.y = fmaxf(v0.y, 0.f);
                v1.x = fmaxf(v1.x, 0.f); v1.y = fmaxf(v1.y, 0.f);
            }
            const size_t o0 = (size_t)row * ldc + coff + col;
            const size_t o1 = (size_t)(row + 8) * ldc + coff + col;
            if (C) {
                *(float2*)&C[o0] = v0;
                *(float2*)&C[o1] = v1;
            }
            if (Ch) {
                __nv_bfloat162 hh, ll;
                split1(v0.x, hh.x, ll.x); split1(v0.y, hh.y, ll.y);
                *(__nv_bfloat162*)&Ch[o0] = hh;
                *(__nv_bfloat162*)&Cl[o0] = ll;
                split1(v1.x, hh.x, ll.x); split1(v1.y, hh.y, ll.y);
                *(__nv_bfloat162*)&Ch[o1] = hh;
                *(__nv_bfloat162*)&Cl[o1] = ll;
            }
        }
    }
}

// ---------------------------------------------------------------------------
// Fused flash attention (unchanged — occupancy 2, SW128 64-row K/V tiles)
// ---------------------------------------------------------------------------
constexpr int FA_QTB   = 128 * 144;
constexpr int FA_KTB   = 64 * 128;
constexpr int FA_STAGE = 4 * FA_KTB;
constexpr int FA_SMEM  = 2*FA_QTB + 2*FA_STAGE + 4096;

__global__ __launch_bounds__(256, 2) void flash_attn(
    const __nv_bfloat16* __restrict__ Xh, const __nv_bfloat16* __restrict__ Xl,
    const float* __restrict__ mask, const int* __restrict__ pad,
    __nv_bfloat16* __restrict__ Oh, __nv_bfloat16* __restrict__ Ol)
{
    extern __shared__ char sm[];
    const uint32_t sb = smem_u32(sm);
    const int tid  = threadIdx.x;
    const int wid  = tid >> 5;
    const int lane = tid & 31;
    const int qy   = blockIdx.x * 128;
    const int bh   = blockIdx.y;
    const int b    = bh >> 4;
    const int hcol = (bh & 15) * HDc;
    const int wq   = wid * 16;

    const uint32_t sQh    = sb;
    const uint32_t sQl    = sb + FA_QTB;
    const uint32_t sStage = sb + 2*FA_QTB;
    float* spad = (float*)(sm + 2*FA_QTB + 2*FA_STAGE);

    for (int i = tid; i < 1024; i += 256)
        spad[i] = (float)pad[b*Lc + i];

    for (int i = tid; i < 1024; i += 256) {
        const int r = i >> 3, j = i & 7;
        const uint32_t so = (uint32_t)(r * 144 + j * 16);
        const size_t gq = (size_t)(b*Lc + qy + r) * QKVW + hcol + j*8;
        cpasync16(sQh + so, Xh + gq);
        cpasync16(sQl + so, Xl + gq);
    }
    CP_COMMIT();

    auto issueKV = [&](int t, int s) {
        const int kx = t * 64;
        const uint32_t base = sStage + s * FA_STAGE;
        for (int i = tid; i < 512; i += 256) {
            const int r = i >> 3, j = i & 7;
            const uint32_t so = FSW((uint32_t)(r * 128 + j * 16));
            const size_t gk = (size_t)(b*Lc + kx + r) * QKVW + 1024 + hcol + j*8;
            cpasync16(base + so,             Xh + gk);
            cpasync16(base + FA_KTB + so,    Xl + gk);
            cpasync16(base + 2*FA_KTB + so,  Xh + gk + 1024);
            cpasync16(base + 3*FA_KTB + so,  Xl + gk + 1024);
        }
        CP_COMMIT();
    };
    issueKV(0, 0);

    CP_WAIT(1);
    __syncthreads();

    const int a_row = lane & 15;
    const int a_kof = (lane >> 4) << 3;
    uint32_t qh[4][4];
    #pragma unroll
    for (int kt = 0; kt < 4; kt++)
        LDSM4(qh[kt], sQh + (uint32_t)((wq + a_row)*144 + (kt*16 + a_kof)*2));

    float m[2] = { -1e30f, -1e30f };
    float l[2] = { 0.f, 0.f };
    float o[8][4];
    #pragma unroll
    for (int i = 0; i < 8; i++)
        #pragma unroll
        for (int j = 0; j < 4; j++) o[i][j] = 0.f;

    const int g    = lane >> 2;
    const int tg   = lane & 3;
    const int g8   = lane >> 3;
    const int b_nt  = (g8 >> 1) << 3;
    const int b_kof = (g8 & 1) << 3;
    const int b_row = lane & 7;
    const int v_kv = ((lane >> 3) & 1) << 3;
    const int v_d  = (lane >> 4) << 3;

    for (int t = 0; t < 16; t++) {
        const int kx = t * 64;
        if (t + 1 < 16) { issueKV(t + 1, (t + 1) & 1); CP_WAIT(1); }
        else            { CP_WAIT(0); }
        __syncthreads();

        const uint32_t stK  = sStage + (t & 1) * FA_STAGE;
        const uint32_t stKl = stK + FA_KTB;
        const uint32_t stVh = stK + 2*FA_KTB;
        const uint32_t stVl = stK + 3*FA_KTB;

        float sf[8][4];
        #pragma unroll
        for (int i = 0; i < 8; i++)
            #pragma unroll
            for (int j = 0; j < 4; j++) sf[i][j] = 0.f;

        #pragma unroll
        for (int kst = 0; kst < 4; kst++) {
            uint32_t qlf[4];
            LDSM4(qlf, sQl + (uint32_t)((wq + a_row)*144 + (kst*16 + a_kof)*2));
            uint32_t kb[4][4];
            #pragma unroll
            for (int p = 0; p < 4; p++) {
                const uint32_t ad = stK + FSW((uint32_t)((p*16 + b_nt + b_row)*128
                                                          + kst*32 + b_kof*2));
                LDSM4(kb[p], ad);
            }
            #pragma unroll
            for (int p = 0; p < 4; p++) {
                uint32_t b0[2] = { kb[p][0], kb[p][1] };
                uint32_t b1[2] = { kb[p][2], kb[p][3] };
                mma16816(sf[2*p],   qh[kst], b0);
                mma16816(sf[2*p+1], qh[kst], b1);
                mma16816(sf[2*p],   qlf, b0);
                mma16816(sf[2*p+1], qlf, b1);
            }
            #pragma unroll
            for (int p = 0; p < 4; p++) {
                const uint32_t ad = stKl + FSW((uint32_t)((p*16 + b_nt + b_row)*128
                                                           + kst*32 + b_kof*2));
                LDSM4(kb[p], ad);
            }
            #pragma unroll
            for (int p = 0; p < 4; p++) {
                uint32_t b0[2] = { kb[p][0], kb[p][1] };
                uint32_t b1[2] = { kb[p][2], kb[p][3] };
                mma16816(sf[2*p],   qh[kst], b0);
                mma16816(sf[2*p+1], qh[kst], b1);
            }
        }

        const int qg0 = qy + wq + g;
        #pragma unroll
        for (int nt = 0; nt < 8; nt++) {
            const int kvl = nt*8 + tg*2;
            const int kvg = kx + kvl;
            float2 m0 = *(const float2*)&mask[(size_t)qg0 * Lc + kvg];
            float2 m1 = *(const float2*)&mask[(size_t)(qg0 + 8) * Lc + kvg];
            const float p0 = spad[kvg], p1 = spad[kvg + 1];
            sf[nt][0] = sf[nt][0]*0.125f + m0.x + p0;
            sf[nt][1] = sf[nt][1]*0.125f + m0.y + p1;
            sf[nt][2] = sf[nt][2]*0.125f + m1.x + p0;
            sf[nt][3] = sf[nt][3]*0.125f + m1.y + p1;
        }

        float mx0 = m[0], mx1 = m[1];
        #pragma unroll
        for (int nt = 0; nt < 8; nt++) {
            mx0 = fmaxf(mx0, fmaxf(sf[nt][0], sf[nt][1]));
            mx1 = fmaxf(mx1, fmaxf(sf[nt][2], sf[nt][3]));
        }
        mx0 = fmaxf(mx0, __shfl_xor_sync(0xffffffffu, mx0, 1));
        mx0 = fmaxf(mx0, __shfl_xor_sync(0xffffffffu, mx0, 2));
        mx1 = fmaxf(mx1, __shfl_xor_sync(0xffffffffu, mx1, 1));
        mx1 = fmaxf(mx1, __shfl_xor_sync(0xffffffffu, mx1, 2));

        const float al0 = __expf(m[0] - mx0);
        const float al1 = __expf(m[1] - mx1);
        m[0] = mx0; m[1] = mx1;
        #pragma unroll
        for (int nt = 0; nt < 8; nt++) {
            o[nt][0] *= al0; o[nt][1] *= al0;
            o[nt][2] *= al1; o[nt][3] *= al1;
        }

        uint32_t ph[4][4], pl[4][4];
        float s0 = 0.f, s1 = 0.f;
        #pragma unroll
        for (int j = 0; j < 4; j++) {
            float e00 = __expf(sf[2*j][0]   - mx0);
            float e01 = __expf(sf[2*j][1]   - mx0);
            float e10 = __expf(sf[2*j][2]   - mx1);
            float e11 = __expf(sf[2*j][3]   - mx1);
            float e20 = __expf(sf[2*j+1][0] - mx0);
            float e21 = __expf(sf[2*j+1][1] - mx0);
            float e30 = __expf(sf[2*j+1][2] - mx1);
            float e31 = __expf(sf[2*j+1][3] - mx1);
            s0 += e00 + e01 + e20 + e21;
            s1 += e10 + e11 + e30 + e31;
            ph[j][0] = packbf(e00, e01);
            ph[j][1] = packbf(e10, e11);
            ph[j][2] = packbf(e20, e21);
            ph[j][3] = packbf(e30, e31);
            __nv_bfloat162* hp = (__nv_bfloat162*)&ph[j][0];
            pl[j][0] = packbf(e00 - __bfloat162float(hp[0].x),
                              e01 - __bfloat162float(hp[0].y));
            hp = (__nv_bfloat162*)&ph[j][1];
            pl[j][1] = packbf(e10 - __bfloat162float(hp[0].x),
                              e11 - __bfloat162float(hp[0].y));
            hp = (__nv_bfloat162*)&ph[j][2];
            pl[j][2] = packbf(e20 - __bfloat162float(hp[0].x),
                              e21 - __bfloat162float(hp[0].y));
            hp = (__nv_bfloat162*)&ph[j][3];
            pl[j][3] = packbf(e30 - __bfloat162float(hp[0].x),
                              e31 - __bfloat162float(hp[0].y));
        }
        s0 += __shfl_xor_sync(0xffffffffu, s0, 1);
        s0 += __shfl_xor_sync(0xffffffffu, s0, 2);
        s1 += __shfl_xor_sync(0xffffffffu, s1, 1);
        s1 += __shfl_xor_sync(0xffffffffu, s1, 2);
        l[0] = l[0]*al0 + s0;
        l[1] = l[1]*al1 + s1;

        #pragma unroll
        for (int j = 0; j < 4; j++) {
            #pragma unroll
            for (int p = 0; p < 4; p++) {
                uint32_t th[4], tl[4];
                const uint32_t off = FSW((uint32_t)((j*16 + v_kv + b_row)*128
                                                     + p*32 + v_d*2));
                LDSM4T(th, stVh + off);
                LDSM4T(tl, stVl + off);
                uint32_t bh0[2] = { th[0], th[1] }, bh1[2] = { th[2], th[3] };
                uint32_t bl0[2] = { tl[0], tl[1] }, bl1[2] = { tl[2], tl[3] };
                mma16816(o[2*p],   ph[j], bh0);
                mma16816(o[2*p+1], ph[j], bh1);
                mma16816(o[2*p],   ph[j], bl0);
                mma16816(o[2*p+1], ph[j], bl1);
                mma16816(o[2*p],   pl[j], bh0);
                mma16816(o[2*p+1], pl[j], bh1);
            }
        }
        __syncthreads();
    }

    const float inv0 = 1.f / l[0];
    const float inv1 = 1.f / l[1];
    const int row = b*Lc + qy + wq + g;
    #pragma unroll
    for (int nt = 0; nt < 8; nt++) {
        const int col = hcol + nt*8 + tg*2;
        __nv_bfloat162 hh, ll;
        split1(o[nt][0]*inv0, hh.x, ll.x);
        split1(o[nt][1]*inv0, hh.y, ll.y);
        *(__nv_bfloat162*)&Oh[(size_t)row * Dc + col] = hh;
        *(__nv_bfloat162*)&Ol[(size_t)row * Dc + col] = ll;
        split1(o[nt][2]*inv1, hh.x, ll.x);
        split1(o[nt][3]*inv1, hh.y, ll.y);
        *(__nv_bfloat162*)&Oh[(size_t)(row + 8) * Dc + col] = hh;
        *(__nv_bfloat162*)&Ol[(size_t)(row + 8) * Dc + col] = ll;
    }
}

// ---------------------------------------------------------------------------
// small kernels (unchanged)
// ---------------------------------------------------------------------------
__global__ __launch_bounds__(256) void split_f32(
    const float* __restrict__ x, __nv_bfloat16* __restrict__ h,
    __nv_bfloat16* __restrict__ l)
{
    const size_t i = ((size_t)blockIdx.x * 256 + threadIdx.x) * 4;
    float4 v = *(const float4*)(x + i);
    __nv_bfloat162 hh0, hh1, ll0, ll1;
    split1(v.x, hh0.x, ll0.x); split1(v.y, hh0.y, ll0.y);
    split1(v.z, hh1.x, ll1.x); split1(v.w, hh1.y, ll1.y);
    *(__nv_bfloat162*)(h + i)     = hh0;
    *(__nv_bfloat162*)(h + i + 2) = hh1;
    *(__nv_bfloat162*)(l + i)     = ll0;
    *(__nv_bfloat162*)(l + i + 2) = ll1;
}

__global__ __launch_bounds__(256) void transpose_split(
    const float* __restrict__ W, __nv_bfloat16* __restrict__ h,
    __nv_bfloat16* __restrict__ l, int K, int N, size_t ostrideZ)
{
    __shared__ float t[32][33];
    const size_t ibase = (size_t)blockIdx.z * K * N;
    const size_t obase = (size_t)blockIdx.z * ostrideZ;
    const int k0 = blockIdx.y * 32, n0 = blockIdx.x * 32;
    const int tx = threadIdx.x & 31, ty = threadIdx.x >> 5;
    #pragma unroll
    for (int r = 0; r < 32; r += 8)
        t[ty + r][tx] = W[ibase + (size_t)(k0 + ty + r) * N + n0 + tx];
    __syncthreads();
    #pragma unroll
    for (int r = 0; r < 32; r += 8) {
        const float v = t[tx][ty + r];
        const size_t o = obase + (size_t)(n0 + ty + r) * K + k0 + tx;
        __nv_bfloat16 hh, ll;
        split1(v, hh, ll);
        h[o] = hh; l[o] = ll;
    }
}

__global__ void bias_cat(const float* __restrict__ bq, const float* __restrict__ bk,
                         const float* __restrict__ bv, float* __restrict__ o)
{
    const int i = blockIdx.x, seg = blockIdx.y, j = threadIdx.x;
    const float* src = (seg == 0) ? bq : (seg == 1) ? bk : bv;
    o[i*QKVW + seg*1024 + j] = src[i*1024 + j];
}

__global__ __launch_bounds__(256) void add_ln(
    const float* __restrict__ x, const float* __restrict__ res,
    const float* __restrict__ g, const float* __restrict__ bta,
    float* __restrict__ y, __nv_bfloat16* __restrict__ yh,
    __nv_bfloat16* __restrict__ yl)
{
    __shared__ float rs[8], rq[8];
    const int tid = threadIdx.x;
    const size_t base = (size_t)blockIdx.x * 1024 + tid * 4;

    float4 a = *(const float4*)&x[base];
    float4 r = *(const float4*)&res[base];
    a.x += r.x; a.y += r.y; a.z += r.z; a.w += r.w;

    float s = a.x + a.y + a.z + a.w;
    float q = a.x*a.x + a.y*a.y + a.z*a.z + a.w*a.w;
    #pragma unroll
    for (int o = 16; o > 0; o >>= 1) {
        s += __shfl_xor_sync(0xffffffffu, s, o);
        q += __shfl_xor_sync(0xffffffffu, q, o);
    }
    if ((tid & 31) == 0) { rs[tid >> 5] = s; rq[tid >> 5] = q; }
    __syncthreads();
    s = 0.f; q = 0.f;
    #pragma unroll
    for (int i = 0; i < 8; i++) { s += rs[i]; q += rq[i]; }

    const float mean = s * (1.f / 1024.f);
    const float var  = q * (1.f / 1024.f) - mean * mean;
    const float rstd = rsqrtf(var + 1e-5f);

    const int c = tid * 4;
    float4 gv = *(const float4*)&g[c];
    float4 bv = *(const float4*)&bta[c];
    float4 o;
    o.x = (a.x - mean) * rstd * gv.x + bv.x;
    o.y = (a.y - mean) * rstd * gv.y + bv.y;
    o.z = (a.z - mean) * rstd * gv.z + bv.z;
    o.w = (a.w - mean) * rstd * gv.w + bv.w;
    if (y) *(float4*)&y[base] = o;

    __nv_bfloat162 hh0, hh1, ll0, ll1;
    split1(o.x, hh0.x, ll0.x); split1(o.y, hh0.y, ll0.y);
    split1(o.z, hh1.x, ll1.x); split1(o.w, hh1.y, ll1.y);
    *(__nv_bfloat162*)&yh[base]     = hh0;
    *(__nv_bfloat162*)&yh[base + 2] = hh1;
    *(__nv_bfloat162*)&yl[base]     = ll0;
    *(__nv_bfloat162*)&yl[base + 2] = ll1;
}

// ---------------------------------------------------------------------------
// Launch orchestration — round 9 DAG:
//   * deferred weight prep on stream sC overlapping phase 1
//   * flash2 gated on {Q2, KV2} only; Q3 overlaps flash2; flash3 waits eQ3
// ---------------------------------------------------------------------------
extern "C" void kernel_launch(void* const* d_in, const int* in_sizes, int n_in,
                              void* d_out, int out_size)
{
    const float* T    = (const float*)d_in[0];
    const float* A    = (const float*)d_in[1];
    const float* mask = (const float*)d_in[2];
    const int*   pad  = (const int*)  d_in[3];
    const float* Wq   = (const float*)d_in[4];
    const float* bq   = (const float*)d_in[5];
    const float* Wk   = (const float*)d_in[6];
    const float* bk   = (const float*)d_in[7];
    const float* Wv   = (const float*)d_in[8];
    const float* bv   = (const float*)d_in[9];
    const float* Wo   = (const float*)d_in[10];
    const float* ffW1 = (const float*)d_in[11];
    const float* ffb1 = (const float*)d_in[12];
    const float* ffW2 = (const float*)d_in[13];
    const float* ffb2 = (const float*)d_in[14];
    const float* lng  = (const float*)d_in[15];
    const float* lnb  = (const float*)d_in[16];
    float* out = (float*)d_out;

    static cudaStream_t sA = nullptr, sB = nullptr, sC = nullptr;
    static cudaEvent_t  eF = nullptr, eA = nullptr, eB = nullptr;
    static cudaEvent_t  eC = nullptr, eQ2 = nullptr, eKV2 = nullptr, eQ3 = nullptr;
    if (!sA) {
        cudaStreamCreateWithFlags(&sA, cudaStreamNonBlocking);
        cudaStreamCreateWithFlags(&sB, cudaStreamNonBlocking);
        cudaStreamCreateWithFlags(&sC, cudaStreamNonBlocking);
        cudaEventCreateWithFlags(&eF,  cudaEventDisableTiming);
        cudaEventCreateWithFlags(&eA,  cudaEventDisableTiming);
        cudaEventCreateWithFlags(&eB,  cudaEventDisableTiming);
        cudaEventCreateWithFlags(&eC,  cudaEventDisableTiming);
        cudaEventCreateWithFlags(&eQ2, cudaEventDisableTiming);
        cudaEventCreateWithFlags(&eKV2,cudaEventDisableTiming);
        cudaEventCreateWithFlags(&eQ3, cudaEventDisableTiming);
    }
    auto fork = [&]() {
        cudaEventRecord(eF, 0);
        cudaStreamWaitEvent(sA, eF, 0);
        cudaStreamWaitEvent(sB, eF, 0);
    };
    auto join = [&]() {
        cudaEventRecord(eA, sA);
        cudaEventRecord(eB, sB);
        cudaStreamWaitEvent(0, eA, 0);
        cudaStreamWaitEvent(0, eB, 0);
    };

    float *Mo0, *Mo1, *T1f, *A1f;
    cudaGetSymbolAddress((void**)&Mo0, g_Mo0);
    cudaGetSymbolAddress((void**)&Mo1, g_Mo1);
    cudaGetSymbolAddress((void**)&T1f, g_T1f);
    cudaGetSymbolAddress((void**)&A1f, g_A1f);

    __nv_bfloat16 *iTh,*iTl,*iAh,*iAl,*T1h,*T1l,*A1h,*A1l,*T2h,*T2l,*A2h,*A2l;
    __nv_bfloat16 *QKV0h,*QKV0l,*QKV1h,*QKV1l,*O0h,*O0l,*O1h,*O1l;
    __nv_bfloat16 *H0h,*H0l,*H1h,*H1l;
    __nv_bfloat16 *wch,*wcl,*woh,*wol,*w1h,*w1l,*w2h,*w2l;
    float* bcat;
    cudaGetSymbolAddress((void**)&iTh, g_iTh); cudaGetSymbolAddress((void**)&iTl, g_iTl);
    cudaGetSymbolAddress((void**)&iAh, g_iAh); cudaGetSymbolAddress((void**)&iAl, g_iAl);
    cudaGetSymbolAddress((void**)&T1h, g_T1h); cudaGetSymbolAddress((void**)&T1l, g_T1l);
    cudaGetSymbolAddress((void**)&A1h, g_A1h); cudaGetSymbolAddress((void**)&A1l, g_A1l);
    cudaGetSymbolAddress((void**)&T2h, g_T2h); cudaGetSymbolAddress((void**)&T2l, g_T2l);
    cudaGetSymbolAddress((void**)&A2h, g_A2h); cudaGetSymbolAddress((void**)&A2l, g_A2l);
    cudaGetSymbolAddress((void**)&QKV0h, g_QKV0h); cudaGetSymbolAddress((void**)&QKV0l, g_QKV0l);
    cudaGetSymbolAddress((void**)&QKV1h, g_QKV1h); cudaGetSymbolAddress((void**)&QKV1l, g_QKV1l);
    cudaGetSymbolAddress((void**)&O0h, g_O0h); cudaGetSymbolAddress((void**)&O0l, g_O0l);
    cudaGetSymbolAddress((void**)&O1h, g_O1h); cudaGetSymbolAddress((void**)&O1l, g_O1l);
    cudaGetSymbolAddress((void**)&H0h, g_H0h); cudaGetSymbolAddress((void**)&H0l, g_H0l);
    cudaGetSymbolAddress((void**)&H1h, g_H1h); cudaGetSymbolAddress((void**)&H1l, g_H1l);
    cudaGetSymbolAddress((void**)&wch, g_wch); cudaGetSymbolAddress((void**)&wcl, g_wcl);
    cudaGetSymbolAddress((void**)&woh, g_woh); cudaGetSymbolAddress((void**)&wol, g_wol);
    cudaGetSymbolAddress((void**)&w1h, g_w1h); cudaGetSymbolAddress((void**)&w1l, g_w1l);
    cudaGetSymbolAddress((void**)&w2h, g_w2h); cudaGetSymbolAddress((void**)&w2l, g_w2l);
    cudaGetSymbolAddress((void**)&bcat, g_bcat);

    cudaFuncSetAttribute(gemm_mma,   cudaFuncAttributeMaxDynamicSharedMemorySize, GEMM_SMEM);
    cudaFuncSetAttribute(flash_attn, cudaFuncAttributeMaxDynamicSharedMemorySize, FA_SMEM);

    const size_t DD = (size_t)Dc * Dc;
    const size_t WCZ = (size_t)QKVW * Dc;

    auto gemm = [&](cudaStream_t st,
                    const __nv_bfloat16* ah, const __nv_bfloat16* al,
                    const __nv_bfloat16* bh, const __nv_bfloat16* bl,
                    const float* bias, float* c, __nv_bfloat16* ch, __nv_bfloat16* cl,
                    int M, int N, int K, int ldc, int coff, int relu) {
        gemm_mma<<<dim3(N/128, M/128), 256, GEMM_SMEM, st>>>(
            ah, al, bh, bl, bias, c, ch, cl, M, N, K, ldc, coff, relu);
    };

    // ------- Phase 0: CRITICAL prep (sA/sB) + DEFERRED prep (sC) -------
    fork();
    cudaStreamWaitEvent(sC, eF, 0);
    // sA: QKV weights for i=0,1 + bias + split(T)
    transpose_split<<<dim3(32,32,2), 256, 0, sA>>>(Wq, wch,        wcl,        Dc, Dc, WCZ);
    transpose_split<<<dim3(32,32,2), 256, 0, sA>>>(Wk, wch + DD,   wcl + DD,   Dc, Dc, WCZ);
    transpose_split<<<dim3(32,32,2), 256, 0, sA>>>(Wv, wch + 2*DD, wcl + 2*DD, Dc, Dc, WCZ);
    bias_cat<<<dim3(4,3), 1024, 0, sA>>>(bq, bk, bv, bcat);
    split_f32<<<BLc, 256, 0, sA>>>(T, iTh, iTl);
    // sB: Wo for i=0,1 + split(A)
    transpose_split<<<dim3(32,32,2), 256, 0, sB>>>(Wo, woh, wol, Dc, Dc, DD);
    split_f32<<<BLc, 256, 0, sB>>>(A, iAh, iAl);
    // sC (deferred, overlaps phase 1): QKV i=2,3; Wo i=2,3; FFN weights
    transpose_split<<<dim3(32,32,2), 256, 0, sC>>>(Wq + 2*DD, wch + 2*WCZ,
                                                   wcl + 2*WCZ, Dc, Dc, WCZ);
    transpose_split<<<dim3(32,32,2), 256, 0, sC>>>(Wk + 2*DD, wch + 2*WCZ + DD,
                                                   wcl + 2*WCZ + DD, Dc, Dc, WCZ);
    transpose_split<<<dim3(32,32,2), 256, 0, sC>>>(Wv + 2*DD, wch + 2*WCZ + 2*DD,
                                                   wcl + 2*WCZ + 2*DD, Dc, Dc, WCZ);
    transpose_split<<<dim3(32,32,2), 256, 0, sC>>>(Wo + 2*DD, woh + 2*DD,
                                                   wol + 2*DD, Dc, Dc, DD);
    transpose_split<<<dim3(128,32,2), 256, 0, sC>>>(ffW1, w1h, w1l, Dc, Fc, (size_t)Dc*Fc);
    transpose_split<<<dim3(32,128,2), 256, 0, sC>>>(ffW2, w2h, w2l, Fc, Dc, (size_t)Fc*Dc);
    cudaEventRecord(eC, sC);
    join();

    // ---------------- Phase 1: mha0 (T, sA) || mha1 (A, sB) ----------------
    fork();
    gemm(sA, iTh, iTl, wch, wcl, bcat, nullptr, QKV0h, QKV0l,
         BLc, QKVW, Dc, QKVW, 0, 0);
    flash_attn<<<dim3(Lc/128, 64), 256, FA_SMEM, sA>>>(QKV0h, QKV0l, mask, pad, O0h, O0l);
    gemm(sA, O0h, O0l, woh, wol, nullptr, Mo0, nullptr, nullptr,
         BLc, Dc, Dc, Dc, 0, 0);
    add_ln<<<BLc, 256, 0, sA>>>(T, Mo0, lng, lnb, T1f, T1h, T1l);
    gemm(sB, iAh, iAl, wch + WCZ, wcl + WCZ, bcat + QKVW, nullptr, QKV1h, QKV1l,
         BLc, QKVW, Dc, QKVW, 0, 0);
    flash_attn<<<dim3(Lc/128, 64), 256, FA_SMEM, sB>>>(QKV1h, QKV1l, mask, pad, O1h, O1l);
    gemm(sB, O1h, O1l, woh + DD, wol + DD, nullptr, Mo1, nullptr, nullptr,
         BLc, Dc, Dc, Dc, 0, 0);
    add_ln<<<BLc, 256, 0, sB>>>(A, Mo1, lng + Dc, lnb + Dc, A1f, A1h, A1l);
    join();
    cudaStreamWaitEvent(0, eC, 0);     // deferred weights ready before phase 2

    // ------- Phase 2: KV2 (sA) || Q2,Q3 (sB); flash2 waits only {KV2,Q2} -------
    fork();
    gemm(sA, A1h, A1l, wch + 2*WCZ + DD, wcl + 2*WCZ + DD, bcat + 2*QKVW + 1024,
         nullptr, QKV0h, QKV0l, BLc, 2*Dc, Dc, QKVW, 1024, 0);
    cudaEventRecord(eKV2, sA);
    gemm(sB, T1h, T1l, wch + 2*WCZ, wcl + 2*WCZ, bcat + 2*QKVW,
         nullptr, QKV0h, QKV0l, BLc, Dc, Dc, QKVW, 0, 0);
    cudaEventRecord(eQ2, sB);
    gemm(sB, A1h, A1l, wch + 3*WCZ, wcl + 3*WCZ, bcat + 3*QKVW,
         nullptr, QKV1h, QKV1l, BLc, Dc, Dc, QKVW, 0, 0);   // Q3, overlaps flash2
    cudaEventRecord(eQ3, sB);

    // mha2 tail on default: gated on KV2+Q2 only
    cudaStreamWaitEvent(0, eKV2, 0);
    cudaStreamWaitEvent(0, eQ2, 0);
    flash_attn<<<dim3(Lc/128, 64), 256, FA_SMEM>>>(QKV0h, QKV0l, mask, pad, O0h, O0l);
    gemm(0, O0h, O0l, woh + 2*DD, wol + 2*DD, nullptr, Mo0, nullptr, nullptr,
         BLc, Dc, Dc, Dc, 0, 0);
    add_ln<<<BLc, 256>>>(T1f, Mo0, lng + 2*Dc, lnb + 2*Dc, nullptr, T2h, T2l);

    // ------- Phase 3: mha3 chain + FFN-A (sA)  ||  FFN-T (sB) -------
    fork();
    // sA: KV3 (needs only T2) -> wait Q3 -> flash3 -> Wo3 -> LN3 -> FFN-A
    gemm(sA, T2h, T2l, wch + 3*WCZ + DD, wcl + 3*WCZ + DD, bcat + 3*QKVW + 1024,
         nullptr, QKV1h, QKV1l, BLc, 2*Dc, Dc, QKVW, 1024, 0);
    cudaStreamWaitEvent(sA, eQ3, 0);
    flash_attn<<<dim3(Lc/128, 64), 256, FA_SMEM, sA>>>(QKV1h, QKV1l, mask, pad, O0h, O0l);
    gemm(sA, O0h, O0l, woh + 3*DD, wol + 3*DD, nullptr, Mo0, nullptr, nullptr,
         BLc, Dc, Dc, Dc, 0, 0);
    add_ln<<<BLc, 256, 0, sA>>>(A1f, Mo0, lng + 3*Dc, lnb + 3*Dc, nullptr, A2h, A2l);
    gemm(sA, A2h, A2l, w1h + (size_t)Dc*Fc, w1l + (size_t)Dc*Fc, ffb1 + Fc,
         nullptr, H1h, H1l, BLc, Fc, Dc, Fc, 0, 1);
    gemm(sA, H1h, H1l, w2h + (size_t)Fc*Dc, w2l + (size_t)Fc*Dc, ffb2 + Dc,
         out + (size_t)BLc*Dc, nullptr, nullptr, BLc, Dc, Fc, Dc, 0, 0);
    // sB: FFN-T (T2 ready via fork) — overlaps the whole sA chain
    gemm(sB, T2h, T2l, w1h, w1l, ffb1, nullptr, H0h, H0l, BLc, Fc, Dc, Fc, 0, 1);
    gemm(sB, H0h, H0l, w2h, w2l, ffb2, out, nullptr, nullptr, BLc, Dc, Fc, Dc, 0, 0);
    join();
}

// round 10
// speedup vs baseline: 4.7260x; 1.3625x over previous
#include <cuda_runtime.h>
#include <cuda_fp16.h>
#include <math.h>
#include <stdint.h>

// Problem constants
constexpr int Bc  = 4;
constexpr int Lc  = 1024;
constexpr int Dc  = 1024;
constexpr int Fc  = 4096;
constexpr int HDc = 64;
constexpr int BLc = Bc * Lc;          // 4096 rows
constexpr int QKVW = 3 * Dc;          // 3072 concat width

// ---------------------------------------------------------------------------
// Scratch (static __device__ arrays — allocation-free per harness rules)
// ---------------------------------------------------------------------------
__device__ float g_Mo0[BLc * Dc];
__device__ float g_Mo1[BLc * Dc];
__device__ float g_T1f[BLc * Dc];
__device__ float g_A1f[BLc * Dc];

// single-fp16 activations
__device__ __half g_iT [BLc*Dc], g_iA [BLc*Dc];
__device__ __half g_T1 [BLc*Dc], g_A1 [BLc*Dc];
__device__ __half g_T2 [BLc*Dc], g_A2 [BLc*Dc];
__device__ __half g_O0 [BLc*Dc], g_O1 [BLc*Dc];
__device__ __half g_H0 [(size_t)BLc*Fc], g_H1 [(size_t)BLc*Fc];
// QKV buffers: split (K/V consumed as hi+lo by flash; Q region's lo unused)
__device__ __half g_QKV0h[(size_t)BLc*QKVW], g_QKV0l[(size_t)BLc*QKVW];
__device__ __half g_QKV1h[(size_t)BLc*QKVW], g_QKV1l[(size_t)BLc*QKVW];

// weights: split fp16, concat QKV^T [4][3072,1024]; others [N,K]
__device__ __half g_wch[(size_t)4*QKVW*Dc], g_wcl[(size_t)4*QKVW*Dc];
__device__ __half g_woh[4*Dc*Dc], g_wol[4*Dc*Dc];
__device__ __half g_w1h[2*Dc*Fc], g_w1l[2*Dc*Fc];
__device__ __half g_w2h[2*Fc*Dc], g_w2l[2*Fc*Dc];
__device__ float g_bcat[4*QKVW];

// ---------------------------------------------------------------------------
// PTX helpers (sm_103 baseline-safe)
// ---------------------------------------------------------------------------
__device__ __forceinline__ uint32_t smem_u32(const void* p) {
    uint32_t a;
    asm("{ .reg .u64 t; cvta.to.shared.u64 t, %1; cvt.u32.u64 %0, t; }" : "=r"(a) : "l"(p));
    return a;
}
__device__ __forceinline__ void cpasync16(uint32_t dst, const void* src) {
    asm volatile("cp.async.cg.shared.global [%0], [%1], 16;" :: "r"(dst), "l"(src));
}
#define CP_COMMIT()  asm volatile("cp.async.commit_group;" ::: "memory")
#define CP_WAIT(n)   asm volatile("cp.async.wait_group %0;" :: "n"(n) : "memory")

#define LDSM4(r, a) \
    asm volatile("ldmatrix.sync.aligned.m8n8.x4.shared.b16 {%0,%1,%2,%3}, [%4];" \
        : "=r"((r)[0]), "=r"((r)[1]), "=r"((r)[2]), "=r"((r)[3]) : "r"(a))
#define LDSM4T(r, a) \
    asm volatile("ldmatrix.sync.aligned.m8n8.x4.trans.shared.b16 {%0,%1,%2,%3}, [%4];" \
        : "=r"((r)[0]), "=r"((r)[1]), "=r"((r)[2]), "=r"((r)[3]) : "r"(a))

// fp16 MMA, fp32 accumulate
__device__ __forceinline__ void mma16816(float* c, const uint32_t* a, const uint32_t* b) {
    asm volatile(
        "mma.sync.aligned.m16n8k16.row.col.f32.f16.f16.f32 "
        "{%0,%1,%2,%3}, {%4,%5,%6,%7}, {%8,%9}, {%0,%1,%2,%3};"
        : "+f"(c[0]), "+f"(c[1]), "+f"(c[2]), "+f"(c[3])
        : "r"(a[0]), "r"(a[1]), "r"(a[2]), "r"(a[3]), "r"(b[0]), "r"(b[1]));
}

__device__ __forceinline__ void split1h(float v, __half& h, __half& l) {
    h = __float2half(v);
    l = __float2half(v - __half2float(h));
}
__device__ __forceinline__ uint32_t packh(float a, float b) {
    __half2 t; t.x = __float2half(a); t.y = __float2half(b);
    return *(uint32_t*)&t;
}
#define FSW(o) ((o) ^ (((o) >> 3) & 0x70))     // SW128 swizzle for 128B rows

// ---------------------------------------------------------------------------
// Tensor-core GEMM: C[M,N] = A[M,K] @ (Bh+Bl)[N,K]^T (+bias)(+relu)
// A single fp16; B split fp16 (2 MMA products). Output: fp32 (C), split
// (Ch+Cl), or single-half (Ch only). ldc stride, coff col offset.
// ---------------------------------------------------------------------------
constexpr int GSTR    = 40;
constexpr int TILE_B  = 128 * GSTR * 2;       // 10240 B per tile
constexpr int STAGE_B = 3 * TILE_B;           // A, Bh, Bl = 30720 B
constexpr int GEMM_SMEM = 2 * STAGE_B;        // 61440 B

__global__ __launch_bounds__(256, 2) void gemm_mma(
    const __half* __restrict__ Aa,
    const __half* __restrict__ Bh, const __half* __restrict__ Bl,
    const float* __restrict__ bias, float* __restrict__ C,
    __half* __restrict__ Ch, __half* __restrict__ Cl,
    int M, int N, int K, int ldc, int coff, int relu)
{
    extern __shared__ char sm[];
    const uint32_t sb = smem_u32(sm);
    const int tid  = threadIdx.x;
    const int wid  = tid >> 5;
    const int lane = tid & 31;
    const int brow = blockIdx.y * 128;
    const int bcol = blockIdx.x * 128;
    const int wm   = (wid & 1) * 64;
    const int wn   = (wid >> 1) * 32;

    float acc[4][4][4];
    #pragma unroll
    for (int i = 0; i < 4; i++)
        #pragma unroll
        for (int j = 0; j < 4; j++)
            #pragma unroll
            for (int k = 0; k < 4; k++) acc[i][j][k] = 0.f;

    const int r0 = tid >> 2,            q0 = tid & 3;
    const int r1 = (tid + 256) >> 2,    q1 = (tid + 256) & 3;
    const int nch = K >> 5;

    auto issue = [&](int c, int s) {
        const int kc = c << 5;
        const uint32_t st = sb + s * STAGE_B;
        {
            const uint32_t so = (uint32_t)(r0 * 80 + q0 * 16);
            const size_t ga = (size_t)(brow + r0) * K + kc + q0 * 8;
            const size_t gb = (size_t)(bcol + r0) * K + kc + q0 * 8;
            cpasync16(st + so,              Aa + ga);
            cpasync16(st + TILE_B + so,     Bh + gb);
            cpasync16(st + 2*TILE_B + so,   Bl + gb);
        }
        {
            const uint32_t so = (uint32_t)(r1 * 80 + q1 * 16);
            const size_t ga = (size_t)(brow + r1) * K + kc + q1 * 8;
            const size_t gb = (size_t)(bcol + r1) * K + kc + q1 * 8;
            cpasync16(st + so,              Aa + ga);
            cpasync16(st + TILE_B + so,     Bh + gb);
            cpasync16(st + 2*TILE_B + so,   Bl + gb);
        }
        CP_COMMIT();
    };

    issue(0, 0);

    const int a_row = (lane & 15);
    const int a_kof = ((lane >> 4) << 3);
    const int g8    = lane >> 3;
    const int b_nt  = (g8 >> 1) << 3;
    const int b_kof = (g8 & 1) << 3;
    const int b_row = (lane & 7);

    for (int c = 0; c < nch; c++) {
        if (c + 1 < nch) { issue(c + 1, (c + 1) & 1); CP_WAIT(1); }
        else             { CP_WAIT(0); }
        __syncthreads();

        const uint32_t st = sb + (c & 1) * STAGE_B;
        #pragma unroll
        for (int k16 = 0; k16 < 32; k16 += 16) {
            uint32_t aH[4][4], t[4];
            #pragma unroll
            for (int mt = 0; mt < 4; mt++) {
                uint32_t ad = st + (uint32_t)((wm + mt*16 + a_row) * 80
                                              + (k16 + a_kof) * 2);
                LDSM4(aH[mt], ad);
            }
            // B-hi: 2 LDSM -> 16 MMA
            #pragma unroll
            for (int p = 0; p < 2; p++) {
                uint32_t ad = st + TILE_B
                    + (uint32_t)((wn + p*16 + b_nt + b_row) * 80
                                 + (k16 + b_kof) * 2);
                LDSM4(t, ad);
                uint32_t b0[2] = { t[0], t[1] }, b1[2] = { t[2], t[3] };
                #pragma unroll
                for (int mt = 0; mt < 4; mt++) {
                    mma16816(acc[mt][2*p    ], aH[mt], b0);
                    mma16816(acc[mt][2*p + 1], aH[mt], b1);
                }
            }
            // B-lo: 2 LDSM -> 16 MMA
            #pragma unroll
            for (int p = 0; p < 2; p++) {
                uint32_t ad = st + 2*TILE_B
                    + (uint32_t)((wn + p*16 + b_nt + b_row) * 80
                                 + (k16 + b_kof) * 2);
                LDSM4(t, ad);
                uint32_t b0[2] = { t[0], t[1] }, b1[2] = { t[2], t[3] };
                #pragma unroll
                for (int mt = 0; mt < 4; mt++) {
                    mma16816(acc[mt][2*p    ], aH[mt], b0);
                    mma16816(acc[mt][2*p + 1], aH[mt], b1);
                }
            }
        }
        __syncthreads();
    }

    const int g  = lane >> 2;
    const int tg = lane & 3;
    #pragma unroll
    for (int mt = 0; mt < 4; mt++) {
        #pragma unroll
        for (int nt = 0; nt < 4; nt++) {
            const int row = brow + wm + mt*16 + g;
            const int col = bcol + wn + nt*8 + tg*2;
            float2 v0, v1;
            v0.x = acc[mt][nt][0]; v0.y = acc[mt][nt][1];
            v1.x = acc[mt][nt][2]; v1.y = acc[mt][nt][3];
            if (bias) {
                float2 bb = *(const float2*)&bias[col];
                v0.x += bb.x; v0.y += bb.y; v1.x += bb.x; v1.y += bb.y;
            }
            if (relu) {
                v0.x = fmaxf(v0.x, 0.f); v0.y = fmaxf(v0.y, 0.f);
                v1.x = fmaxf(v1.x, 0.f); v1.y = fmaxf(v1.y, 0.f);
            }
            const size_t o0 = (size_t)row * ldc + coff + col;
            const size_t o1 = (size_t)(row + 8) * ldc + coff + col;
            if (C) {
                *(float2*)&C[o0] = v0;
                *(float2*)&C[o1] = v1;
            }
            if (Ch) {
                __half2 hh, ll;
                split1h(v0.x, hh.x, ll.x); split1h(v0.y, hh.y, ll.y);
                *(__half2*)&Ch[o0] = hh;
                if (Cl) *(__half2*)&Cl[o0] = ll;
                split1h(v1.x, hh.x, ll.x); split1h(v1.y, hh.y, ll.y);
                *(__half2*)&Ch[o1] = hh;
                if (Cl) *(__half2*)&Cl[o1] = ll;
            }
        }
    }
}

// ---------------------------------------------------------------------------
// Fused flash attention: Q single fp16, K/V split fp16 (2-product MMAs),
// P single fp16, O single fp16. Occupancy 2; SW128 64-row K/V tiles.
// ---------------------------------------------------------------------------
constexpr int FA_QTB   = 128 * 144;               // 18432 B, Q single tile
constexpr int FA_KTB   = 64 * 128;                // 8192 B
constexpr int FA_STAGE = 4 * FA_KTB;              // Kh,Kl,Vh,Vl = 32768 B
constexpr int FA_SMEM  = FA_QTB + 2*FA_STAGE + 4096;   // 88064 B

__global__ __launch_bounds__(256, 2) void flash_attn(
    const __half* __restrict__ Xh, const __half* __restrict__ Xl,
    const float* __restrict__ mask, const int* __restrict__ pad,
    __half* __restrict__ O)
{
    extern __shared__ char sm[];
    const uint32_t sb = smem_u32(sm);
    const int tid  = threadIdx.x;
    const int wid  = tid >> 5;
    const int lane = tid & 31;
    const int qy   = blockIdx.x * 128;
    const int bh   = blockIdx.y;
    const int b    = bh >> 4;
    const int hcol = (bh & 15) * HDc;
    const int wq   = wid * 16;

    const uint32_t sQ     = sb;
    const uint32_t sStage = sb + FA_QTB;
    float* spad = (float*)(sm + FA_QTB + 2*FA_STAGE);

    for (int i = tid; i < 1024; i += 256)
        spad[i] = (float)pad[b*Lc + i];

    // Q tile (single fp16) cp.async, stride 144
    for (int i = tid; i < 1024; i += 256) {
        const int r = i >> 3, j = i & 7;
        const uint32_t so = (uint32_t)(r * 144 + j * 16);
        const size_t gq = (size_t)(b*Lc + qy + r) * QKVW + hcol + j*8;
        cpasync16(sQ + so, Xh + gq);
    }
    CP_COMMIT();

    auto issueKV = [&](int t, int s) {
        const int kx = t * 64;
        const uint32_t base = sStage + s * FA_STAGE;
        for (int i = tid; i < 512; i += 256) {
            const int r = i >> 3, j = i & 7;
            const uint32_t so = FSW((uint32_t)(r * 128 + j * 16));
            const size_t gk = (size_t)(b*Lc + kx + r) * QKVW + 1024 + hcol + j*8;
            cpasync16(base + so,             Xh + gk);
            cpasync16(base + FA_KTB + so,    Xl + gk);
            cpasync16(base + 2*FA_KTB + so,  Xh + gk + 1024);
            cpasync16(base + 3*FA_KTB + so,  Xl + gk + 1024);
        }
        CP_COMMIT();
    };
    issueKV(0, 0);

    CP_WAIT(1);          // Q complete
    __syncthreads();

    const int a_row = lane & 15;
    const int a_kof = (lane >> 4) << 3;
    uint32_t qh[4][4];
    #pragma unroll
    for (int kt = 0; kt < 4; kt++)
        LDSM4(qh[kt], sQ + (uint32_t)((wq + a_row)*144 + (kt*16 + a_kof)*2));

    float m[2] = { -1e30f, -1e30f };
    float l[2] = { 0.f, 0.f };
    float o[8][4];
    #pragma unroll
    for (int i = 0; i < 8; i++)
        #pragma unroll
        for (int j = 0; j < 4; j++) o[i][j] = 0.f;

    const int g    = lane >> 2;
    const int tg   = lane & 3;
    const int g8   = lane >> 3;
    const int b_nt  = (g8 >> 1) << 3;
    const int b_kof = (g8 & 1) << 3;
    const int b_row = lane & 7;
    const int v_kv = ((lane >> 3) & 1) << 3;
    const int v_d  = (lane >> 4) << 3;

    for (int t = 0; t < 16; t++) {
        const int kx = t * 64;
        if (t + 1 < 16) { issueKV(t + 1, (t + 1) & 1); CP_WAIT(1); }
        else            { CP_WAIT(0); }
        __syncthreads();

        const uint32_t stK  = sStage + (t & 1) * FA_STAGE;
        const uint32_t stKl = stK + FA_KTB;
        const uint32_t stVh = stK + 2*FA_KTB;
        const uint32_t stVl = stK + 3*FA_KTB;

        // ---- S = Q (Kh+Kl)^T : 2 products ----
        float sf[8][4];
        #pragma unroll
        for (int i = 0; i < 8; i++)
            #pragma unroll
            for (int j = 0; j < 4; j++) sf[i][j] = 0.f;

        #pragma unroll
        for (int kst = 0; kst < 4; kst++) {
            uint32_t kb[4][4];
            #pragma unroll
            for (int p = 0; p < 4; p++) {
                const uint32_t ad = stK + FSW((uint32_t)((p*16 + b_nt + b_row)*128
                                                          + kst*32 + b_kof*2));
                LDSM4(kb[p], ad);
            }
            #pragma unroll
            for (int p = 0; p < 4; p++) {
                uint32_t b0[2] = { kb[p][0], kb[p][1] };
                uint32_t b1[2] = { kb[p][2], kb[p][3] };
                mma16816(sf[2*p],   qh[kst], b0);
                mma16816(sf[2*p+1], qh[kst], b1);
            }
            #pragma unroll
            for (int p = 0; p < 4; p++) {
                const uint32_t ad = stKl + FSW((uint32_t)((p*16 + b_nt + b_row)*128
                                                           + kst*32 + b_kof*2));
                LDSM4(kb[p], ad);
            }
            #pragma unroll
            for (int p = 0; p < 4; p++) {
                uint32_t b0[2] = { kb[p][0], kb[p][1] };
                uint32_t b1[2] = { kb[p][2], kb[p][3] };
                mma16816(sf[2*p],   qh[kst], b0);
                mma16816(sf[2*p+1], qh[kst], b1);
            }
        }

        // ---- scale + mask + pad ----
        const int qg0 = qy + wq + g;
        #pragma unroll
        for (int nt = 0; nt < 8; nt++) {
            const int kvl = nt*8 + tg*2;
            const int kvg = kx + kvl;
            float2 m0 = *(const float2*)&mask[(size_t)qg0 * Lc + kvg];
            float2 m1 = *(const float2*)&mask[(size_t)(qg0 + 8) * Lc + kvg];
            const float p0 = spad[kvg], p1 = spad[kvg + 1];
            sf[nt][0] = sf[nt][0]*0.125f + m0.x + p0;
            sf[nt][1] = sf[nt][1]*0.125f + m0.y + p1;
            sf[nt][2] = sf[nt][2]*0.125f + m1.x + p0;
            sf[nt][3] = sf[nt][3]*0.125f + m1.y + p1;
        }

        // ---- online softmax ----
        float mx0 = m[0], mx1 = m[1];
        #pragma unroll
        for (int nt = 0; nt < 8; nt++) {
            mx0 = fmaxf(mx0, fmaxf(sf[nt][0], sf[nt][1]));
            mx1 = fmaxf(mx1, fmaxf(sf[nt][2], sf[nt][3]));
        }
        mx0 = fmaxf(mx0, __shfl_xor_sync(0xffffffffu, mx0, 1));
        mx0 = fmaxf(mx0, __shfl_xor_sync(0xffffffffu, mx0, 2));
        mx1 = fmaxf(mx1, __shfl_xor_sync(0xffffffffu, mx1, 1));
        mx1 = fmaxf(mx1, __shfl_xor_sync(0xffffffffu, mx1, 2));

        const float al0 = __expf(m[0] - mx0);
        const float al1 = __expf(m[1] - mx1);
        m[0] = mx0; m[1] = mx1;
        #pragma unroll
        for (int nt = 0; nt < 8; nt++) {
            o[nt][0] *= al0; o[nt][1] *= al0;
            o[nt][2] *= al1; o[nt][3] *= al1;
        }

        uint32_t ph[4][4];
        float s0 = 0.f, s1 = 0.f;
        #pragma unroll
        for (int j = 0; j < 4; j++) {
            float e00 = __expf(sf[2*j][0]   - mx0);
            float e01 = __expf(sf[2*j][1]   - mx0);
            float e10 = __expf(sf[2*j][2]   - mx1);
            float e11 = __expf(sf[2*j][3]   - mx1);
            float e20 = __expf(sf[2*j+1][0] - mx0);
            float e21 = __expf(sf[2*j+1][1] - mx0);
            float e30 = __expf(sf[2*j+1][2] - mx1);
            float e31 = __expf(sf[2*j+1][3] - mx1);
            s0 += e00 + e01 + e20 + e21;
            s1 += e10 + e11 + e30 + e31;
            ph[j][0] = packh(e00, e01);
            ph[j][1] = packh(e10, e11);
            ph[j][2] = packh(e20, e21);
            ph[j][3] = packh(e30, e31);
        }
        s0 += __shfl_xor_sync(0xffffffffu, s0, 1);
        s0 += __shfl_xor_sync(0xffffffffu, s0, 2);
        s1 += __shfl_xor_sync(0xffffffffu, s1, 1);
        s1 += __shfl_xor_sync(0xffffffffu, s1, 2);
        l[0] = l[0]*al0 + s0;
        l[1] = l[1]*al1 + s1;

        // ---- O += P (Vh+Vl) : 2 products ----
        #pragma unroll
        for (int j = 0; j < 4; j++) {
            #pragma unroll
            for (int p = 0; p < 4; p++) {
                uint32_t th[4], tl[4];
                const uint32_t off = FSW((uint32_t)((j*16 + v_kv + b_row)*128
                                                     + p*32 + v_d*2));
                LDSM4T(th, stVh + off);
                LDSM4T(tl, stVl + off);
                uint32_t bh0[2] = { th[0], th[1] }, bh1[2] = { th[2], th[3] };
                uint32_t bl0[2] = { tl[0], tl[1] }, bl1[2] = { tl[2], tl[3] };
                mma16816(o[2*p],   ph[j], bh0);
                mma16816(o[2*p+1], ph[j], bh1);
                mma16816(o[2*p],   ph[j], bl0);
                mma16816(o[2*p+1], ph[j], bl1);
            }
        }
        __syncthreads();
    }

    // ---- finalize: O /= l, write single fp16 ----
    const float inv0 = 1.f / l[0];
    const float inv1 = 1.f / l[1];
    const int row = b*Lc + qy + wq + g;
    #pragma unroll
    for (int nt = 0; nt < 8; nt++) {
        const int col = hcol + nt*8 + tg*2;
        *(uint32_t*)&O[(size_t)row * Dc + col]       = packh(o[nt][0]*inv0, o[nt][1]*inv0);
        *(uint32_t*)&O[(size_t)(row + 8) * Dc + col] = packh(o[nt][2]*inv1, o[nt][3]*inv1);
    }
}

// ---------------------------------------------------------------------------
// small kernels
// ---------------------------------------------------------------------------
__global__ __launch_bounds__(256) void cvt_f16(
    const float* __restrict__ x, __half* __restrict__ h)
{
    const size_t i = ((size_t)blockIdx.x * 256 + threadIdx.x) * 4;
    float4 v = *(const float4*)(x + i);
    *(uint32_t*)(h + i)     = packh(v.x, v.y);
    *(uint32_t*)(h + i + 2) = packh(v.z, v.w);
}

// W[z][K,N] fp32 -> out[z*ostrideZ + n*K + k] fp16 hi/lo ([N,K] transpose)
__global__ __launch_bounds__(256) void transpose_split(
    const float* __restrict__ W, __half* __restrict__ h,
    __half* __restrict__ l, int K, int N, size_t ostrideZ)
{
    __shared__ float t[32][33];
    const size_t ibase = (size_t)blockIdx.z * K * N;
    const size_t obase = (size_t)blockIdx.z * ostrideZ;
    const int k0 = blockIdx.y * 32, n0 = blockIdx.x * 32;
    const int tx = threadIdx.x & 31, ty = threadIdx.x >> 5;
    #pragma unroll
    for (int r = 0; r < 32; r += 8)
        t[ty + r][tx] = W[ibase + (size_t)(k0 + ty + r) * N + n0 + tx];
    __syncthreads();
    #pragma unroll
    for (int r = 0; r < 32; r += 8) {
        const float v = t[tx][ty + r];
        const size_t o = obase + (size_t)(n0 + ty + r) * K + k0 + tx;
        __half hh, ll;
        split1h(v, hh, ll);
        h[o] = hh; l[o] = ll;
    }
}

__global__ void bias_cat(const float* __restrict__ bq, const float* __restrict__ bk,
                         const float* __restrict__ bv, float* __restrict__ o)
{
    const int i = blockIdx.x, seg = blockIdx.y, j = threadIdx.x;
    const float* src = (seg == 0) ? bq : (seg == 1) ? bk : bv;
    o[i*QKVW + seg*1024 + j] = src[i*1024 + j];
}

// y (fp32, nullable) and yh (single fp16) outputs
__global__ __launch_bounds__(256) void add_ln(
    const float* __restrict__ x, const float* __restrict__ res,
    const float* __restrict__ g, const float* __restrict__ bta,
    float* __restrict__ y, __half* __restrict__ yh)
{
    __shared__ float rs[8], rq[8];
    const int tid = threadIdx.x;
    const size_t base = (size_t)blockIdx.x * 1024 + tid * 4;

    float4 a = *(const float4*)&x[base];
    float4 r = *(const float4*)&res[base];
    a.x += r.x; a.y += r.y; a.z += r.z; a.w += r.w;

    float s = a.x + a.y + a.z + a.w;
    float q = a.x*a.x + a.y*a.y + a.z*a.z + a.w*a.w;
    #pragma unroll
    for (int o = 16; o > 0; o >>= 1) {
        s += __shfl_xor_sync(0xffffffffu, s, o);
        q += __shfl_xor_sync(0xffffffffu, q, o);
    }
    if ((tid & 31) == 0) { rs[tid >> 5] = s; rq[tid >> 5] = q; }
    __syncthreads();
    s = 0.f; q = 0.f;
    #pragma unroll
    for (int i = 0; i < 8; i++) { s += rs[i]; q += rq[i]; }

    const float mean = s * (1.f / 1024.f);
    const float var  = q * (1.f / 1024.f) - mean * mean;
    const float rstd = rsqrtf(var + 1e-5f);

    const int c = tid * 4;
    float4 gv = *(const float4*)&g[c];
    float4 bv = *(const float4*)&bta[c];
    float4 o;
    o.x = (a.x - mean) * rstd * gv.x + bv.x;
    o.y = (a.y - mean) * rstd * gv.y + bv.y;
    o.z = (a.z - mean) * rstd * gv.z + bv.z;
    o.w = (a.w - mean) * rstd * gv.w + bv.w;
    if (y) *(float4*)&y[base] = o;

    *(uint32_t*)&yh[base]     = packh(o.x, o.y);
    *(uint32_t*)&yh[base + 2] = packh(o.z, o.w);
}

// ---------------------------------------------------------------------------
// Launch orchestration — round 9 DAG, fp16 buffers
// ---------------------------------------------------------------------------
extern "C" void kernel_launch(void* const* d_in, const int* in_sizes, int n_in,
                              void* d_out, int out_size)
{
    const float* T    = (const float*)d_in[0];
    const float* A    = (const float*)d_in[1];
    const float* mask = (const float*)d_in[2];
    const int*   pad  = (const int*)  d_in[3];
    const float* Wq   = (const float*)d_in[4];
    const float* bq   = (const float*)d_in[5];
    const float* Wk   = (const float*)d_in[6];
    const float* bk   = (const float*)d_in[7];
    const float* Wv   = (const float*)d_in[8];
    const float* bv   = (const float*)d_in[9];
    const float* Wo   = (const float*)d_in[10];
    const float* ffW1 = (const float*)d_in[11];
    const float* ffb1 = (const float*)d_in[12];
    const float* ffW2 = (const float*)d_in[13];
    const float* ffb2 = (const float*)d_in[14];
    const float* lng  = (const float*)d_in[15];
    const float* lnb  = (const float*)d_in[16];
    float* out = (float*)d_out;

    static cudaStream_t sA = nullptr, sB = nullptr, sC = nullptr;
    static cudaEvent_t  eF = nullptr, eA = nullptr, eB = nullptr;
    static cudaEvent_t  eC = nullptr, eQ2 = nullptr, eKV2 = nullptr, eQ3 = nullptr;
    if (!sA) {
        cudaStreamCreateWithFlags(&sA, cudaStreamNonBlocking);
        cudaStreamCreateWithFlags(&sB, cudaStreamNonBlocking);
        cudaStreamCreateWithFlags(&sC, cudaStreamNonBlocking);
        cudaEventCreateWithFlags(&eF,  cudaEventDisableTiming);
        cudaEventCreateWithFlags(&eA,  cudaEventDisableTiming);
        cudaEventCreateWithFlags(&eB,  cudaEventDisableTiming);
        cudaEventCreateWithFlags(&eC,  cudaEventDisableTiming);
        cudaEventCreateWithFlags(&eQ2, cudaEventDisableTiming);
        cudaEventCreateWithFlags(&eKV2,cudaEventDisableTiming);
        cudaEventCreateWithFlags(&eQ3, cudaEventDisableTiming);
    }
    auto fork = [&]() {
        cudaEventRecord(eF, 0);
        cudaStreamWaitEvent(sA, eF, 0);
        cudaStreamWaitEvent(sB, eF, 0);
    };
    auto join = [&]() {
        cudaEventRecord(eA, sA);
        cudaEventRecord(eB, sB);
        cudaStreamWaitEvent(0, eA, 0);
        cudaStreamWaitEvent(0, eB, 0);
    };

    float *Mo0, *Mo1, *T1f, *A1f;
    cudaGetSymbolAddress((void**)&Mo0, g_Mo0);
    cudaGetSymbolAddress((void**)&Mo1, g_Mo1);
    cudaGetSymbolAddress((void**)&T1f, g_T1f);
    cudaGetSymbolAddress((void**)&A1f, g_A1f);

    __half *iT,*iA,*T1,*A1,*T2,*A2,*O0,*O1,*H0,*H1;
    __half *QKV0h,*QKV0l,*QKV1h,*QKV1l;
    __half *wch,*wcl,*woh,*wol,*w1h,*w1l,*w2h,*w2l;
    float* bcat;
    cudaGetSymbolAddress((void**)&iT, g_iT);   cudaGetSymbolAddress((void**)&iA, g_iA);
    cudaGetSymbolAddress((void**)&T1, g_T1);   cudaGetSymbolAddress((void**)&A1, g_A1);
    cudaGetSymbolAddress((void**)&T2, g_T2);   cudaGetSymbolAddress((void**)&A2, g_A2);
    cudaGetSymbolAddress((void**)&O0, g_O0);   cudaGetSymbolAddress((void**)&O1, g_O1);
    cudaGetSymbolAddress((void**)&H0, g_H0);   cudaGetSymbolAddress((void**)&H1, g_H1);
    cudaGetSymbolAddress((void**)&QKV0h, g_QKV0h); cudaGetSymbolAddress((void**)&QKV0l, g_QKV0l);
    cudaGetSymbolAddress((void**)&QKV1h, g_QKV1h); cudaGetSymbolAddress((void**)&QKV1l, g_QKV1l);
    cudaGetSymbolAddress((void**)&wch, g_wch); cudaGetSymbolAddress((void**)&wcl, g_wcl);
    cudaGetSymbolAddress((void**)&woh, g_woh); cudaGetSymbolAddress((void**)&wol, g_wol);
    cudaGetSymbolAddress((void**)&w1h, g_w1h); cudaGetSymbolAddress((void**)&w1l, g_w1l);
    cudaGetSymbolAddress((void**)&w2h, g_w2h); cudaGetSymbolAddress((void**)&w2l, g_w2l);
    cudaGetSymbolAddress((void**)&bcat, g_bcat);

    cudaFuncSetAttribute(gemm_mma,   cudaFuncAttributeMaxDynamicSharedMemorySize, GEMM_SMEM);
    cudaFuncSetAttribute(flash_attn, cudaFuncAttributeMaxDynamicSharedMemorySize, FA_SMEM);

    const size_t DD = (size_t)Dc * Dc;
    const size_t WCZ = (size_t)QKVW * Dc;

    auto gemm = [&](cudaStream_t st, const __half* a,
                    const __half* bh, const __half* bl,
                    const float* bias, float* c, __half* ch, __half* cl,
                    int M, int N, int K, int ldc, int coff, int relu) {
        gemm_mma<<<dim3(N/128, M/128), 256, GEMM_SMEM, st>>>(
            a, bh, bl, bias, c, ch, cl, M, N, K, ldc, coff, relu);
    };

    // ------- Phase 0: CRITICAL prep (sA/sB) + DEFERRED prep (sC) -------
    fork();
    cudaStreamWaitEvent(sC, eF, 0);
    transpose_split<<<dim3(32,32,2), 256, 0, sA>>>(Wq, wch,        wcl,        Dc, Dc, WCZ);
    transpose_split<<<dim3(32,32,2), 256, 0, sA>>>(Wk, wch + DD,   wcl + DD,   Dc, Dc, WCZ);
    transpose_split<<<dim3(32,32,2), 256, 0, sA>>>(Wv, wch + 2*DD, wcl + 2*DD, Dc, Dc, WCZ);
    bias_cat<<<dim3(4,3), 1024, 0, sA>>>(bq, bk, bv, bcat);
    cvt_f16<<<BLc, 256, 0, sA>>>(T, iT);
    transpose_split<<<dim3(32,32,2), 256, 0, sB>>>(Wo, woh, wol, Dc, Dc, DD);
    cvt_f16<<<BLc, 256, 0, sB>>>(A, iA);
    transpose_split<<<dim3(32,32,2), 256, 0, sC>>>(Wq + 2*DD, wch + 2*WCZ,
                                                   wcl + 2*WCZ, Dc, Dc, WCZ);
    transpose_split<<<dim3(32,32,2), 256, 0, sC>>>(Wk + 2*DD, wch + 2*WCZ + DD,
                                                   wcl + 2*WCZ + DD, Dc, Dc, WCZ);
    transpose_split<<<dim3(32,32,2), 256, 0, sC>>>(Wv + 2*DD, wch + 2*WCZ + 2*DD,
                                                   wcl + 2*WCZ + 2*DD, Dc, Dc, WCZ);
    transpose_split<<<dim3(32,32,2), 256, 0, sC>>>(Wo + 2*DD, woh + 2*DD,
                                                   wol + 2*DD, Dc, Dc, DD);
    transpose_split<<<dim3(128,32,2), 256, 0, sC>>>(ffW1, w1h, w1l, Dc, Fc, (size_t)Dc*Fc);
    transpose_split<<<dim3(32,128,2), 256, 0, sC>>>(ffW2, w2h, w2l, Fc, Dc, (size_t)Fc*Dc);
    cudaEventRecord(eC, sC);
    join();

    // ---------------- Phase 1: mha0 (T, sA) || mha1 (A, sB) ----------------
    fork();
    gemm(sA, iT, wch, wcl, bcat, nullptr, QKV0h, QKV0l, BLc, QKVW, Dc, QKVW, 0, 0);
    flash_attn<<<dim3(Lc/128, 64), 256, FA_SMEM, sA>>>(QKV0h, QKV0l, mask, pad, O0);
    gemm(sA, O0, woh, wol, nullptr, Mo0, nullptr, nullptr, BLc, Dc, Dc, Dc, 0, 0);
    add_ln<<<BLc, 256, 0, sA>>>(T, Mo0, lng, lnb, T1f, T1);
    gemm(sB, iA, wch + WCZ, wcl + WCZ, bcat + QKVW, nullptr, QKV1h, QKV1l,
         BLc, QKVW, Dc, QKVW, 0, 0);
    flash_attn<<<dim3(Lc/128, 64), 256, FA_SMEM, sB>>>(QKV1h, QKV1l, mask, pad, O1);
    gemm(sB, O1, woh + DD, wol + DD, nullptr, Mo1, nullptr, nullptr, BLc, Dc, Dc, Dc, 0, 0);
    add_ln<<<BLc, 256, 0, sB>>>(A, Mo1, lng + Dc, lnb + Dc, A1f, A1);
    join();
    cudaStreamWaitEvent(0, eC, 0);

    // ------- Phase 2: KV2 (sA) || Q2,Q3 (sB); flash2 waits only {KV2,Q2} -------
    fork();
    gemm(sA, A1, wch + 2*WCZ + DD, wcl + 2*WCZ + DD, bcat + 2*QKVW + 1024,
         nullptr, QKV0h, QKV0l, BLc, 2*Dc, Dc, QKVW, 1024, 0);
    cudaEventRecord(eKV2, sA);
    gemm(sB, T1, wch + 2*WCZ, wcl + 2*WCZ, bcat + 2*QKVW,
         nullptr, QKV0h, QKV0l, BLc, Dc, Dc, QKVW, 0, 0);
    cudaEventRecord(eQ2, sB);
    gemm(sB, A1, wch + 3*WCZ, wcl + 3*WCZ, bcat + 3*QKVW,
         nullptr, QKV1h, QKV1l, BLc, Dc, Dc, QKVW, 0, 0);
    cudaEventRecord(eQ3, sB);

    cudaStreamWaitEvent(0, eKV2, 0);
    cudaStreamWaitEvent(0, eQ2, 0);
    flash_attn<<<dim3(Lc/128, 64), 256, FA_SMEM>>>(QKV0h, QKV0l, mask, pad, O0);
    gemm(0, O0, woh + 2*DD, wol + 2*DD, nullptr, Mo0, nullptr, nullptr, BLc, Dc, Dc, Dc, 0, 0);
    add_ln<<<BLc, 256>>>(T1f, Mo0, lng + 2*Dc, lnb + 2*Dc, nullptr, T2);

    // ------- Phase 3: mha3 chain + FFN-A (sA)  ||  FFN-T (sB) -------
    fork();
    gemm(sA, T2, wch + 3*WCZ + DD, wcl + 3*WCZ + DD, bcat + 3*QKVW + 1024,
         nullptr, QKV1h, QKV1l, BLc, 2*Dc, Dc, QKVW, 1024, 0);
    cudaStreamWaitEvent(sA, eQ3, 0);
    flash_attn<<<dim3(Lc/128, 64), 256, FA_SMEM, sA>>>(QKV1h, QKV1l, mask, pad, O0);
    gemm(sA, O0, woh + 3*DD, wol + 3*DD, nullptr, Mo0, nullptr, nullptr, BLc, Dc, Dc, Dc, 0, 0);
    add_ln<<<BLc, 256, 0, sA>>>(A1f, Mo0, lng + 3*Dc, lnb + 3*Dc, nullptr, A2);
    gemm(sA, A2, w1h + (size_t)Dc*Fc, w1l + (size_t)Dc*Fc, ffb1 + Fc,
         nullptr, H1, nullptr, BLc, Fc, Dc, Fc, 0, 1);
    gemm(sA, H1, w2h + (size_t)Fc*Dc, w2l + (size_t)Fc*Dc, ffb2 + Dc,
         out + (size_t)BLc*Dc, nullptr, nullptr, BLc, Dc, Fc, Dc, 0, 0);
    gemm(sB, T2, w1h, w1l, ffb1, nullptr, H0, nullptr, BLc, Fc, Dc, Fc, 0, 1);
    gemm(sB, H0, w2h, w2l, ffb2, out, nullptr, nullptr, BLc, Dc, Fc, Dc, 0, 0);
    join();
}

// round 11
// speedup vs baseline: 7.5754x; 1.6029x over previous
#include <cuda_runtime.h>
#include <cuda_fp16.h>
#include <math.h>
#include <stdint.h>

// Problem constants
constexpr int Bc  = 4;
constexpr int Lc  = 1024;
constexpr int Dc  = 1024;
constexpr int Fc  = 4096;
constexpr int HDc = 64;
constexpr int BLc = Bc * Lc;          // 4096 rows
constexpr int QKVW = 3 * Dc;          // 3072 concat width

// ---------------------------------------------------------------------------
// Scratch (static __device__ arrays — allocation-free per harness rules)
// ---------------------------------------------------------------------------
__device__ float g_Mo0[BLc * Dc];
__device__ float g_Mo1[BLc * Dc];
__device__ float g_T1f[BLc * Dc];
__device__ float g_A1f[BLc * Dc];

// single-fp16 activations
__device__ __half g_iT [BLc*Dc], g_iA [BLc*Dc];
__device__ __half g_T1 [BLc*Dc], g_A1 [BLc*Dc];
__device__ __half g_T2 [BLc*Dc], g_A2 [BLc*Dc];
__device__ __half g_O0 [BLc*Dc], g_O1 [BLc*Dc];
__device__ __half g_H0 [(size_t)BLc*Fc], g_H1 [(size_t)BLc*Fc];
__device__ __half g_QKV0[(size_t)BLc*QKVW];
__device__ __half g_QKV1[(size_t)BLc*QKVW];

// weights: single fp16, concat QKV^T [4][3072,1024]; others [N,K]
__device__ __half g_wc[(size_t)4*QKVW*Dc];
__device__ __half g_wo[4*Dc*Dc];
__device__ __half g_w1[2*Dc*Fc];
__device__ __half g_w2[2*Fc*Dc];
__device__ float g_bcat[4*QKVW];

// ---------------------------------------------------------------------------
// PTX helpers (sm_103 baseline-safe)
// ---------------------------------------------------------------------------
__device__ __forceinline__ uint32_t smem_u32(const void* p) {
    uint32_t a;
    asm("{ .reg .u64 t; cvta.to.shared.u64 t, %1; cvt.u32.u64 %0, t; }" : "=r"(a) : "l"(p));
    return a;
}
__device__ __forceinline__ void cpasync16(uint32_t dst, const void* src) {
    asm volatile("cp.async.cg.shared.global [%0], [%1], 16;" :: "r"(dst), "l"(src));
}
#define CP_COMMIT()  asm volatile("cp.async.commit_group;" ::: "memory")
#define CP_WAIT(n)   asm volatile("cp.async.wait_group %0;" :: "n"(n) : "memory")

#define LDSM4(r, a) \
    asm volatile("ldmatrix.sync.aligned.m8n8.x4.shared.b16 {%0,%1,%2,%3}, [%4];" \
        : "=r"((r)[0]), "=r"((r)[1]), "=r"((r)[2]), "=r"((r)[3]) : "r"(a))
#define LDSM4T(r, a) \
    asm volatile("ldmatrix.sync.aligned.m8n8.x4.trans.shared.b16 {%0,%1,%2,%3}, [%4];" \
        : "=r"((r)[0]), "=r"((r)[1]), "=r"((r)[2]), "=r"((r)[3]) : "r"(a))

__device__ __forceinline__ void mma16816(float* c, const uint32_t* a, const uint32_t* b) {
    asm volatile(
        "mma.sync.aligned.m16n8k16.row.col.f32.f16.f16.f32 "
        "{%0,%1,%2,%3}, {%4,%5,%6,%7}, {%8,%9}, {%0,%1,%2,%3};"
        : "+f"(c[0]), "+f"(c[1]), "+f"(c[2]), "+f"(c[3])
        : "r"(a[0]), "r"(a[1]), "r"(a[2]), "r"(a[3]), "r"(b[0]), "r"(b[1]));
}

__device__ __forceinline__ uint32_t packh(float a, float b) {
    __half2 t; t.x = __float2half(a); t.y = __float2half(b);
    return *(uint32_t*)&t;
}
#define FSW(o) ((o) ^ (((o) >> 3) & 0x70))     // SW128 swizzle for 128B rows

// ---------------------------------------------------------------------------
// Tensor-core GEMM: C[M,N] = A[M,K] @ B[N,K]^T (+bias)(+relu); single fp16
// operands, fp32 accumulate; 3-stage cp.async pipeline.
// Output: fp32 (C) and/or single fp16 (Ch). ldc stride, coff col offset.
// ---------------------------------------------------------------------------
constexpr int GSTR    = 40;
constexpr int TILE_B  = 128 * GSTR * 2;       // 10240 B per tile
constexpr int STAGE_B = 2 * TILE_B;           // A, B = 20480 B
constexpr int GEMM_SMEM = 3 * STAGE_B;        // 61440 B (3 stages)

__global__ __launch_bounds__(256, 2) void gemm_mma(
    const __half* __restrict__ Aa, const __half* __restrict__ Bb,
    const float* __restrict__ bias, float* __restrict__ C,
    __half* __restrict__ Ch,
    int M, int N, int K, int ldc, int coff, int relu)
{
    extern __shared__ char sm[];
    const uint32_t sb = smem_u32(sm);
    const int tid  = threadIdx.x;
    const int wid  = tid >> 5;
    const int lane = tid & 31;
    const int brow = blockIdx.y * 128;
    const int bcol = blockIdx.x * 128;
    const int wm   = (wid & 1) * 64;
    const int wn   = (wid >> 1) * 32;

    float acc[4][4][4];
    #pragma unroll
    for (int i = 0; i < 4; i++)
        #pragma unroll
        for (int j = 0; j < 4; j++)
            #pragma unroll
            for (int k = 0; k < 4; k++) acc[i][j][k] = 0.f;

    const int r0 = tid >> 2,            q0 = tid & 3;
    const int r1 = (tid + 256) >> 2,    q1 = (tid + 256) & 3;
    const int nch = K >> 5;

    auto issue = [&](int c, int s) {
        const int kc = c << 5;
        const uint32_t st = sb + s * STAGE_B;
        {
            const uint32_t so = (uint32_t)(r0 * 80 + q0 * 16);
            cpasync16(st + so,          Aa + (size_t)(brow + r0) * K + kc + q0 * 8);
            cpasync16(st + TILE_B + so, Bb + (size_t)(bcol + r0) * K + kc + q0 * 8);
        }
        {
            const uint32_t so = (uint32_t)(r1 * 80 + q1 * 16);
            cpasync16(st + so,          Aa + (size_t)(brow + r1) * K + kc + q1 * 8);
            cpasync16(st + TILE_B + so, Bb + (size_t)(bcol + r1) * K + kc + q1 * 8);
        }
        CP_COMMIT();
    };

    issue(0, 0);
    if (nch > 1) issue(1, 1);

    const int a_row = (lane & 15);
    const int a_kof = ((lane >> 4) << 3);
    const int g8    = lane >> 3;
    const int b_nt  = (g8 >> 1) << 3;
    const int b_kof = (g8 & 1) << 3;
    const int b_row = (lane & 7);

    for (int c = 0; c < nch; c++) {
        if (c + 2 < nch) { issue(c + 2, (c + 2) % 3); CP_WAIT(2); }
        else if (c + 1 < nch) CP_WAIT(1);
        else CP_WAIT(0);
        __syncthreads();

        const uint32_t st = sb + (c % 3) * STAGE_B;
        #pragma unroll
        for (int k16 = 0; k16 < 32; k16 += 16) {
            uint32_t aH[4][4], t[4];
            #pragma unroll
            for (int mt = 0; mt < 4; mt++) {
                uint32_t ad = st + (uint32_t)((wm + mt*16 + a_row) * 80
                                              + (k16 + a_kof) * 2);
                LDSM4(aH[mt], ad);
            }
            #pragma unroll
            for (int p = 0; p < 2; p++) {
                uint32_t ad = st + TILE_B
                    + (uint32_t)((wn + p*16 + b_nt + b_row) * 80
                                 + (k16 + b_kof) * 2);
                LDSM4(t, ad);
                uint32_t b0[2] = { t[0], t[1] }, b1[2] = { t[2], t[3] };
                #pragma unroll
                for (int mt = 0; mt < 4; mt++) {
                    mma16816(acc[mt][2*p    ], aH[mt], b0);
                    mma16816(acc[mt][2*p + 1], aH[mt], b1);
                }
            }
        }
        __syncthreads();
    }

    const int g  = lane >> 2;
    const int tg = lane & 3;
    #pragma unroll
    for (int mt = 0; mt < 4; mt++) {
        #pragma unroll
        for (int nt = 0; nt < 4; nt++) {
            const int row = brow + wm + mt*16 + g;
            const int col = bcol + wn + nt*8 + tg*2;
            float2 v0, v1;
            v0.x = acc[mt][nt][0]; v0.y = acc[mt][nt][1];
            v1.x = acc[mt][nt][2]; v1.y = acc[mt][nt][3];
            if (bias) {
                float2 bb = *(const float2*)&bias[col];
                v0.x += bb.x; v0.y += bb.y; v1.x += bb.x; v1.y += bb.y;
            }
            if (relu) {
                v0.x = fmaxf(v0.x, 0.f); v0.y = fmaxf(v0.y, 0.f);
                v1.x = fmaxf(v1.x, 0.f); v1.y = fmaxf(v1.y, 0.f);
            }
            const size_t o0 = (size_t)row * ldc + coff + col;
            const size_t o1 = (size_t)(row + 8) * ldc + coff + col;
            if (C) {
                *(float2*)&C[o0] = v0;
                *(float2*)&C[o1] = v1;
            }
            if (Ch) {
                *(uint32_t*)&Ch[o0] = packh(v0.x, v0.y);
                *(uint32_t*)&Ch[o1] = packh(v1.x, v1.y);
            }
        }
    }
}

// ---------------------------------------------------------------------------
// Fused flash attention: Q/K/V/P/O all single fp16, fp32 accumulate.
// Occupancy 2; SW128 64-row K/V tiles; 1-product MMAs.
// ---------------------------------------------------------------------------
constexpr int FA_QTB   = 128 * 144;               // 18432 B
constexpr int FA_KTB   = 64 * 128;                // 8192 B
constexpr int FA_STAGE = 2 * FA_KTB;              // K,V = 16384 B
constexpr int FA_SMEM  = FA_QTB + 2*FA_STAGE + 4096;   // 55296 B

__global__ __launch_bounds__(256, 2) void flash_attn(
    const __half* __restrict__ X,
    const float* __restrict__ mask, const int* __restrict__ pad,
    __half* __restrict__ O)
{
    extern __shared__ char sm[];
    const uint32_t sb = smem_u32(sm);
    const int tid  = threadIdx.x;
    const int wid  = tid >> 5;
    const int lane = tid & 31;
    const int qy   = blockIdx.x * 128;
    const int bh   = blockIdx.y;
    const int b    = bh >> 4;
    const int hcol = (bh & 15) * HDc;
    const int wq   = wid * 16;

    const uint32_t sQ     = sb;
    const uint32_t sStage = sb + FA_QTB;
    float* spad = (float*)(sm + FA_QTB + 2*FA_STAGE);

    for (int i = tid; i < 1024; i += 256)
        spad[i] = (float)pad[b*Lc + i];

    for (int i = tid; i < 1024; i += 256) {
        const int r = i >> 3, j = i & 7;
        const uint32_t so = (uint32_t)(r * 144 + j * 16);
        cpasync16(sQ + so, X + (size_t)(b*Lc + qy + r) * QKVW + hcol + j*8);
    }
    CP_COMMIT();

    auto issueKV = [&](int t, int s) {
        const int kx = t * 64;
        const uint32_t base = sStage + s * FA_STAGE;
        for (int i = tid; i < 512; i += 256) {
            const int r = i >> 3, j = i & 7;
            const uint32_t so = FSW((uint32_t)(r * 128 + j * 16));
            const size_t gk = (size_t)(b*Lc + kx + r) * QKVW + 1024 + hcol + j*8;
            cpasync16(base + so,            X + gk);
            cpasync16(base + FA_KTB + so,   X + gk + 1024);
        }
        CP_COMMIT();
    };
    issueKV(0, 0);

    CP_WAIT(1);
    __syncthreads();

    const int a_row = lane & 15;
    const int a_kof = (lane >> 4) << 3;
    uint32_t qh[4][4];
    #pragma unroll
    for (int kt = 0; kt < 4; kt++)
        LDSM4(qh[kt], sQ + (uint32_t)((wq + a_row)*144 + (kt*16 + a_kof)*2));

    float m[2] = { -1e30f, -1e30f };
    float l[2] = { 0.f, 0.f };
    float o[8][4];
    #pragma unroll
    for (int i = 0; i < 8; i++)
        #pragma unroll
        for (int j = 0; j < 4; j++) o[i][j] = 0.f;

    const int g    = lane >> 2;
    const int tg   = lane & 3;
    const int g8   = lane >> 3;
    const int b_nt  = (g8 >> 1) << 3;
    const int b_kof = (g8 & 1) << 3;
    const int b_row = lane & 7;
    const int v_kv = ((lane >> 3) & 1) << 3;
    const int v_d  = (lane >> 4) << 3;

    for (int t = 0; t < 16; t++) {
        const int kx = t * 64;
        if (t + 1 < 16) { issueKV(t + 1, (t + 1) & 1); CP_WAIT(1); }
        else            { CP_WAIT(0); }
        __syncthreads();

        const uint32_t stK = sStage + (t & 1) * FA_STAGE;
        const uint32_t stV = stK + FA_KTB;

        // ---- S = Q K^T ----
        float sf[8][4];
        #pragma unroll
        for (int i = 0; i < 8; i++)
            #pragma unroll
            for (int j = 0; j < 4; j++) sf[i][j] = 0.f;

        #pragma unroll
        for (int kst = 0; kst < 4; kst++) {
            uint32_t kb[4][4];
            #pragma unroll
            for (int p = 0; p < 4; p++) {
                const uint32_t ad = stK + FSW((uint32_t)((p*16 + b_nt + b_row)*128
                                                          + kst*32 + b_kof*2));
                LDSM4(kb[p], ad);
            }
            #pragma unroll
            for (int p = 0; p < 4; p++) {
                uint32_t b0[2] = { kb[p][0], kb[p][1] };
                uint32_t b1[2] = { kb[p][2], kb[p][3] };
                mma16816(sf[2*p],   qh[kst], b0);
                mma16816(sf[2*p+1], qh[kst], b1);
            }
        }

        // ---- scale + mask + pad ----
        const int qg0 = qy + wq + g;
        #pragma unroll
        for (int nt = 0; nt < 8; nt++) {
            const int kvl = nt*8 + tg*2;
            const int kvg = kx + kvl;
            float2 m0 = *(const float2*)&mask[(size_t)qg0 * Lc + kvg];
            float2 m1 = *(const float2*)&mask[(size_t)(qg0 + 8) * Lc + kvg];
            const float p0 = spad[kvg], p1 = spad[kvg + 1];
            sf[nt][0] = sf[nt][0]*0.125f + m0.x + p0;
            sf[nt][1] = sf[nt][1]*0.125f + m0.y + p1;
            sf[nt][2] = sf[nt][2]*0.125f + m1.x + p0;
            sf[nt][3] = sf[nt][3]*0.125f + m1.y + p1;
        }

        // ---- online softmax ----
        float mx0 = m[0], mx1 = m[1];
        #pragma unroll
        for (int nt = 0; nt < 8; nt++) {
            mx0 = fmaxf(mx0, fmaxf(sf[nt][0], sf[nt][1]));
            mx1 = fmaxf(mx1, fmaxf(sf[nt][2], sf[nt][3]));
        }
        mx0 = fmaxf(mx0, __shfl_xor_sync(0xffffffffu, mx0, 1));
        mx0 = fmaxf(mx0, __shfl_xor_sync(0xffffffffu, mx0, 2));
        mx1 = fmaxf(mx1, __shfl_xor_sync(0xffffffffu, mx1, 1));
        mx1 = fmaxf(mx1, __shfl_xor_sync(0xffffffffu, mx1, 2));

        const float al0 = __expf(m[0] - mx0);
        const float al1 = __expf(m[1] - mx1);
        m[0] = mx0; m[1] = mx1;
        #pragma unroll
        for (int nt = 0; nt < 8; nt++) {
            o[nt][0] *= al0; o[nt][1] *= al0;
            o[nt][2] *= al1; o[nt][3] *= al1;
        }

        uint32_t ph[4][4];
        float s0 = 0.f, s1 = 0.f;
        #pragma unroll
        for (int j = 0; j < 4; j++) {
            float e00 = __expf(sf[2*j][0]   - mx0);
            float e01 = __expf(sf[2*j][1]   - mx0);
            float e10 = __expf(sf[2*j][2]   - mx1);
            float e11 = __expf(sf[2*j][3]   - mx1);
            float e20 = __expf(sf[2*j+1][0] - mx0);
            float e21 = __expf(sf[2*j+1][1] - mx0);
            float e30 = __expf(sf[2*j+1][2] - mx1);
            float e31 = __expf(sf[2*j+1][3] - mx1);
            s0 += e00 + e01 + e20 + e21;
            s1 += e10 + e11 + e30 + e31;
            ph[j][0] = packh(e00, e01);
            ph[j][1] = packh(e10, e11);
            ph[j][2] = packh(e20, e21);
            ph[j][3] = packh(e30, e31);
        }
        s0 += __shfl_xor_sync(0xffffffffu, s0, 1);
        s0 += __shfl_xor_sync(0xffffffffu, s0, 2);
        s1 += __shfl_xor_sync(0xffffffffu, s1, 1);
        s1 += __shfl_xor_sync(0xffffffffu, s1, 2);
        l[0] = l[0]*al0 + s0;
        l[1] = l[1]*al1 + s1;

        // ---- O += P V ----
        #pragma unroll
        for (int j = 0; j < 4; j++) {
            #pragma unroll
            for (int p = 0; p < 4; p++) {
                uint32_t th[4];
                const uint32_t off = FSW((uint32_t)((j*16 + v_kv + b_row)*128
                                                     + p*32 + v_d*2));
                LDSM4T(th, stV + off);
                uint32_t b0[2] = { th[0], th[1] }, b1[2] = { th[2], th[3] };
                mma16816(o[2*p],   ph[j], b0);
                mma16816(o[2*p+1], ph[j], b1);
            }
        }
        __syncthreads();
    }

    const float inv0 = 1.f / l[0];
    const float inv1 = 1.f / l[1];
    const int row = b*Lc + qy + wq + g;
    #pragma unroll
    for (int nt = 0; nt < 8; nt++) {
        const int col = hcol + nt*8 + tg*2;
        *(uint32_t*)&O[(size_t)row * Dc + col]       = packh(o[nt][0]*inv0, o[nt][1]*inv0);
        *(uint32_t*)&O[(size_t)(row + 8) * Dc + col] = packh(o[nt][2]*inv1, o[nt][3]*inv1);
    }
}

// ---------------------------------------------------------------------------
// small kernels
// ---------------------------------------------------------------------------
__global__ __launch_bounds__(256) void cvt_f16(
    const float* __restrict__ x, __half* __restrict__ h)
{
    const size_t i = ((size_t)blockIdx.x * 256 + threadIdx.x) * 4;
    float4 v = *(const float4*)(x + i);
    *(uint32_t*)(h + i)     = packh(v.x, v.y);
    *(uint32_t*)(h + i + 2) = packh(v.z, v.w);
}

// W[z][K,N] fp32 -> out[z*ostrideZ + n*K + k] single fp16 ([N,K] transpose)
__global__ __launch_bounds__(256) void transpose_cvt(
    const float* __restrict__ W, __half* __restrict__ h,
    int K, int N, size_t ostrideZ)
{
    __shared__ float t[32][33];
    const size_t ibase = (size_t)blockIdx.z * K * N;
    const size_t obase = (size_t)blockIdx.z * ostrideZ;
    const int k0 = blockIdx.y * 32, n0 = blockIdx.x * 32;
    const int tx = threadIdx.x & 31, ty = threadIdx.x >> 5;
    #pragma unroll
    for (int r = 0; r < 32; r += 8)
        t[ty + r][tx] = W[ibase + (size_t)(k0 + ty + r) * N + n0 + tx];
    __syncthreads();
    #pragma unroll
    for (int r = 0; r < 32; r += 8) {
        const size_t o = obase + (size_t)(n0 + ty + r) * K + k0 + tx;
        h[o] = __float2half(t[tx][ty + r]);
    }
}

__global__ void bias_cat(const float* __restrict__ bq, const float* __restrict__ bk,
                         const float* __restrict__ bv, float* __restrict__ o)
{
    const int i = blockIdx.x, seg = blockIdx.y, j = threadIdx.x;
    const float* src = (seg == 0) ? bq : (seg == 1) ? bk : bv;
    o[i*QKVW + seg*1024 + j] = src[i*1024 + j];
}

// y (fp32, nullable) and yh (single fp16) outputs
__global__ __launch_bounds__(256) void add_ln(
    const float* __restrict__ x, const float* __restrict__ res,
    const float* __restrict__ g, const float* __restrict__ bta,
    float* __restrict__ y, __half* __restrict__ yh)
{
    __shared__ float rs[8], rq[8];
    const int tid = threadIdx.x;
    const size_t base = (size_t)blockIdx.x * 1024 + tid * 4;

    float4 a = *(const float4*)&x[base];
    float4 r = *(const float4*)&res[base];
    a.x += r.x; a.y += r.y; a.z += r.z; a.w += r.w;

    float s = a.x + a.y + a.z + a.w;
    float q = a.x*a.x + a.y*a.y + a.z*a.z + a.w*a.w;
    #pragma unroll
    for (int o = 16; o > 0; o >>= 1) {
        s += __shfl_xor_sync(0xffffffffu, s, o);
        q += __shfl_xor_sync(0xffffffffu, q, o);
    }
    if ((tid & 31) == 0) { rs[tid >> 5] = s; rq[tid >> 5] = q; }
    __syncthreads();
    s = 0.f; q = 0.f;
    #pragma unroll
    for (int i = 0; i < 8; i++) { s += rs[i]; q += rq[i]; }

    const float mean = s * (1.f / 1024.f);
    const float var  = q * (1.f / 1024.f) - mean * mean;
    const float rstd = rsqrtf(var + 1e-5f);

    const int c = tid * 4;
    float4 gv = *(const float4*)&g[c];
    float4 bv = *(const float4*)&bta[c];
    float4 o;
    o.x = (a.x - mean) * rstd * gv.x + bv.x;
    o.y = (a.y - mean) * rstd * gv.y + bv.y;
    o.z = (a.z - mean) * rstd * gv.z + bv.z;
    o.w = (a.w - mean) * rstd * gv.w + bv.w;
    if (y) *(float4*)&y[base] = o;

    *(uint32_t*)&yh[base]     = packh(o.x, o.y);
    *(uint32_t*)&yh[base + 2] = packh(o.z, o.w);
}

// ---------------------------------------------------------------------------
// Launch orchestration — round 9 DAG, single-fp16 buffers
// ---------------------------------------------------------------------------
extern "C" void kernel_launch(void* const* d_in, const int* in_sizes, int n_in,
                              void* d_out, int out_size)
{
    const float* T    = (const float*)d_in[0];
    const float* A    = (const float*)d_in[1];
    const float* mask = (const float*)d_in[2];
    const int*   pad  = (const int*)  d_in[3];
    const float* Wq   = (const float*)d_in[4];
    const float* bq   = (const float*)d_in[5];
    const float* Wk   = (const float*)d_in[6];
    const float* bk   = (const float*)d_in[7];
    const float* Wv   = (const float*)d_in[8];
    const float* bv   = (const float*)d_in[9];
    const float* Wo   = (const float*)d_in[10];
    const float* ffW1 = (const float*)d_in[11];
    const float* ffb1 = (const float*)d_in[12];
    const float* ffW2 = (const float*)d_in[13];
    const float* ffb2 = (const float*)d_in[14];
    const float* lng  = (const float*)d_in[15];
    const float* lnb  = (const float*)d_in[16];
    float* out = (float*)d_out;

    static cudaStream_t sA = nullptr, sB = nullptr, sC = nullptr;
    static cudaEvent_t  eF = nullptr, eA = nullptr, eB = nullptr;
    static cudaEvent_t  eC = nullptr, eQ2 = nullptr, eKV2 = nullptr, eQ3 = nullptr;
    if (!sA) {
        cudaStreamCreateWithFlags(&sA, cudaStreamNonBlocking);
        cudaStreamCreateWithFlags(&sB, cudaStreamNonBlocking);
        cudaStreamCreateWithFlags(&sC, cudaStreamNonBlocking);
        cudaEventCreateWithFlags(&eF,  cudaEventDisableTiming);
        cudaEventCreateWithFlags(&eA,  cudaEventDisableTiming);
        cudaEventCreateWithFlags(&eB,  cudaEventDisableTiming);
        cudaEventCreateWithFlags(&eC,  cudaEventDisableTiming);
        cudaEventCreateWithFlags(&eQ2, cudaEventDisableTiming);
        cudaEventCreateWithFlags(&eKV2,cudaEventDisableTiming);
        cudaEventCreateWithFlags(&eQ3, cudaEventDisableTiming);
    }
    auto fork = [&]() {
        cudaEventRecord(eF, 0);
        cudaStreamWaitEvent(sA, eF, 0);
        cudaStreamWaitEvent(sB, eF, 0);
    };
    auto join = [&]() {
        cudaEventRecord(eA, sA);
        cudaEventRecord(eB, sB);
        cudaStreamWaitEvent(0, eA, 0);
        cudaStreamWaitEvent(0, eB, 0);
    };

    float *Mo0, *Mo1, *T1f, *A1f;
    cudaGetSymbolAddress((void**)&Mo0, g_Mo0);
    cudaGetSymbolAddress((void**)&Mo1, g_Mo1);
    cudaGetSymbolAddress((void**)&T1f, g_T1f);
    cudaGetSymbolAddress((void**)&A1f, g_A1f);

    __half *iT,*iA,*T1,*A1,*T2,*A2,*O0,*O1,*H0,*H1,*QKV0,*QKV1;
    __half *wc,*wo,*w1,*w2;
    float* bcat;
    cudaGetSymbolAddress((void**)&iT, g_iT);   cudaGetSymbolAddress((void**)&iA, g_iA);
    cudaGetSymbolAddress((void**)&T1, g_T1);   cudaGetSymbolAddress((void**)&A1, g_A1);
    cudaGetSymbolAddress((void**)&T2, g_T2);   cudaGetSymbolAddress((void**)&A2, g_A2);
    cudaGetSymbolAddress((void**)&O0, g_O0);   cudaGetSymbolAddress((void**)&O1, g_O1);
    cudaGetSymbolAddress((void**)&H0, g_H0);   cudaGetSymbolAddress((void**)&H1, g_H1);
    cudaGetSymbolAddress((void**)&QKV0, g_QKV0);
    cudaGetSymbolAddress((void**)&QKV1, g_QKV1);
    cudaGetSymbolAddress((void**)&wc, g_wc);   cudaGetSymbolAddress((void**)&wo, g_wo);
    cudaGetSymbolAddress((void**)&w1, g_w1);   cudaGetSymbolAddress((void**)&w2, g_w2);
    cudaGetSymbolAddress((void**)&bcat, g_bcat);

    cudaFuncSetAttribute(gemm_mma,   cudaFuncAttributeMaxDynamicSharedMemorySize, GEMM_SMEM);
    cudaFuncSetAttribute(flash_attn, cudaFuncAttributeMaxDynamicSharedMemorySize, FA_SMEM);

    const size_t DD = (size_t)Dc * Dc;
    const size_t WCZ = (size_t)QKVW * Dc;

    auto gemm = [&](cudaStream_t st, const __half* a, const __half* b,
                    const float* bias, float* c, __half* ch,
                    int M, int N, int K, int ldc, int coff, int relu) {
        gemm_mma<<<dim3(N/128, M/128), 256, GEMM_SMEM, st>>>(
            a, b, bias, c, ch, M, N, K, ldc, coff, relu);
    };

    // ------- Phase 0: CRITICAL prep (sA/sB) + DEFERRED prep (sC) -------
    fork();
    cudaStreamWaitEvent(sC, eF, 0);
    transpose_cvt<<<dim3(32,32,2), 256, 0, sA>>>(Wq, wc,        Dc, Dc, WCZ);
    transpose_cvt<<<dim3(32,32,2), 256, 0, sA>>>(Wk, wc + DD,   Dc, Dc, WCZ);
    transpose_cvt<<<dim3(32,32,2), 256, 0, sA>>>(Wv, wc + 2*DD, Dc, Dc, WCZ);
    bias_cat<<<dim3(4,3), 1024, 0, sA>>>(bq, bk, bv, bcat);
    cvt_f16<<<BLc, 256, 0, sA>>>(T, iT);
    transpose_cvt<<<dim3(32,32,2), 256, 0, sB>>>(Wo, wo, Dc, Dc, DD);
    cvt_f16<<<BLc, 256, 0, sB>>>(A, iA);
    transpose_cvt<<<dim3(32,32,2), 256, 0, sC>>>(Wq + 2*DD, wc + 2*WCZ,        Dc, Dc, WCZ);
    transpose_cvt<<<dim3(32,32,2), 256, 0, sC>>>(Wk + 2*DD, wc + 2*WCZ + DD,   Dc, Dc, WCZ);
    transpose_cvt<<<dim3(32,32,2), 256, 0, sC>>>(Wv + 2*DD, wc + 2*WCZ + 2*DD, Dc, Dc, WCZ);
    transpose_cvt<<<dim3(32,32,2), 256, 0, sC>>>(Wo + 2*DD, wo + 2*DD, Dc, Dc, DD);
    transpose_cvt<<<dim3(128,32,2), 256, 0, sC>>>(ffW1, w1, Dc, Fc, (size_t)Dc*Fc);
    transpose_cvt<<<dim3(32,128,2), 256, 0, sC>>>(ffW2, w2, Fc, Dc, (size_t)Fc*Dc);
    cudaEventRecord(eC, sC);
    join();

    // ---------------- Phase 1: mha0 (T, sA) || mha1 (A, sB) ----------------
    fork();
    gemm(sA, iT, wc, bcat, nullptr, QKV0, BLc, QKVW, Dc, QKVW, 0, 0);
    flash_attn<<<dim3(Lc/128, 64), 256, FA_SMEM, sA>>>(QKV0, mask, pad, O0);
    gemm(sA, O0, wo, nullptr, Mo0, nullptr, BLc, Dc, Dc, Dc, 0, 0);
    add_ln<<<BLc, 256, 0, sA>>>(T, Mo0, lng, lnb, T1f, T1);
    gemm(sB, iA, wc + WCZ, bcat + QKVW, nullptr, QKV1, BLc, QKVW, Dc, QKVW, 0, 0);
    flash_attn<<<dim3(Lc/128, 64), 256, FA_SMEM, sB>>>(QKV1, mask, pad, O1);
    gemm(sB, O1, wo + DD, nullptr, Mo1, nullptr, BLc, Dc, Dc, Dc, 0, 0);
    add_ln<<<BLc, 256, 0, sB>>>(A, Mo1, lng + Dc, lnb + Dc, A1f, A1);
    join();
    cudaStreamWaitEvent(0, eC, 0);

    // ------- Phase 2: KV2 (sA) || Q2,Q3 (sB); flash2 waits only {KV2,Q2} -------
    fork();
    gemm(sA, A1, wc + 2*WCZ + DD, bcat + 2*QKVW + 1024,
         nullptr, QKV0, BLc, 2*Dc, Dc, QKVW, 1024, 0);
    cudaEventRecord(eKV2, sA);
    gemm(sB, T1, wc + 2*WCZ, bcat + 2*QKVW, nullptr, QKV0, BLc, Dc, Dc, QKVW, 0, 0);
    cudaEventRecord(eQ2, sB);
    gemm(sB, A1, wc + 3*WCZ, bcat + 3*QKVW, nullptr, QKV1, BLc, Dc, Dc, QKVW, 0, 0);
    cudaEventRecord(eQ3, sB);

    cudaStreamWaitEvent(0, eKV2, 0);
    cudaStreamWaitEvent(0, eQ2, 0);
    flash_attn<<<dim3(Lc/128, 64), 256, FA_SMEM>>>(QKV0, mask, pad, O0);
    gemm(0, O0, wo + 2*DD, nullptr, Mo0, nullptr, BLc, Dc, Dc, Dc, 0, 0);
    add_ln<<<BLc, 256>>>(T1f, Mo0, lng + 2*Dc, lnb + 2*Dc, nullptr, T2);

    // ------- Phase 3: mha3 chain + FFN-A (sA)  ||  FFN-T (sB) -------
    fork();
    gemm(sA, T2, wc + 3*WCZ + DD, bcat + 3*QKVW + 1024,
         nullptr, QKV1, BLc, 2*Dc, Dc, QKVW, 1024, 0);
    cudaStreamWaitEvent(sA, eQ3, 0);
    flash_attn<<<dim3(Lc/128, 64), 256, FA_SMEM, sA>>>(QKV1, mask, pad, O0);
    gemm(sA, O0, wo + 3*DD, nullptr, Mo0, nullptr, BLc, Dc, Dc, Dc, 0, 0);
    add_ln<<<BLc, 256, 0, sA>>>(A1f, Mo0, lng + 3*Dc, lnb + 3*Dc, nullptr, A2);
    gemm(sA, A2, w1 + (size_t)Dc*Fc, ffb1 + Fc, nullptr, H1, BLc, Fc, Dc, Fc, 0, 1);
    gemm(sA, H1, w2 + (size_t)Fc*Dc, ffb2 + Dc,
         out + (size_t)BLc*Dc, nullptr, BLc, Dc, Fc, Dc, 0, 0);
    gemm(sB, T2, w1, ffb1, nullptr, H0, BLc, Fc, Dc, Fc, 0, 1);
    gemm(sB, H0, w2, ffb2, out, nullptr, BLc, Dc, Fc, Dc, 0, 0);
    join();
}